// round 8
// baseline (speedup 1.0000x reference)
#include <cuda_runtime.h>
#include <cuda_bf16.h>
#include <cstdint>

typedef unsigned int u32;

#define QSCALE 0.17677669529663687f

// ---- smem byte offsets (1 window per CTA, 110592 B total) ----
#define OFF_WB    0         /* 2 x 16384 weight ping-pong            */
#define OFF_VTLO  16384     /* VT bf16 lo [128 rows][128B] = WB1     */
#define OFF_QHI   32768     /* Q bf16 hi  [64 rows][256B]            */
#define OFF_QLO   49152
#define OFF_KHI   65536     /* K bf16 hi  [56 rows][256B]            */
#define OFF_KLO   79872
#define OFF_VTHI  94208     /* VT bf16 hi [128 rows][128B]           */
#define OFF_AHI   94208     /* A staging hi [64 rows][128B] (alias VT-hi) */
#define OFF_ALO   102400    /* A staging lo */
#define OFF_PHI   32768     /* proj A' hi (alias Q hi)               */
#define OFF_PLO   49152     /* proj A' lo (alias Q lo)               */
#define SMEM_BYTES 110592

// pre-packed bf16 weight fragments (round-6/7 validated layout)
__device__ __align__(16) unsigned char g_wq[196608];
__device__ __align__(16) unsigned char g_wp[65536];
// combined bias+mask table: [w<64][h<4][i<49][j stride 56]
__device__ __align__(16) float g_bm[702464];

__device__ __forceinline__ u32 sw16(int ch, int r) {
    return (u32)((ch & 8) | ((ch ^ (r & 7)) & 7));
}

// ---------------- prep kernel: weights + bias/mask table ----------------
__global__ void prep_all(const float* __restrict__ qkv_w,
                         const float* __restrict__ proj_w,
                         const float* __restrict__ mask,
                         const float* __restrict__ bias_table,
                         const int*   __restrict__ rel_index,
                         int nW) {
    int e = blockIdx.x * 256 + threadIdx.x;
    if (e < 32768) {
        bool isq = e < 24576;
        int idx = isq ? e : e - 24576;
        const float* W = isq ? qkv_w : proj_w;
        unsigned char* dst = isq ? g_wq : g_wp;
        int ldw = isq ? 384 : 128;
        int piece = idx >> 11;
        int rem = idx & 2047;
        int lane = rem & 31, ks = (rem >> 5) & 3, nt = rem >> 7;
        int chunk = isq ? (piece >> 2) : 0;
        int kh = isq ? ((piece >> 1) & 1) : (piece >> 1);
        int part = piece & 1;
        int k0 = kh * 64 + ks * 16 + (lane & 3) * 2;
        int n  = chunk * 128 + nt * 8 + (lane >> 2);
        float v0 = W[k0 * ldw + n],       v1 = W[(k0 + 1) * ldw + n];
        float v2 = W[(k0 + 8) * ldw + n], v3 = W[(k0 + 9) * ldw + n];
        __nv_bfloat16 h0 = __float2bfloat16_rn(v0), h1 = __float2bfloat16_rn(v1);
        __nv_bfloat16 h2 = __float2bfloat16_rn(v2), h3 = __float2bfloat16_rn(v3);
        __nv_bfloat162 r0, r1;
        if (part == 0) {
            r0 = __halves2bfloat162(h0, h1);
            r1 = __halves2bfloat162(h2, h3);
        } else {
            r0 = __halves2bfloat162(__float2bfloat16_rn(v0 - __bfloat162float(h0)),
                                    __float2bfloat16_rn(v1 - __bfloat162float(h1)));
            r1 = __halves2bfloat162(__float2bfloat16_rn(v2 - __bfloat162float(h2)),
                                    __float2bfloat16_rn(v3 - __bfloat162float(h3)));
        }
        *(__nv_bfloat162*)(dst + (size_t)idx * 8)     = r0;
        *(__nv_bfloat162*)(dst + (size_t)idx * 8 + 4) = r1;
    } else {
        int idx = e - 32768;                  // < 702464
        if (idx < 702464) {
            int w = idx / 10976;
            int r = idx % 10976;
            int h = r / 2744;
            int r2 = r % 2744;
            int i = r2 / 56, j = r2 % 56;
            float val = 0.f;
            if (j < 49 && w < nW)
                val = bias_table[rel_index[i * 49 + j] * 4 + h] + mask[w * 2401 + i * 49 + j];
            g_bm[idx] = val;
        }
    }
}

// ---------------- PTX helpers ----------------
__device__ __forceinline__ void cp16(u32 dst, const void* src) {
    asm volatile("cp.async.cg.shared.global [%0], [%1], 16;" :: "r"(dst), "l"(src));
}
__device__ __forceinline__ void cp_commit() { asm volatile("cp.async.commit_group;"); }
template <int N> __device__ __forceinline__ void cp_wait() {
    asm volatile("cp.async.wait_group %0;" :: "n"(N));
}
__device__ __forceinline__ void ldm4(u32 r[4], u32 addr) {
    asm volatile("ldmatrix.sync.aligned.m8n8.x4.shared.b16 {%0,%1,%2,%3}, [%4];"
        : "=r"(r[0]), "=r"(r[1]), "=r"(r[2]), "=r"(r[3]) : "r"(addr));
}
__device__ __forceinline__ void ldm2(u32 r[2], u32 addr) {
    asm volatile("ldmatrix.sync.aligned.m8n8.x2.shared.b16 {%0,%1}, [%2];"
        : "=r"(r[0]), "=r"(r[1]) : "r"(addr));
}
__device__ __forceinline__ void mma16816(float c[4], const u32 a[4], u32 b0, u32 b1) {
    asm volatile("mma.sync.aligned.m16n8k16.row.col.f32.bf16.bf16.f32 "
        "{%0,%1,%2,%3}, {%4,%5,%6,%7}, {%8,%9}, {%0,%1,%2,%3};"
        : "+f"(c[0]), "+f"(c[1]), "+f"(c[2]), "+f"(c[3])
        : "r"(a[0]), "r"(a[1]), "r"(a[2]), "r"(a[3]), "r"(b0), "r"(b1));
}
__device__ __forceinline__ u32 pk_hi(float a, float b) {
    __nv_bfloat162 t = __halves2bfloat162(__float2bfloat16_rn(a), __float2bfloat16_rn(b));
    return *(u32*)&t;
}
__device__ __forceinline__ u32 pk_lo(float a, float b) {
    __nv_bfloat16 ha = __float2bfloat16_rn(a), hb = __float2bfloat16_rn(b);
    __nv_bfloat162 t = __halves2bfloat162(
        __float2bfloat16_rn(a - __bfloat162float(ha)),
        __float2bfloat16_rn(b - __bfloat162float(hb)));
    return *(u32*)&t;
}

// issue one 16KB weight piece into ping-pong buffer (piece i -> buf i&1)
// 256 threads x 64B each
__device__ __forceinline__ void issue_piece(u32 sb, int i, int tid) {
    const unsigned char* src =
        (i < 12 ? g_wq + (u32)i * 16384 : g_wp + (u32)(i - 12) * 16384) + tid * 64;
    u32 dst = sb + OFF_WB + (u32)(i & 1) * 16384 + (u32)tid * 64;
    cp16(dst, src); cp16(dst + 16, src + 16);
    cp16(dst + 32, src + 32); cp16(dst + 48, src + 48);
    cp_commit();
}

// one k-half (4 ksteps) of mma over 2 m-tiles x 4 n-tiles (weight GEMMs)
__device__ __forceinline__ void mma_tiles(float acc[2][4][4],
    u32 ahiB, u32 aloB, u32 bufB, int mg, int ng, int lane,
    int rowShift, int chBase, bool both)
{
    #pragma unroll
    for (int ks = 0; ks < 4; ++ks) {
        u32 a_hi[2][4], a_lo[2][4];
        #pragma unroll
        for (int mt = 0; mt < 2; ++mt) {
            int row = mg * 32 + mt * 16 + (lane & 7) + ((lane >> 3) & 1) * 8;
            u32 ch = (u32)(chBase + ks * 2 + (lane >> 4));
            u32 sw = ((ch ^ (u32)(row & 7)) << 4);
            ldm4(a_hi[mt], ahiB + ((u32)row << rowShift) + sw);
            if (both) ldm4(a_lo[mt], aloB + ((u32)row << rowShift) + sw);
        }
        u32 b0[4], b1[4];
        #pragma unroll
        for (int nt = 0; nt < 4; ++nt) {
            u32 addr = bufB + (u32)((((ng * 4 + nt) * 4 + ks) * 32 + lane) * 8);
            asm volatile("ld.shared.v2.b32 {%0,%1}, [%2];"
                : "=r"(b0[nt]), "=r"(b1[nt]) : "r"(addr));
        }
        #pragma unroll
        for (int mt = 0; mt < 2; ++mt)
            #pragma unroll
            for (int nt = 0; nt < 4; ++nt) {
                mma16816(acc[mt][nt], a_hi[mt], b0[nt], b1[nt]);
                if (both) mma16816(acc[mt][nt], a_lo[mt], b0[nt], b1[nt]);
            }
    }
}

// ---------------- main kernel: 1 window per CTA, 2 CTAs/SM ----------------
__global__ __launch_bounds__(256, 2)
void win_attn_fa2(const float* __restrict__ x,
                  const float* __restrict__ qkv_b,
                  const float* __restrict__ proj_b,
                  float* __restrict__ out, int nW)
{
    extern __shared__ __align__(1024) unsigned char sm[];
    const u32 sb = (u32)__cvta_generic_to_shared(sm);
    const int tid = threadIdx.x, lane = tid & 31, wid = tid >> 5;
    const int b = blockIdx.x;
    const int mg = wid >> 2, ng = wid & 3;     // mg in {0,1}

    issue_piece(sb, 0, tid);
    issue_piece(sb, 1, tid);

    const float* xw = x + (size_t)b * 49 * 128;

    // ======== QKV GEMM: 3 chunks (q,k,v), M=64 ========
    #pragma unroll 1
    for (int c = 0; c < 3; ++c) {
        float acc[2][4][4];
        #pragma unroll
        for (int mt = 0; mt < 2; ++mt)
            #pragma unroll
            for (int nt = 0; nt < 4; ++nt)
                #pragma unroll
                for (int e = 0; e < 4; ++e) acc[mt][nt][e] = 0.f;

        #pragma unroll 1
        for (int kh = 0; kh < 2; ++kh) {
            // build A(kh) hi/lo from gmem x (staging aliases VT-hi)
            {
                int row = tid >> 2, cg = tid & 3;   // row 0..63
                float xv[16];
                if (row < 49) {
                    const float4* src = (const float4*)(xw + (size_t)row * 128
                                                        + kh * 64 + cg * 16);
                    #pragma unroll
                    for (int q = 0; q < 4; ++q) {
                        float4 t = src[q];
                        xv[4*q] = t.x; xv[4*q+1] = t.y; xv[4*q+2] = t.z; xv[4*q+3] = t.w;
                    }
                } else {
                    #pragma unroll
                    for (int q = 0; q < 16; ++q) xv[q] = 0.f;
                }
                #pragma unroll
                for (int h = 0; h < 2; ++h) {
                    u32 hi[4], lo[4];
                    #pragma unroll
                    for (int p = 0; p < 4; ++p) {
                        float a = xv[h*8 + 2*p], bb = xv[h*8 + 2*p + 1];
                        hi[p] = pk_hi(a, bb);
                        lo[p] = pk_lo(a, bb);
                    }
                    int ch = cg * 2 + h;
                    u32 a = (u32)row * 128 + (u32)((ch ^ (row & 7)) << 4);
                    *(uint4*)(sm + OFF_AHI + a) = make_uint4(hi[0], hi[1], hi[2], hi[3]);
                    *(uint4*)(sm + OFF_ALO + a) = make_uint4(lo[0], lo[1], lo[2], lo[3]);
                }
            }
            int p = c * 4 + kh * 2;
            cp_wait<1>(); __syncthreads();
            mma_tiles(acc, sb + OFF_AHI, sb + OFF_ALO, sb + OFF_WB + (u32)(p & 1) * 16384,
                      mg, ng, lane, 7, 0, true);
            __syncthreads();
            if (p + 2 <= 12) issue_piece(sb, p + 2, tid);
            cp_wait<1>(); __syncthreads();
            mma_tiles(acc, sb + OFF_AHI, sb + OFF_ALO, sb + OFF_WB + (u32)((p + 1) & 1) * 16384,
                      mg, ng, lane, 7, 0, false);
            __syncthreads();
            if (p + 3 <= 12) issue_piece(sb, p + 3, tid);
        }

        // epilogue: write Q / K / VT as bf16 hi/lo (pad rows/cols zeroed)
        {
            int rb = mg * 32 + (lane >> 2);
            int cb = ng * 32 + (lane & 3) * 2;
            #pragma unroll
            for (int mt = 0; mt < 2; ++mt)
                #pragma unroll
                for (int rh = 0; rh < 2; ++rh) {
                    int r = rb + mt * 16 + rh * 8;     // 0..63
                    bool ok = r < 49;
                    #pragma unroll
                    for (int nt = 0; nt < 4; ++nt) {
                        int cc = cb + nt * 8;
                        float v0 = acc[mt][nt][rh*2]   + __ldg(qkv_b + c*128 + cc);
                        float v1 = acc[mt][nt][rh*2+1] + __ldg(qkv_b + c*128 + cc + 1);
                        if (c == 0) {
                            v0 = ok ? v0 * QSCALE : 0.f;
                            v1 = ok ? v1 * QSCALE : 0.f;
                            u32 byte = (u32)r * 256 + sw16(cc >> 3, r) * 16 + (cc & 7) * 2;
                            *(u32*)(sm + OFF_QHI + byte) = pk_hi(v0, v1);
                            *(u32*)(sm + OFF_QLO + byte) = pk_lo(v0, v1);
                        } else if (c == 1) {
                            if (r < 56) {
                                v0 = ok ? v0 : 0.f; v1 = ok ? v1 : 0.f;
                                u32 byte = (u32)r * 256 + sw16(cc >> 3, r) * 16 + (cc & 7) * 2;
                                *(u32*)(sm + OFF_KHI + byte) = pk_hi(v0, v1);
                                *(u32*)(sm + OFF_KLO + byte) = pk_lo(v0, v1);
                            }
                        } else {
                            v0 = ok ? v0 : 0.f; v1 = ok ? v1 : 0.f;
                            #pragma unroll
                            for (int e = 0; e < 2; ++e) {
                                float vv = e ? v1 : v0;
                                int vr = cc + e;                 // 0..127
                                u32 byte = (u32)vr * 128
                                         + (u32)((((r >> 3) ^ (vr & 7)) & 7) << 4)
                                         + (r & 7) * 2;
                                __nv_bfloat16 hb = __float2bfloat16_rn(vv);
                                *(__nv_bfloat16*)(sm + OFF_VTHI + byte) = hb;
                                *(__nv_bfloat16*)(sm + OFF_VTLO + byte) =
                                    __float2bfloat16_rn(vv - __bfloat162float(hb));
                            }
                        }
                    }
                }
        }
    }
    __syncthreads();   // Q/K/VT visible to all warps

    // ======== attention: unit = head h (2 warps each, 2 m-tiles per warp) ========
    {
        const int h = wid >> 1;
        const int g = lane >> 2, t = lane & 3;
        const float* bm = g_bm + ((size_t)(b % nW) * 4 + h) * 2744;

        #pragma unroll 1
        for (int tk = 0; tk < 2; ++tk) {
            const int mt = (wid & 1) * 2 + tk;

            // ---- S = Q @ K^T (3-pass hi/lo) ----
            float s[7][4];
            #pragma unroll
            for (int nt = 0; nt < 7; ++nt)
                #pragma unroll
                for (int e = 0; e < 4; ++e) s[nt][e] = 0.f;

            u32 aqh[2][4], aql[2][4];
            #pragma unroll
            for (int ks = 0; ks < 2; ++ks) {
                int rr = mt * 16 + (lane & 7) + ((lane >> 3) & 1) * 8;
                int ch = h * 4 + ks * 2 + (lane >> 4);
                u32 off = (u32)rr * 256 + sw16(ch, rr) * 16;
                ldm4(aqh[ks], sb + OFF_QHI + off);
                ldm4(aql[ks], sb + OFF_QLO + off);
            }
            #pragma unroll
            for (int ks = 0; ks < 2; ++ks) {
                u32 bkh[7][2], bkl[7][2];
                #pragma unroll
                for (int ntp = 0; ntp < 3; ++ntp) {
                    int kr = ntp * 16 + ((lane >> 4) << 3) + (lane & 7);
                    int ch = h * 4 + ks * 2 + ((lane >> 3) & 1);
                    u32 off = (u32)kr * 256 + sw16(ch, kr) * 16;
                    u32 r4[4];
                    ldm4(r4, sb + OFF_KHI + off);
                    bkh[2*ntp][0] = r4[0]; bkh[2*ntp][1] = r4[1];
                    bkh[2*ntp+1][0] = r4[2]; bkh[2*ntp+1][1] = r4[3];
                    ldm4(r4, sb + OFF_KLO + off);
                    bkl[2*ntp][0] = r4[0]; bkl[2*ntp][1] = r4[1];
                    bkl[2*ntp+1][0] = r4[2]; bkl[2*ntp+1][1] = r4[3];
                }
                {
                    int kr = 48 + (lane & 7);
                    int ch = h * 4 + ks * 2 + ((lane >> 3) & 1);
                    u32 off = (u32)kr * 256 + sw16(ch, kr) * 16;
                    ldm2(bkh[6], sb + OFF_KHI + off);
                    ldm2(bkl[6], sb + OFF_KLO + off);
                }
                #pragma unroll
                for (int nt = 0; nt < 7; ++nt) {
                    mma16816(s[nt], aqh[ks], bkh[nt][0], bkh[nt][1]);
                    mma16816(s[nt], aql[ks], bkh[nt][0], bkh[nt][1]);
                    mma16816(s[nt], aqh[ks], bkl[nt][0], bkl[nt][1]);
                }
            }

            // ---- +bias+mask, softmax (rows g, g+8; quad reductions) ----
            {
                int i0 = mt * 16 + g;
                int o0 = min(i0, 48) * 56, o1 = min(i0 + 8, 48) * 56;
                #pragma unroll
                for (int nt = 0; nt < 7; ++nt) {
                    int jj = nt * 8 + 2 * t;
                    float2 b0 = *(const float2*)(bm + o0 + jj);
                    float2 b1 = *(const float2*)(bm + o1 + jj);
                    s[nt][0] = (jj     < 49) ? s[nt][0] + b0.x : -1e30f;
                    s[nt][1] = (jj + 1 < 49) ? s[nt][1] + b0.y : -1e30f;
                    s[nt][2] = (jj     < 49) ? s[nt][2] + b1.x : -1e30f;
                    s[nt][3] = (jj + 1 < 49) ? s[nt][3] + b1.y : -1e30f;
                }
                float m0 = -1e30f, m1 = -1e30f;
                #pragma unroll
                for (int nt = 0; nt < 7; ++nt) {
                    m0 = fmaxf(m0, fmaxf(s[nt][0], s[nt][1]));
                    m1 = fmaxf(m1, fmaxf(s[nt][2], s[nt][3]));
                }
                m0 = fmaxf(m0, __shfl_xor_sync(0xffffffffu, m0, 1));
                m1 = fmaxf(m1, __shfl_xor_sync(0xffffffffu, m1, 1));
                m0 = fmaxf(m0, __shfl_xor_sync(0xffffffffu, m0, 2));
                m1 = fmaxf(m1, __shfl_xor_sync(0xffffffffu, m1, 2));
                float s0 = 0.f, s1 = 0.f;
                #pragma unroll
                for (int nt = 0; nt < 7; ++nt) {
                    s[nt][0] = __expf(s[nt][0] - m0); s0 += s[nt][0];
                    s[nt][1] = __expf(s[nt][1] - m0); s0 += s[nt][1];
                    s[nt][2] = __expf(s[nt][2] - m1); s1 += s[nt][2];
                    s[nt][3] = __expf(s[nt][3] - m1); s1 += s[nt][3];
                }
                s0 += __shfl_xor_sync(0xffffffffu, s0, 1);
                s1 += __shfl_xor_sync(0xffffffffu, s1, 1);
                s0 += __shfl_xor_sync(0xffffffffu, s0, 2);
                s1 += __shfl_xor_sync(0xffffffffu, s1, 2);
                float i0v = 1.f / s0, i1v = 1.f / s1;
                #pragma unroll
                for (int nt = 0; nt < 7; ++nt) {
                    s[nt][0] *= i0v; s[nt][1] *= i0v;
                    s[nt][2] *= i1v; s[nt][3] *= i1v;
                }
            }

            // ---- pack P fragments (S frags map 1:1 onto A frags) ----
            u32 ph[4][4], pl[4][4];
            #pragma unroll
            for (int k2 = 0; k2 < 4; ++k2) {
                int na = 2 * k2, nb = 2 * k2 + 1;
                ph[k2][0] = pk_hi(s[na][0], s[na][1]);
                ph[k2][1] = pk_hi(s[na][2], s[na][3]);
                pl[k2][0] = pk_lo(s[na][0], s[na][1]);
                pl[k2][1] = pk_lo(s[na][2], s[na][3]);
                if (nb < 7) {
                    ph[k2][2] = pk_hi(s[nb][0], s[nb][1]);
                    ph[k2][3] = pk_hi(s[nb][2], s[nb][3]);
                    pl[k2][2] = pk_lo(s[nb][0], s[nb][1]);
                    pl[k2][3] = pk_lo(s[nb][2], s[nb][3]);
                } else {
                    ph[k2][2] = ph[k2][3] = pl[k2][2] = pl[k2][3] = 0u;
                }
            }

            // ---- O = P @ V (3-pass) ----
            float o[4][4];
            #pragma unroll
            for (int nt = 0; nt < 4; ++nt)
                #pragma unroll
                for (int e = 0; e < 4; ++e) o[nt][e] = 0.f;
            #pragma unroll
            for (int k2 = 0; k2 < 4; ++k2) {
                u32 bvh[4][2], bvl[4][2];
                #pragma unroll
                for (int dp = 0; dp < 2; ++dp) {
                    int vr = h * 32 + dp * 16 + ((lane >> 4) << 3) + (lane & 7);
                    int ch = k2 * 2 + ((lane >> 3) & 1);
                    u32 off = (u32)vr * 128 + (u32)(((ch ^ (vr & 7)) & 7) << 4);
                    u32 r4[4];
                    ldm4(r4, sb + OFF_VTHI + off);
                    bvh[2*dp][0] = r4[0]; bvh[2*dp][1] = r4[1];
                    bvh[2*dp+1][0] = r4[2]; bvh[2*dp+1][1] = r4[3];
                    ldm4(r4, sb + OFF_VTLO + off);
                    bvl[2*dp][0] = r4[0]; bvl[2*dp][1] = r4[1];
                    bvl[2*dp+1][0] = r4[2]; bvl[2*dp+1][1] = r4[3];
                }
                #pragma unroll
                for (int nt = 0; nt < 4; ++nt) {
                    mma16816(o[nt], ph[k2], bvh[nt][0], bvh[nt][1]);
                    mma16816(o[nt], pl[k2], bvh[nt][0], bvh[nt][1]);
                    mma16816(o[nt], ph[k2], bvl[nt][0], bvl[nt][1]);
                }
            }

            // ---- write O hi/lo into proj-A layout (aliases dead Q cols) ----
            #pragma unroll
            for (int nt = 0; nt < 4; ++nt)
                #pragma unroll
                for (int rh = 0; rh < 2; ++rh) {
                    int r = mt * 16 + g + rh * 8;
                    int col = h * 32 + nt * 8 + 2 * t;
                    u32 byte = (u32)r * 256 + sw16(col >> 3, r) * 16 + (col & 7) * 2;
                    *(u32*)(sm + OFF_PHI + byte) = pk_hi(o[nt][rh*2], o[nt][rh*2+1]);
                    *(u32*)(sm + OFF_PLO + byte) = pk_lo(o[nt][rh*2], o[nt][rh*2+1]);
                }
        }
    }
    __syncthreads();

    // ======== proj GEMM (pieces 12..15; 12 prefetched during attention) ========
    issue_piece(sb, 13, tid);   // WB1 (was VT-lo; dead after attention)

    float pacc[2][4][4];
    #pragma unroll
    for (int mt = 0; mt < 2; ++mt)
        #pragma unroll
        for (int nt = 0; nt < 4; ++nt)
            #pragma unroll
            for (int e = 0; e < 4; ++e) pacc[mt][nt][e] = 0.f;

    cp_wait<1>(); __syncthreads();
    mma_tiles(pacc, sb + OFF_PHI, sb + OFF_PLO, sb + OFF_WB, mg, ng, lane, 8, 0, true);
    __syncthreads();
    issue_piece(sb, 14, tid);
    cp_wait<1>(); __syncthreads();
    mma_tiles(pacc, sb + OFF_PHI, sb + OFF_PLO, sb + OFF_WB + 16384, mg, ng, lane, 8, 0, false);
    __syncthreads();
    issue_piece(sb, 15, tid);
    cp_wait<1>(); __syncthreads();
    mma_tiles(pacc, sb + OFF_PHI, sb + OFF_PLO, sb + OFF_WB, mg, ng, lane, 8, 8, true);
    __syncthreads();
    cp_wait<0>(); __syncthreads();
    mma_tiles(pacc, sb + OFF_PHI, sb + OFF_PLO, sb + OFF_WB + 16384, mg, ng, lane, 8, 8, false);

    // proj epilogue -> gmem (+bias)
    {
        int rb = mg * 32 + (lane >> 2);
        int cb = ng * 32 + (lane & 3) * 2;
        #pragma unroll
        for (int mt = 0; mt < 2; ++mt)
            #pragma unroll
            for (int rh = 0; rh < 2; ++rh) {
                int r = rb + mt * 16 + rh * 8;
                if (r < 49) {
                    float* go = out + ((size_t)b * 49 + r) * 128;
                    #pragma unroll
                    for (int nt = 0; nt < 4; ++nt) {
                        int cc = cb + nt * 8;
                        float v0 = pacc[mt][nt][rh*2]   + __ldg(proj_b + cc);
                        float v1 = pacc[mt][nt][rh*2+1] + __ldg(proj_b + cc + 1);
                        *(float2*)(go + cc) = make_float2(v0, v1);
                    }
                }
            }
    }
}

extern "C" void kernel_launch(void* const* d_in, const int* in_sizes, int n_in,
                              void* d_out, int out_size)
{
    const float* x      = (const float*)d_in[0];
    const float* mask   = (const float*)d_in[1];
    const float* qkv_w  = (const float*)d_in[2];
    const float* qkv_b  = (const float*)d_in[3];
    const float* proj_w = (const float*)d_in[4];
    const float* proj_b = (const float*)d_in[5];
    const float* table  = (const float*)d_in[6];
    const int*   relidx = (const int*)d_in[7];
    float*       out    = (float*)d_out;

    const int B  = in_sizes[0] / (49 * 128);
    const int nW = in_sizes[1] / (49 * 49);

    prep_all<<<2872, 256>>>(qkv_w, proj_w, mask, table, relidx, nW);

    cudaFuncSetAttribute(win_attn_fa2,
                         cudaFuncAttributeMaxDynamicSharedMemorySize, SMEM_BYTES);
    win_attn_fa2<<<B, 256, SMEM_BYTES>>>(x, qkv_b, proj_b, out, nW);
}

// round 9
// speedup vs baseline: 1.0806x; 1.0806x over previous
#include <cuda_runtime.h>
#include <cuda_bf16.h>
#include <cstdint>

typedef unsigned int u32;

#define QSCALE 0.17677669529663687f

// ---- smem byte offsets (2 windows per CTA, 221184 B) ----
#define OFF_WB    0         /* 2 x 16384 weight ping-pong            */
#define OFF_QHI   32768     /* Q bf16 hi  [128 rows][256B]           */
#define OFF_QLO   65536
#define OFF_KHI   98304     /* K bf16 hi  [112 rows (2x56)][256B]    */
#define OFF_KLO   126976
#define OFF_AFHI  155648    /* A full hi [128 rows][256B] (VT alias) */
#define OFF_AFLO  188416    /* A full lo                             */
#define OFF_VTHI  155648    /* VT bf16 hi [256 rows][128B]           */
#define OFF_VTLO  188416
#define OFF_PHI   32768     /* proj A' hi (alias Q hi)               */
#define OFF_PLO   65536
#define SMEM_BYTES 221184

// pre-packed bf16 weight fragments (round-6/7 validated layout)
__device__ __align__(16) unsigned char g_wq[196608];
__device__ __align__(16) unsigned char g_wp[65536];
// combined bias+mask table: [w<64][h<4][i<49][j stride 56]
__device__ __align__(16) float g_bm[702464];

__device__ __forceinline__ u32 sw16(int ch, int r) {
    return (u32)((ch & 8) | ((ch ^ (r & 7)) & 7));
}

// ---------------- prep kernel (unchanged, RN splits) ----------------
__global__ void prep_all(const float* __restrict__ qkv_w,
                         const float* __restrict__ proj_w,
                         const float* __restrict__ mask,
                         const float* __restrict__ bias_table,
                         const int*   __restrict__ rel_index,
                         int nW) {
    int e = blockIdx.x * 256 + threadIdx.x;
    if (e < 32768) {
        bool isq = e < 24576;
        int idx = isq ? e : e - 24576;
        const float* W = isq ? qkv_w : proj_w;
        unsigned char* dst = isq ? g_wq : g_wp;
        int ldw = isq ? 384 : 128;
        int piece = idx >> 11;
        int rem = idx & 2047;
        int lane = rem & 31, ks = (rem >> 5) & 3, nt = rem >> 7;
        int chunk = isq ? (piece >> 2) : 0;
        int kh = isq ? ((piece >> 1) & 1) : (piece >> 1);
        int part = piece & 1;
        int k0 = kh * 64 + ks * 16 + (lane & 3) * 2;
        int n  = chunk * 128 + nt * 8 + (lane >> 2);
        float v0 = W[k0 * ldw + n],       v1 = W[(k0 + 1) * ldw + n];
        float v2 = W[(k0 + 8) * ldw + n], v3 = W[(k0 + 9) * ldw + n];
        __nv_bfloat16 h0 = __float2bfloat16_rn(v0), h1 = __float2bfloat16_rn(v1);
        __nv_bfloat16 h2 = __float2bfloat16_rn(v2), h3 = __float2bfloat16_rn(v3);
        __nv_bfloat162 r0, r1;
        if (part == 0) {
            r0 = __halves2bfloat162(h0, h1);
            r1 = __halves2bfloat162(h2, h3);
        } else {
            r0 = __halves2bfloat162(__float2bfloat16_rn(v0 - __bfloat162float(h0)),
                                    __float2bfloat16_rn(v1 - __bfloat162float(h1)));
            r1 = __halves2bfloat162(__float2bfloat16_rn(v2 - __bfloat162float(h2)),
                                    __float2bfloat16_rn(v3 - __bfloat162float(h3)));
        }
        *(__nv_bfloat162*)(dst + (size_t)idx * 8)     = r0;
        *(__nv_bfloat162*)(dst + (size_t)idx * 8 + 4) = r1;
    } else {
        int idx = e - 32768;
        if (idx < 702464) {
            int w = idx / 10976;
            int r = idx % 10976;
            int h = r / 2744;
            int r2 = r % 2744;
            int i = r2 / 56, j = r2 % 56;
            float val = 0.f;
            if (j < 49 && w < nW)
                val = bias_table[rel_index[i * 49 + j] * 4 + h] + mask[w * 2401 + i * 49 + j];
            g_bm[idx] = val;
        }
    }
}

// ---------------- PTX helpers ----------------
__device__ __forceinline__ void cp16(u32 dst, const void* src) {
    asm volatile("cp.async.cg.shared.global [%0], [%1], 16;" :: "r"(dst), "l"(src));
}
__device__ __forceinline__ void cp_commit() { asm volatile("cp.async.commit_group;"); }
template <int N> __device__ __forceinline__ void cp_wait() {
    asm volatile("cp.async.wait_group %0;" :: "n"(N));
}
__device__ __forceinline__ void ldm4(u32 r[4], u32 addr) {
    asm volatile("ldmatrix.sync.aligned.m8n8.x4.shared.b16 {%0,%1,%2,%3}, [%4];"
        : "=r"(r[0]), "=r"(r[1]), "=r"(r[2]), "=r"(r[3]) : "r"(addr));
}
__device__ __forceinline__ void ldm2(u32 r[2], u32 addr) {
    asm volatile("ldmatrix.sync.aligned.m8n8.x2.shared.b16 {%0,%1}, [%2];"
        : "=r"(r[0]), "=r"(r[1]) : "r"(addr));
}
__device__ __forceinline__ void mma16816(float c[4], const u32 a[4], u32 b0, u32 b1) {
    asm volatile("mma.sync.aligned.m16n8k16.row.col.f32.bf16.bf16.f32 "
        "{%0,%1,%2,%3}, {%4,%5,%6,%7}, {%8,%9}, {%0,%1,%2,%3};"
        : "+f"(c[0]), "+f"(c[1]), "+f"(c[2]), "+f"(c[3])
        : "r"(a[0]), "r"(a[1]), "r"(a[2]), "r"(a[3]), "r"(b0), "r"(b1));
}
// PRMT-based bf16 hi/lo split (truncation; lo captures residual)
__device__ __forceinline__ u32 pk_hi(float a, float b) {
    u32 r;
    asm("prmt.b32 %0, %1, %2, 0x7632;" : "=r"(r)
        : "r"(__float_as_uint(a)), "r"(__float_as_uint(b)));
    return r;
}
__device__ __forceinline__ u32 pk_lo(float a, float b) {
    float ah = __uint_as_float(__float_as_uint(a) & 0xFFFF0000u);
    float bh = __uint_as_float(__float_as_uint(b) & 0xFFFF0000u);
    return pk_hi(a - ah, b - bh);
}

// issue one 16KB weight piece into ping-pong buffer (piece i -> buf i&1)
__device__ __forceinline__ void issue_piece(u32 sb, int i, int tid) {
    const unsigned char* src =
        (i < 12 ? g_wq + (u32)i * 16384 : g_wp + (u32)(i - 12) * 16384) + tid * 32;
    u32 dst = sb + OFF_WB + (u32)(i & 1) * 16384 + (u32)tid * 32;
    cp16(dst, src); cp16(dst + 16, src + 16);
    cp_commit();
}

// one k-half (4 ksteps) of mma over 2 m-tiles x 4 n-tiles (weight GEMMs)
__device__ __forceinline__ void mma_tiles(float acc[2][4][4],
    u32 ahiB, u32 aloB, u32 bufB, int mg, int ng, int lane,
    int chBase, bool both)
{
    #pragma unroll
    for (int ks = 0; ks < 4; ++ks) {
        u32 a_hi[2][4], a_lo[2][4];
        #pragma unroll
        for (int mt = 0; mt < 2; ++mt) {
            int row = mg * 32 + mt * 16 + (lane & 7) + ((lane >> 3) & 1) * 8;
            int ch = chBase + ks * 2 + (lane >> 4);
            u32 off = (u32)row * 256 + sw16(ch, row) * 16;
            ldm4(a_hi[mt], ahiB + off);
            if (both) ldm4(a_lo[mt], aloB + off);
        }
        u32 b0[4], b1[4];
        #pragma unroll
        for (int nt = 0; nt < 4; ++nt) {
            u32 addr = bufB + (u32)((((ng * 4 + nt) * 4 + ks) * 32 + lane) * 8);
            asm volatile("ld.shared.v2.b32 {%0,%1}, [%2];"
                : "=r"(b0[nt]), "=r"(b1[nt]) : "r"(addr));
        }
        #pragma unroll
        for (int mt = 0; mt < 2; ++mt)
            #pragma unroll
            for (int nt = 0; nt < 4; ++nt) {
                mma16816(acc[mt][nt], a_hi[mt], b0[nt], b1[nt]);
                if (both) mma16816(acc[mt][nt], a_lo[mt], b0[nt], b1[nt]);
            }
    }
}

// ---------------- main kernel: 2 windows per CTA, all-HMMA ----------------
__global__ __launch_bounds__(512, 1)
void win_attn_fa3(const float* __restrict__ x,
                  const float* __restrict__ qkv_b,
                  const float* __restrict__ proj_b,
                  float* __restrict__ out, int nW)
{
    extern __shared__ __align__(1024) unsigned char sm[];
    const u32 sb = (u32)__cvta_generic_to_shared(sm);
    const int tid = threadIdx.x, lane = tid & 31, wid = tid >> 5;
    const int b = blockIdx.x;
    const int mg = wid >> 2, ng = wid & 3;

    issue_piece(sb, 0, tid);
    issue_piece(sb, 1, tid);

    const float* xw = x + (size_t)(2 * b) * 49 * 128;

    // ---- build FULL A hi/lo once: [128 rows][K=128] ----
    {
        int row = tid >> 2, cg = tid & 3;           // cg: 32-K-col group
        int win = row >> 6, nr = row & 63;
        float xv[32];
        if (nr < 49) {
            const float4* src = (const float4*)(xw + ((size_t)win * 49 + nr) * 128 + cg * 32);
            #pragma unroll
            for (int q = 0; q < 8; ++q) {
                float4 t = src[q];
                xv[4*q] = t.x; xv[4*q+1] = t.y; xv[4*q+2] = t.z; xv[4*q+3] = t.w;
            }
        } else {
            #pragma unroll
            for (int q = 0; q < 32; ++q) xv[q] = 0.f;
        }
        #pragma unroll
        for (int h = 0; h < 4; ++h) {
            u32 hi[4], lo[4];
            #pragma unroll
            for (int p = 0; p < 4; ++p) {
                float a = xv[h*8 + 2*p], bb = xv[h*8 + 2*p + 1];
                hi[p] = pk_hi(a, bb);
                lo[p] = pk_lo(a, bb);
            }
            int ch = cg * 4 + h;
            u32 off = (u32)row * 256 + sw16(ch, row) * 16;
            *(uint4*)(sm + OFF_AFHI + off) = make_uint4(hi[0], hi[1], hi[2], hi[3]);
            *(uint4*)(sm + OFF_AFLO + off) = make_uint4(lo[0], lo[1], lo[2], lo[3]);
        }
    }

    // ======== QKV GEMM: 3 chunks (q,k,v) ========
    #pragma unroll 1
    for (int c = 0; c < 3; ++c) {
        float acc[2][4][4];
        #pragma unroll
        for (int mt = 0; mt < 2; ++mt)
            #pragma unroll
            for (int nt = 0; nt < 4; ++nt)
                #pragma unroll
                for (int e = 0; e < 4; ++e) acc[mt][nt][e] = 0.f;

        #pragma unroll 1
        for (int kh = 0; kh < 2; ++kh) {
            int p = c * 4 + kh * 2;
            cp_wait<1>(); __syncthreads();
            mma_tiles(acc, sb + OFF_AFHI, sb + OFF_AFLO, sb + OFF_WB + (u32)(p & 1) * 16384,
                      mg, ng, lane, kh * 8, true);
            __syncthreads();
            issue_piece(sb, p + 2, tid);
            cp_wait<1>(); __syncthreads();
            mma_tiles(acc, sb + OFF_AFHI, sb + OFF_AFLO, sb + OFF_WB + (u32)((p + 1) & 1) * 16384,
                      mg, ng, lane, kh * 8, false);
            __syncthreads();
            issue_piece(sb, p + 3, tid);
        }

        // epilogue: Q / K / VT (VT aliases A — safe: A dead after c==2 MMAs + barrier)
        {
            int rb = mg * 32 + (lane >> 2);
            int cb = ng * 32 + (lane & 3) * 2;
            #pragma unroll
            for (int mt = 0; mt < 2; ++mt)
                #pragma unroll
                for (int rh = 0; rh < 2; ++rh) {
                    int r = rb + mt * 16 + rh * 8;
                    int win = r >> 6, nr = r & 63;
                    bool ok = nr < 49;
                    #pragma unroll
                    for (int nt = 0; nt < 4; ++nt) {
                        int cc = cb + nt * 8;
                        float v0 = acc[mt][nt][rh*2]   + __ldg(qkv_b + c*128 + cc);
                        float v1 = acc[mt][nt][rh*2+1] + __ldg(qkv_b + c*128 + cc + 1);
                        if (c == 0) {
                            v0 = ok ? v0 * QSCALE : 0.f;
                            v1 = ok ? v1 * QSCALE : 0.f;
                            u32 byte = (u32)r * 256 + sw16(cc >> 3, r) * 16 + (cc & 7) * 2;
                            *(u32*)(sm + OFF_QHI + byte) = pk_hi(v0, v1);
                            *(u32*)(sm + OFF_QLO + byte) = pk_lo(v0, v1);
                        } else if (c == 1) {
                            if (nr < 56) {
                                v0 = ok ? v0 : 0.f; v1 = ok ? v1 : 0.f;
                                int kr = win * 56 + nr;
                                u32 byte = (u32)kr * 256 + sw16(cc >> 3, kr) * 16 + (cc & 7) * 2;
                                *(u32*)(sm + OFF_KHI + byte) = pk_hi(v0, v1);
                                *(u32*)(sm + OFF_KLO + byte) = pk_lo(v0, v1);
                            }
                        } else {
                            v0 = ok ? v0 : 0.f; v1 = ok ? v1 : 0.f;
                            #pragma unroll
                            for (int e = 0; e < 2; ++e) {
                                float vv = e ? v1 : v0;
                                int vr = win * 128 + cc + e;
                                u32 byte = (u32)vr * 128
                                         + (u32)((((nr >> 3) ^ (vr & 7)) & 7) << 4)
                                         + (nr & 7) * 2;
                                u32 bits = __float_as_uint(vv);
                                *(unsigned short*)(sm + OFF_VTHI + byte) =
                                    (unsigned short)(bits >> 16);
                                float hif = __uint_as_float(bits & 0xFFFF0000u);
                                *(unsigned short*)(sm + OFF_VTLO + byte) =
                                    (unsigned short)(__float_as_uint(vv - hif) >> 16);
                            }
                        }
                    }
                }
        }
        if (c == 1) __syncthreads();   // keep K fully written before attention warps race ahead later
    }
    __syncthreads();   // Q/K/VT visible to all warps

    // ======== attention: unit = (win, head), warp handles 2 m-tiles ========
    {
        const int unit = wid >> 1, win = unit >> 2, h = unit & 3;
        const int g = lane >> 2, t = lane & 3;
        const float* bm = g_bm + ((size_t)((2 * b + win) % nW) * 4 + h) * 2744;

        #pragma unroll 1
        for (int tk = 0; tk < 2; ++tk) {
            const int mt = (wid & 1) * 2 + tk;

            float s[7][4];
            #pragma unroll
            for (int nt = 0; nt < 7; ++nt)
                #pragma unroll
                for (int e = 0; e < 4; ++e) s[nt][e] = 0.f;

            u32 aqh[2][4], aql[2][4];
            #pragma unroll
            for (int ks = 0; ks < 2; ++ks) {
                int rr = win * 64 + mt * 16 + (lane & 7) + ((lane >> 3) & 1) * 8;
                int ch = h * 4 + ks * 2 + (lane >> 4);
                u32 off = (u32)rr * 256 + sw16(ch, rr) * 16;
                ldm4(aqh[ks], sb + OFF_QHI + off);
                ldm4(aql[ks], sb + OFF_QLO + off);
            }
            #pragma unroll
            for (int ks = 0; ks < 2; ++ks) {
                u32 bkh[7][2], bkl[7][2];
                #pragma unroll
                for (int ntp = 0; ntp < 3; ++ntp) {
                    int kr = win * 56 + ntp * 16 + ((lane >> 4) << 3) + (lane & 7);
                    int ch = h * 4 + ks * 2 + ((lane >> 3) & 1);
                    u32 off = (u32)kr * 256 + sw16(ch, kr) * 16;
                    u32 r4[4];
                    ldm4(r4, sb + OFF_KHI + off);
                    bkh[2*ntp][0] = r4[0]; bkh[2*ntp][1] = r4[1];
                    bkh[2*ntp+1][0] = r4[2]; bkh[2*ntp+1][1] = r4[3];
                    ldm4(r4, sb + OFF_KLO + off);
                    bkl[2*ntp][0] = r4[0]; bkl[2*ntp][1] = r4[1];
                    bkl[2*ntp+1][0] = r4[2]; bkl[2*ntp+1][1] = r4[3];
                }
                {
                    int kr = win * 56 + 48 + (lane & 7);
                    int ch = h * 4 + ks * 2 + ((lane >> 3) & 1);
                    u32 off = (u32)kr * 256 + sw16(ch, kr) * 16;
                    ldm2(bkh[6], sb + OFF_KHI + off);
                    ldm2(bkl[6], sb + OFF_KLO + off);
                }
                #pragma unroll
                for (int nt = 0; nt < 7; ++nt) {
                    mma16816(s[nt], aqh[ks], bkh[nt][0], bkh[nt][1]);
                    mma16816(s[nt], aql[ks], bkh[nt][0], bkh[nt][1]);
                    mma16816(s[nt], aqh[ks], bkl[nt][0], bkl[nt][1]);
                }
            }

            // +bias+mask, softmax (rows g, g+8; quad reductions)
            {
                int i0 = mt * 16 + g;
                int o0 = min(i0, 48) * 56, o1 = min(i0 + 8, 48) * 56;
                #pragma unroll
                for (int nt = 0; nt < 7; ++nt) {
                    int jj = nt * 8 + 2 * t;
                    float2 b0 = *(const float2*)(bm + o0 + jj);
                    float2 b1 = *(const float2*)(bm + o1 + jj);
                    s[nt][0] = (jj     < 49) ? s[nt][0] + b0.x : -1e30f;
                    s[nt][1] = (jj + 1 < 49) ? s[nt][1] + b0.y : -1e30f;
                    s[nt][2] = (jj     < 49) ? s[nt][2] + b1.x : -1e30f;
                    s[nt][3] = (jj + 1 < 49) ? s[nt][3] + b1.y : -1e30f;
                }
                float m0 = -1e30f, m1 = -1e30f;
                #pragma unroll
                for (int nt = 0; nt < 7; ++nt) {
                    m0 = fmaxf(m0, fmaxf(s[nt][0], s[nt][1]));
                    m1 = fmaxf(m1, fmaxf(s[nt][2], s[nt][3]));
                }
                m0 = fmaxf(m0, __shfl_xor_sync(0xffffffffu, m0, 1));
                m1 = fmaxf(m1, __shfl_xor_sync(0xffffffffu, m1, 1));
                m0 = fmaxf(m0, __shfl_xor_sync(0xffffffffu, m0, 2));
                m1 = fmaxf(m1, __shfl_xor_sync(0xffffffffu, m1, 2));
                float s0 = 0.f, s1 = 0.f;
                #pragma unroll
                for (int nt = 0; nt < 7; ++nt) {
                    s[nt][0] = __expf(s[nt][0] - m0); s0 += s[nt][0];
                    s[nt][1] = __expf(s[nt][1] - m0); s0 += s[nt][1];
                    s[nt][2] = __expf(s[nt][2] - m1); s1 += s[nt][2];
                    s[nt][3] = __expf(s[nt][3] - m1); s1 += s[nt][3];
                }
                s0 += __shfl_xor_sync(0xffffffffu, s0, 1);
                s1 += __shfl_xor_sync(0xffffffffu, s1, 1);
                s0 += __shfl_xor_sync(0xffffffffu, s0, 2);
                s1 += __shfl_xor_sync(0xffffffffu, s1, 2);
                float i0v = 1.f / s0, i1v = 1.f / s1;
                #pragma unroll
                for (int nt = 0; nt < 7; ++nt) {
                    s[nt][0] *= i0v; s[nt][1] *= i0v;
                    s[nt][2] *= i1v; s[nt][3] *= i1v;
                }
            }

            // pack P fragments
            u32 ph[4][4], pl[4][4];
            #pragma unroll
            for (int k2 = 0; k2 < 4; ++k2) {
                int na = 2 * k2, nb = 2 * k2 + 1;
                ph[k2][0] = pk_hi(s[na][0], s[na][1]);
                ph[k2][1] = pk_hi(s[na][2], s[na][3]);
                pl[k2][0] = pk_lo(s[na][0], s[na][1]);
                pl[k2][1] = pk_lo(s[na][2], s[na][3]);
                if (nb < 7) {
                    ph[k2][2] = pk_hi(s[nb][0], s[nb][1]);
                    ph[k2][3] = pk_hi(s[nb][2], s[nb][3]);
                    pl[k2][2] = pk_lo(s[nb][0], s[nb][1]);
                    pl[k2][3] = pk_lo(s[nb][2], s[nb][3]);
                } else {
                    ph[k2][2] = ph[k2][3] = pl[k2][2] = pl[k2][3] = 0u;
                }
            }

            // O = P @ V (3-pass)
            float o[4][4];
            #pragma unroll
            for (int nt = 0; nt < 4; ++nt)
                #pragma unroll
                for (int e = 0; e < 4; ++e) o[nt][e] = 0.f;
            #pragma unroll
            for (int k2 = 0; k2 < 4; ++k2) {
                u32 bvh[4][2], bvl[4][2];
                #pragma unroll
                for (int dp = 0; dp < 2; ++dp) {
                    int vr = win * 128 + h * 32 + dp * 16 + ((lane >> 4) << 3) + (lane & 7);
                    int ch = k2 * 2 + ((lane >> 3) & 1);
                    u32 off = (u32)vr * 128 + (u32)(((ch ^ (vr & 7)) & 7) << 4);
                    u32 r4[4];
                    ldm4(r4, sb + OFF_VTHI + off);
                    bvh[2*dp][0] = r4[0]; bvh[2*dp][1] = r4[1];
                    bvh[2*dp+1][0] = r4[2]; bvh[2*dp+1][1] = r4[3];
                    ldm4(r4, sb + OFF_VTLO + off);
                    bvl[2*dp][0] = r4[0]; bvl[2*dp][1] = r4[1];
                    bvl[2*dp+1][0] = r4[2]; bvl[2*dp+1][1] = r4[3];
                }
                #pragma unroll
                for (int nt = 0; nt < 4; ++nt) {
                    mma16816(o[nt], ph[k2], bvh[nt][0], bvh[nt][1]);
                    mma16816(o[nt], pl[k2], bvh[nt][0], bvh[nt][1]);
                    mma16816(o[nt], ph[k2], bvl[nt][0], bvl[nt][1]);
                }
            }

            // write O hi/lo into proj-A layout (aliases dead Q)
            #pragma unroll
            for (int nt = 0; nt < 4; ++nt)
                #pragma unroll
                for (int rh = 0; rh < 2; ++rh) {
                    int r = win * 64 + mt * 16 + g + rh * 8;
                    int col = h * 32 + nt * 8 + 2 * t;
                    u32 byte = (u32)r * 256 + sw16(col >> 3, r) * 16 + (col & 7) * 2;
                    *(u32*)(sm + OFF_PHI + byte) = pk_hi(o[nt][rh*2], o[nt][rh*2+1]);
                    *(u32*)(sm + OFF_PLO + byte) = pk_lo(o[nt][rh*2], o[nt][rh*2+1]);
                }
        }
    }
    __syncthreads();

    // ======== proj GEMM (pieces 12,13 prefetched during QKV tail/attention) ========
    float pacc[2][4][4];
    #pragma unroll
    for (int mt = 0; mt < 2; ++mt)
        #pragma unroll
        for (int nt = 0; nt < 4; ++nt)
            #pragma unroll
            for (int e = 0; e < 4; ++e) pacc[mt][nt][e] = 0.f;

    cp_wait<1>(); __syncthreads();
    mma_tiles(pacc, sb + OFF_PHI, sb + OFF_PLO, sb + OFF_WB, mg, ng, lane, 0, true);
    __syncthreads();
    issue_piece(sb, 14, tid);
    cp_wait<1>(); __syncthreads();
    mma_tiles(pacc, sb + OFF_PHI, sb + OFF_PLO, sb + OFF_WB + 16384, mg, ng, lane, 0, false);
    __syncthreads();
    issue_piece(sb, 15, tid);
    cp_wait<1>(); __syncthreads();
    mma_tiles(pacc, sb + OFF_PHI, sb + OFF_PLO, sb + OFF_WB, mg, ng, lane, 8, true);
    __syncthreads();
    cp_wait<0>(); __syncthreads();
    mma_tiles(pacc, sb + OFF_PHI, sb + OFF_PLO, sb + OFF_WB + 16384, mg, ng, lane, 8, false);

    // proj epilogue -> gmem (+bias)
    {
        int rb = mg * 32 + (lane >> 2);
        int cb = ng * 32 + (lane & 3) * 2;
        #pragma unroll
        for (int mt = 0; mt < 2; ++mt)
            #pragma unroll
            for (int rh = 0; rh < 2; ++rh) {
                int r = rb + mt * 16 + rh * 8;
                int win = r >> 6, nr = r & 63;
                if (nr < 49) {
                    float* go = out + ((size_t)(2*b + win) * 49 + nr) * 128;
                    #pragma unroll
                    for (int nt = 0; nt < 4; ++nt) {
                        int cc = cb + nt * 8;
                        float v0 = pacc[mt][nt][rh*2]   + __ldg(proj_b + cc);
                        float v1 = pacc[mt][nt][rh*2+1] + __ldg(proj_b + cc + 1);
                        *(float2*)(go + cc) = make_float2(v0, v1);
                    }
                }
            }
    }
}

extern "C" void kernel_launch(void* const* d_in, const int* in_sizes, int n_in,
                              void* d_out, int out_size)
{
    const float* x      = (const float*)d_in[0];
    const float* mask   = (const float*)d_in[1];
    const float* qkv_w  = (const float*)d_in[2];
    const float* qkv_b  = (const float*)d_in[3];
    const float* proj_w = (const float*)d_in[4];
    const float* proj_b = (const float*)d_in[5];
    const float* table  = (const float*)d_in[6];
    const int*   relidx = (const int*)d_in[7];
    float*       out    = (float*)d_out;

    const int B  = in_sizes[0] / (49 * 128);
    const int nW = in_sizes[1] / (49 * 49);

    prep_all<<<2872, 256>>>(qkv_w, proj_w, mask, table, relidx, nW);

    cudaFuncSetAttribute(win_attn_fa3,
                         cudaFuncAttributeMaxDynamicSharedMemorySize, SMEM_BYTES);
    win_attn_fa3<<<B / 2, 512, SMEM_BYTES>>>(x, qkv_b, proj_b, out, nW);
}

// round 10
// speedup vs baseline: 1.0923x; 1.0107x over previous
#include <cuda_runtime.h>
#include <cuda_bf16.h>
#include <cstdint>

typedef unsigned int u32;

#define QSCALE 0.17677669529663687f

// ---- smem byte offsets (2 windows per CTA, 221184 B) ----
#define OFF_WB    0         /* 2 x 16384 weight ping-pong            */
#define OFF_QHI   32768     /* Q bf16 hi  [128 rows][256B]           */
#define OFF_QLO   65536
#define OFF_KHI   98304     /* K bf16 hi  [112 rows (2x56)][256B]    */
#define OFF_KLO   126976
#define OFF_AFHI  155648    /* A full hi [128 rows][256B] (VT alias) */
#define OFF_AFLO  188416    /* A full lo                             */
#define OFF_VTHI  155648    /* VT bf16 hi [256 rows][128B]           */
#define OFF_VTLO  188416
#define OFF_PHI   32768     /* proj A' hi (alias Q hi)               */
#define OFF_PLO   65536
#define SMEM_BYTES 221184

__device__ __align__(16) unsigned char g_wq[196608];
__device__ __align__(16) unsigned char g_wp[65536];
__device__ __align__(16) float g_bm[702464];

__device__ __forceinline__ u32 sw16(int ch, int r) {
    return (u32)((ch & 8) | ((ch ^ (r & 7)) & 7));
}

// ---------------- prep kernel (unchanged) ----------------
__global__ void prep_all(const float* __restrict__ qkv_w,
                         const float* __restrict__ proj_w,
                         const float* __restrict__ mask,
                         const float* __restrict__ bias_table,
                         const int*   __restrict__ rel_index,
                         int nW) {
    int e = blockIdx.x * 256 + threadIdx.x;
    if (e < 32768) {
        bool isq = e < 24576;
        int idx = isq ? e : e - 24576;
        const float* W = isq ? qkv_w : proj_w;
        unsigned char* dst = isq ? g_wq : g_wp;
        int ldw = isq ? 384 : 128;
        int piece = idx >> 11;
        int rem = idx & 2047;
        int lane = rem & 31, ks = (rem >> 5) & 3, nt = rem >> 7;
        int chunk = isq ? (piece >> 2) : 0;
        int kh = isq ? ((piece >> 1) & 1) : (piece >> 1);
        int part = piece & 1;
        int k0 = kh * 64 + ks * 16 + (lane & 3) * 2;
        int n  = chunk * 128 + nt * 8 + (lane >> 2);
        float v0 = W[k0 * ldw + n],       v1 = W[(k0 + 1) * ldw + n];
        float v2 = W[(k0 + 8) * ldw + n], v3 = W[(k0 + 9) * ldw + n];
        __nv_bfloat16 h0 = __float2bfloat16_rn(v0), h1 = __float2bfloat16_rn(v1);
        __nv_bfloat16 h2 = __float2bfloat16_rn(v2), h3 = __float2bfloat16_rn(v3);
        __nv_bfloat162 r0, r1;
        if (part == 0) {
            r0 = __halves2bfloat162(h0, h1);
            r1 = __halves2bfloat162(h2, h3);
        } else {
            r0 = __halves2bfloat162(__float2bfloat16_rn(v0 - __bfloat162float(h0)),
                                    __float2bfloat16_rn(v1 - __bfloat162float(h1)));
            r1 = __halves2bfloat162(__float2bfloat16_rn(v2 - __bfloat162float(h2)),
                                    __float2bfloat16_rn(v3 - __bfloat162float(h3)));
        }
        *(__nv_bfloat162*)(dst + (size_t)idx * 8)     = r0;
        *(__nv_bfloat162*)(dst + (size_t)idx * 8 + 4) = r1;
    } else {
        int idx = e - 32768;
        if (idx < 702464) {
            int w = idx / 10976;
            int r = idx % 10976;
            int h = r / 2744;
            int r2 = r % 2744;
            int i = r2 / 56, j = r2 % 56;
            float val = 0.f;
            if (j < 49 && w < nW)
                val = bias_table[rel_index[i * 49 + j] * 4 + h] + mask[w * 2401 + i * 49 + j];
            g_bm[idx] = val;
        }
    }
}

// ---------------- PTX helpers ----------------
__device__ __forceinline__ void cp16(u32 dst, const void* src) {
    asm volatile("cp.async.cg.shared.global [%0], [%1], 16;" :: "r"(dst), "l"(src));
}
__device__ __forceinline__ void cp_commit() { asm volatile("cp.async.commit_group;"); }
template <int N> __device__ __forceinline__ void cp_wait() {
    asm volatile("cp.async.wait_group %0;" :: "n"(N));
}
__device__ __forceinline__ void ldm4(u32 r[4], u32 addr) {
    asm volatile("ldmatrix.sync.aligned.m8n8.x4.shared.b16 {%0,%1,%2,%3}, [%4];"
        : "=r"(r[0]), "=r"(r[1]), "=r"(r[2]), "=r"(r[3]) : "r"(addr));
}
__device__ __forceinline__ void ldm2(u32 r[2], u32 addr) {
    asm volatile("ldmatrix.sync.aligned.m8n8.x2.shared.b16 {%0,%1}, [%2];"
        : "=r"(r[0]), "=r"(r[1]) : "r"(addr));
}
__device__ __forceinline__ void mma16816(float c[4], const u32 a[4], u32 b0, u32 b1) {
    asm volatile("mma.sync.aligned.m16n8k16.row.col.f32.bf16.bf16.f32 "
        "{%0,%1,%2,%3}, {%4,%5,%6,%7}, {%8,%9}, {%0,%1,%2,%3};"
        : "+f"(c[0]), "+f"(c[1]), "+f"(c[2]), "+f"(c[3])
        : "r"(a[0]), "r"(a[1]), "r"(a[2]), "r"(a[3]), "r"(b0), "r"(b1));
}
__device__ __forceinline__ u32 pk_hi(float a, float b) {
    u32 r;
    asm("prmt.b32 %0, %1, %2, 0x7632;" : "=r"(r)
        : "r"(__float_as_uint(a)), "r"(__float_as_uint(b)));
    return r;
}
__device__ __forceinline__ u32 pk_lo(float a, float b) {
    float ah = __uint_as_float(__float_as_uint(a) & 0xFFFF0000u);
    float bh = __uint_as_float(__float_as_uint(b) & 0xFFFF0000u);
    return pk_hi(a - ah, b - bh);
}

__device__ __forceinline__ void issue_piece(u32 sb, int i, int tid) {
    const unsigned char* src =
        (i < 12 ? g_wq + (u32)i * 16384 : g_wp + (u32)(i - 12) * 16384) + tid * 32;
    u32 dst = sb + OFF_WB + (u32)(i & 1) * 16384 + (u32)tid * 32;
    cp16(dst, src); cp16(dst + 16, src + 16);
    cp_commit();
}

__device__ __forceinline__ void mma_tiles(float acc[2][4][4],
    u32 ahiB, u32 aloB, u32 bufB, int mg, int ng, int lane,
    int chBase, bool both)
{
    #pragma unroll
    for (int ks = 0; ks < 4; ++ks) {
        u32 a_hi[2][4], a_lo[2][4];
        #pragma unroll
        for (int mt = 0; mt < 2; ++mt) {
            int row = mg * 32 + mt * 16 + (lane & 7) + ((lane >> 3) & 1) * 8;
            int ch = chBase + ks * 2 + (lane >> 4);
            u32 off = (u32)row * 256 + sw16(ch, row) * 16;
            ldm4(a_hi[mt], ahiB + off);
            if (both) ldm4(a_lo[mt], aloB + off);
        }
        u32 b0[4], b1[4];
        #pragma unroll
        for (int nt = 0; nt < 4; ++nt) {
            u32 addr = bufB + (u32)((((ng * 4 + nt) * 4 + ks) * 32 + lane) * 8);
            asm volatile("ld.shared.v2.b32 {%0,%1}, [%2];"
                : "=r"(b0[nt]), "=r"(b1[nt]) : "r"(addr));
        }
        #pragma unroll
        for (int mt = 0; mt < 2; ++mt)
            #pragma unroll
            for (int nt = 0; nt < 4; ++nt) {
                mma16816(acc[mt][nt], a_hi[mt], b0[nt], b1[nt]);
                if (both) mma16816(acc[mt][nt], a_lo[mt], b0[nt], b1[nt]);
            }
    }
}

// ---------------- main kernel ----------------
__global__ __launch_bounds__(512, 1)
void win_attn_fa4(const float* __restrict__ x,
                  const float* __restrict__ qkv_b,
                  const float* __restrict__ proj_b,
                  float* __restrict__ out, int nW)
{
    extern __shared__ __align__(1024) unsigned char sm[];
    const u32 sb = (u32)__cvta_generic_to_shared(sm);
    const int tid = threadIdx.x, lane = tid & 31, wid = tid >> 5;
    const int b = blockIdx.x;
    const int mg = wid >> 2, ng = wid & 3;

    issue_piece(sb, 0, tid);
    issue_piece(sb, 1, tid);

    const float* xw = x + (size_t)(2 * b) * 49 * 128;

    // ---- build FULL A hi/lo once ----
    {
        int row = tid >> 2, cg = tid & 3;
        int win = row >> 6, nr = row & 63;
        float xv[32];
        if (nr < 49) {
            const float4* src = (const float4*)(xw + ((size_t)win * 49 + nr) * 128 + cg * 32);
            #pragma unroll
            for (int q = 0; q < 8; ++q) {
                float4 t = src[q];
                xv[4*q] = t.x; xv[4*q+1] = t.y; xv[4*q+2] = t.z; xv[4*q+3] = t.w;
            }
        } else {
            #pragma unroll
            for (int q = 0; q < 32; ++q) xv[q] = 0.f;
        }
        #pragma unroll
        for (int h = 0; h < 4; ++h) {
            u32 hi[4], lo[4];
            #pragma unroll
            for (int p = 0; p < 4; ++p) {
                float a = xv[h*8 + 2*p], bb = xv[h*8 + 2*p + 1];
                hi[p] = pk_hi(a, bb);
                lo[p] = pk_lo(a, bb);
            }
            int ch = cg * 4 + h;
            u32 off = (u32)row * 256 + sw16(ch, row) * 16;
            *(uint4*)(sm + OFF_AFHI + off) = make_uint4(hi[0], hi[1], hi[2], hi[3]);
            *(uint4*)(sm + OFF_AFLO + off) = make_uint4(lo[0], lo[1], lo[2], lo[3]);
        }
    }

    // ======== QKV GEMM ========
    #pragma unroll 1
    for (int c = 0; c < 3; ++c) {
        float acc[2][4][4];
        #pragma unroll
        for (int mt = 0; mt < 2; ++mt)
            #pragma unroll
            for (int nt = 0; nt < 4; ++nt)
                #pragma unroll
                for (int e = 0; e < 4; ++e) acc[mt][nt][e] = 0.f;

        #pragma unroll 1
        for (int kh = 0; kh < 2; ++kh) {
            int p = c * 4 + kh * 2;
            cp_wait<1>(); __syncthreads();
            mma_tiles(acc, sb + OFF_AFHI, sb + OFF_AFLO, sb + OFF_WB + (u32)(p & 1) * 16384,
                      mg, ng, lane, kh * 8, true);
            __syncthreads();
            issue_piece(sb, p + 2, tid);
            cp_wait<1>(); __syncthreads();
            mma_tiles(acc, sb + OFF_AFHI, sb + OFF_AFLO, sb + OFF_WB + (u32)((p + 1) & 1) * 16384,
                      mg, ng, lane, kh * 8, false);
            __syncthreads();
            issue_piece(sb, p + 3, tid);
        }

        // epilogue: Q / K / VT
        {
            int rb = mg * 32 + (lane >> 2);
            int cb = ng * 32 + (lane & 3) * 2;
            #pragma unroll
            for (int mt = 0; mt < 2; ++mt)
                #pragma unroll
                for (int rh = 0; rh < 2; ++rh) {
                    int r = rb + mt * 16 + rh * 8;
                    int win = r >> 6, nr = r & 63;
                    bool ok = nr < 49;
                    #pragma unroll
                    for (int nt = 0; nt < 4; ++nt) {
                        int cc = cb + nt * 8;
                        float v0 = acc[mt][nt][rh*2]   + __ldg(qkv_b + c*128 + cc);
                        float v1 = acc[mt][nt][rh*2+1] + __ldg(qkv_b + c*128 + cc + 1);
                        if (c == 0) {
                            v0 = ok ? v0 * QSCALE : 0.f;
                            v1 = ok ? v1 * QSCALE : 0.f;
                            u32 byte = (u32)r * 256 + sw16(cc >> 3, r) * 16 + (cc & 7) * 2;
                            *(u32*)(sm + OFF_QHI + byte) = pk_hi(v0, v1);
                            *(u32*)(sm + OFF_QLO + byte) = pk_lo(v0, v1);
                        } else if (c == 1) {
                            if (nr < 56) {
                                v0 = ok ? v0 : 0.f; v1 = ok ? v1 : 0.f;
                                int kr = win * 56 + nr;
                                u32 byte = (u32)kr * 256 + sw16(cc >> 3, kr) * 16 + (cc & 7) * 2;
                                *(u32*)(sm + OFF_KHI + byte) = pk_hi(v0, v1);
                                *(u32*)(sm + OFF_KLO + byte) = pk_lo(v0, v1);
                            }
                        } else {
                            v0 = ok ? v0 : 0.f; v1 = ok ? v1 : 0.f;
                            #pragma unroll
                            for (int e = 0; e < 2; ++e) {
                                float vv = e ? v1 : v0;
                                int vr = win * 128 + cc + e;
                                u32 byte = (u32)vr * 128
                                         + (u32)((((nr >> 3) ^ (vr & 7)) & 7) << 4)
                                         + (nr & 7) * 2;
                                u32 bits = __float_as_uint(vv);
                                *(unsigned short*)(sm + OFF_VTHI + byte) =
                                    (unsigned short)(bits >> 16);
                                float hif = __uint_as_float(bits & 0xFFFF0000u);
                                *(unsigned short*)(sm + OFF_VTLO + byte) =
                                    (unsigned short)(__float_as_uint(vv - hif) >> 16);
                            }
                        }
                    }
                }
        }
        if (c == 1) __syncthreads();
    }
    __syncthreads();

    // ======== attention: warp = (win, head, m-tile-pair); 2 m-tiles JOINT ========
    {
        const int win = wid >> 3, h = (wid >> 1) & 3, mp = wid & 1;
        const int g = lane >> 2, t = lane & 3;
        const float* bm = g_bm + ((size_t)((2 * b + win) % nW) * 4 + h) * 2744;

        // ---- S = Q @ K^T for both m-tiles, K frags loaded ONCE per ks ----
        float s[2][7][4];
        #pragma unroll
        for (int m = 0; m < 2; ++m)
            #pragma unroll
            for (int nt = 0; nt < 7; ++nt)
                #pragma unroll
                for (int e = 0; e < 4; ++e) s[m][nt][e] = 0.f;

        #pragma unroll
        for (int ks = 0; ks < 2; ++ks) {
            u32 aqh[2][4], aql[2][4];
            #pragma unroll
            for (int m = 0; m < 2; ++m) {
                int mt = mp * 2 + m;
                int rr = win * 64 + mt * 16 + (lane & 7) + ((lane >> 3) & 1) * 8;
                int ch = h * 4 + ks * 2 + (lane >> 4);
                u32 off = (u32)rr * 256 + sw16(ch, rr) * 16;
                ldm4(aqh[m], sb + OFF_QHI + off);
                ldm4(aql[m], sb + OFF_QLO + off);
            }
            u32 bkh[7][2], bkl[7][2];
            #pragma unroll
            for (int ntp = 0; ntp < 3; ++ntp) {
                int kr = win * 56 + ntp * 16 + ((lane >> 4) << 3) + (lane & 7);
                int ch = h * 4 + ks * 2 + ((lane >> 3) & 1);
                u32 off = (u32)kr * 256 + sw16(ch, kr) * 16;
                u32 r4[4];
                ldm4(r4, sb + OFF_KHI + off);
                bkh[2*ntp][0] = r4[0]; bkh[2*ntp][1] = r4[1];
                bkh[2*ntp+1][0] = r4[2]; bkh[2*ntp+1][1] = r4[3];
                ldm4(r4, sb + OFF_KLO + off);
                bkl[2*ntp][0] = r4[0]; bkl[2*ntp][1] = r4[1];
                bkl[2*ntp+1][0] = r4[2]; bkl[2*ntp+1][1] = r4[3];
            }
            {
                int kr = win * 56 + 48 + (lane & 7);
                int ch = h * 4 + ks * 2 + ((lane >> 3) & 1);
                u32 off = (u32)kr * 256 + sw16(ch, kr) * 16;
                ldm2(bkh[6], sb + OFF_KHI + off);
                ldm2(bkl[6], sb + OFF_KLO + off);
            }
            #pragma unroll
            for (int nt = 0; nt < 7; ++nt)
                #pragma unroll
                for (int m = 0; m < 2; ++m) {
                    mma16816(s[m][nt], aqh[m], bkh[nt][0], bkh[nt][1]);
                    mma16816(s[m][nt], aql[m], bkh[nt][0], bkh[nt][1]);
                    mma16816(s[m][nt], aqh[m], bkl[nt][0], bkl[nt][1]);
                }
        }

        // ---- softmax per m-tile, pack P ----
        u32 ph[2][4][4], pl[2][4][4];
        #pragma unroll
        for (int m = 0; m < 2; ++m) {
            const int mt = mp * 2 + m;
            int i0 = mt * 16 + g;
            int o0 = min(i0, 48) * 56, o1 = min(i0 + 8, 48) * 56;
            #pragma unroll
            for (int nt = 0; nt < 7; ++nt) {
                int jj = nt * 8 + 2 * t;
                float2 b0 = *(const float2*)(bm + o0 + jj);
                float2 b1 = *(const float2*)(bm + o1 + jj);
                s[m][nt][0] = (jj     < 49) ? s[m][nt][0] + b0.x : -1e30f;
                s[m][nt][1] = (jj + 1 < 49) ? s[m][nt][1] + b0.y : -1e30f;
                s[m][nt][2] = (jj     < 49) ? s[m][nt][2] + b1.x : -1e30f;
                s[m][nt][3] = (jj + 1 < 49) ? s[m][nt][3] + b1.y : -1e30f;
            }
            float m0 = -1e30f, m1 = -1e30f;
            #pragma unroll
            for (int nt = 0; nt < 7; ++nt) {
                m0 = fmaxf(m0, fmaxf(s[m][nt][0], s[m][nt][1]));
                m1 = fmaxf(m1, fmaxf(s[m][nt][2], s[m][nt][3]));
            }
            m0 = fmaxf(m0, __shfl_xor_sync(0xffffffffu, m0, 1));
            m1 = fmaxf(m1, __shfl_xor_sync(0xffffffffu, m1, 1));
            m0 = fmaxf(m0, __shfl_xor_sync(0xffffffffu, m0, 2));
            m1 = fmaxf(m1, __shfl_xor_sync(0xffffffffu, m1, 2));
            float s0 = 0.f, s1 = 0.f;
            #pragma unroll
            for (int nt = 0; nt < 7; ++nt) {
                s[m][nt][0] = __expf(s[m][nt][0] - m0); s0 += s[m][nt][0];
                s[m][nt][1] = __expf(s[m][nt][1] - m0); s0 += s[m][nt][1];
                s[m][nt][2] = __expf(s[m][nt][2] - m1); s1 += s[m][nt][2];
                s[m][nt][3] = __expf(s[m][nt][3] - m1); s1 += s[m][nt][3];
            }
            s0 += __shfl_xor_sync(0xffffffffu, s0, 1);
            s1 += __shfl_xor_sync(0xffffffffu, s1, 1);
            s0 += __shfl_xor_sync(0xffffffffu, s0, 2);
            s1 += __shfl_xor_sync(0xffffffffu, s1, 2);
            float i0v = 1.f / s0, i1v = 1.f / s1;
            #pragma unroll
            for (int nt = 0; nt < 7; ++nt) {
                s[m][nt][0] *= i0v; s[m][nt][1] *= i0v;
                s[m][nt][2] *= i1v; s[m][nt][3] *= i1v;
            }
            #pragma unroll
            for (int k2 = 0; k2 < 4; ++k2) {
                int na = 2 * k2, nb = 2 * k2 + 1;
                ph[m][k2][0] = pk_hi(s[m][na][0], s[m][na][1]);
                ph[m][k2][1] = pk_hi(s[m][na][2], s[m][na][3]);
                pl[m][k2][0] = pk_lo(s[m][na][0], s[m][na][1]);
                pl[m][k2][1] = pk_lo(s[m][na][2], s[m][na][3]);
                if (nb < 7) {
                    ph[m][k2][2] = pk_hi(s[m][nb][0], s[m][nb][1]);
                    ph[m][k2][3] = pk_hi(s[m][nb][2], s[m][nb][3]);
                    pl[m][k2][2] = pk_lo(s[m][nb][0], s[m][nb][1]);
                    pl[m][k2][3] = pk_lo(s[m][nb][2], s[m][nb][3]);
                } else {
                    ph[m][k2][2] = ph[m][k2][3] = pl[m][k2][2] = pl[m][k2][3] = 0u;
                }
            }
        }

        // ---- O = P @ V, V frags loaded ONCE per k2 for both m-tiles ----
        float o[2][4][4];
        #pragma unroll
        for (int m = 0; m < 2; ++m)
            #pragma unroll
            for (int nt = 0; nt < 4; ++nt)
                #pragma unroll
                for (int e = 0; e < 4; ++e) o[m][nt][e] = 0.f;
        #pragma unroll
        for (int k2 = 0; k2 < 4; ++k2) {
            u32 bvh[4][2], bvl[4][2];
            #pragma unroll
            for (int dp = 0; dp < 2; ++dp) {
                int vr = win * 128 + h * 32 + dp * 16 + ((lane >> 4) << 3) + (lane & 7);
                int ch = k2 * 2 + ((lane >> 3) & 1);
                u32 off = (u32)vr * 128 + (u32)(((ch ^ (vr & 7)) & 7) << 4);
                u32 r4[4];
                ldm4(r4, sb + OFF_VTHI + off);
                bvh[2*dp][0] = r4[0]; bvh[2*dp][1] = r4[1];
                bvh[2*dp+1][0] = r4[2]; bvh[2*dp+1][1] = r4[3];
                ldm4(r4, sb + OFF_VTLO + off);
                bvl[2*dp][0] = r4[0]; bvl[2*dp][1] = r4[1];
                bvl[2*dp+1][0] = r4[2]; bvl[2*dp+1][1] = r4[3];
            }
            #pragma unroll
            for (int nt = 0; nt < 4; ++nt)
                #pragma unroll
                for (int m = 0; m < 2; ++m) {
                    mma16816(o[m][nt], ph[m][k2], bvh[nt][0], bvh[nt][1]);
                    mma16816(o[m][nt], pl[m][k2], bvh[nt][0], bvh[nt][1]);
                    mma16816(o[m][nt], ph[m][k2], bvl[nt][0], bvl[nt][1]);
                }
        }

        // ---- write O hi/lo into proj-A layout ----
        #pragma unroll
        for (int m = 0; m < 2; ++m) {
            const int mt = mp * 2 + m;
            #pragma unroll
            for (int nt = 0; nt < 4; ++nt)
                #pragma unroll
                for (int rh = 0; rh < 2; ++rh) {
                    int r = win * 64 + mt * 16 + g + rh * 8;
                    int col = h * 32 + nt * 8 + 2 * t;
                    u32 byte = (u32)r * 256 + sw16(col >> 3, r) * 16 + (col & 7) * 2;
                    *(u32*)(sm + OFF_PHI + byte) = pk_hi(o[m][nt][rh*2], o[m][nt][rh*2+1]);
                    *(u32*)(sm + OFF_PLO + byte) = pk_lo(o[m][nt][rh*2], o[m][nt][rh*2+1]);
                }
        }
    }
    __syncthreads();

    // ======== proj GEMM ========
    float pacc[2][4][4];
    #pragma unroll
    for (int mt = 0; mt < 2; ++mt)
        #pragma unroll
        for (int nt = 0; nt < 4; ++nt)
            #pragma unroll
            for (int e = 0; e < 4; ++e) pacc[mt][nt][e] = 0.f;

    cp_wait<1>(); __syncthreads();
    mma_tiles(pacc, sb + OFF_PHI, sb + OFF_PLO, sb + OFF_WB, mg, ng, lane, 0, true);
    __syncthreads();
    issue_piece(sb, 14, tid);
    cp_wait<1>(); __syncthreads();
    mma_tiles(pacc, sb + OFF_PHI, sb + OFF_PLO, sb + OFF_WB + 16384, mg, ng, lane, 0, false);
    __syncthreads();
    issue_piece(sb, 15, tid);
    cp_wait<1>(); __syncthreads();
    mma_tiles(pacc, sb + OFF_PHI, sb + OFF_PLO, sb + OFF_WB, mg, ng, lane, 8, true);
    __syncthreads();
    cp_wait<0>(); __syncthreads();
    mma_tiles(pacc, sb + OFF_PHI, sb + OFF_PLO, sb + OFF_WB + 16384, mg, ng, lane, 8, false);

    // proj epilogue -> gmem (+bias)
    {
        int rb = mg * 32 + (lane >> 2);
        int cb = ng * 32 + (lane & 3) * 2;
        #pragma unroll
        for (int mt = 0; mt < 2; ++mt)
            #pragma unroll
            for (int rh = 0; rh < 2; ++rh) {
                int r = rb + mt * 16 + rh * 8;
                int win = r >> 6, nr = r & 63;
                if (nr < 49) {
                    float* go = out + ((size_t)(2*b + win) * 49 + nr) * 128;
                    #pragma unroll
                    for (int nt = 0; nt < 4; ++nt) {
                        int cc = cb + nt * 8;
                        float v0 = pacc[mt][nt][rh*2]   + __ldg(proj_b + cc);
                        float v1 = pacc[mt][nt][rh*2+1] + __ldg(proj_b + cc + 1);
                        *(float2*)(go + cc) = make_float2(v0, v1);
                    }
                }
            }
    }
}

extern "C" void kernel_launch(void* const* d_in, const int* in_sizes, int n_in,
                              void* d_out, int out_size)
{
    const float* x      = (const float*)d_in[0];
    const float* mask   = (const float*)d_in[1];
    const float* qkv_w  = (const float*)d_in[2];
    const float* qkv_b  = (const float*)d_in[3];
    const float* proj_w = (const float*)d_in[4];
    const float* proj_b = (const float*)d_in[5];
    const float* table  = (const float*)d_in[6];
    const int*   relidx = (const int*)d_in[7];
    float*       out    = (float*)d_out;

    const int B  = in_sizes[0] / (49 * 128);
    const int nW = in_sizes[1] / (49 * 49);

    prep_all<<<2872, 256>>>(qkv_w, proj_w, mask, table, relidx, nW);

    cudaFuncSetAttribute(win_attn_fa4,
                         cudaFuncAttributeMaxDynamicSharedMemorySize, SMEM_BYTES);
    win_attn_fa4<<<B / 2, 512, SMEM_BYTES>>>(x, qkv_b, proj_b, out, nW);
}

// round 11
// speedup vs baseline: 1.1352x; 1.0393x over previous
#include <cuda_runtime.h>
#include <cuda_bf16.h>
#include <cuda_fp16.h>
#include <cstdint>

typedef unsigned int u32;

#define QSCALE 0.17677669529663687f

// ---- smem byte offsets (2 windows per CTA, 221184 B) ----
#define OFF_WB    0         /* 2 x 16384 weight ping-pong            */
#define OFF_QHI   32768     /* Q bf16 hi  [128 rows][256B]           */
#define OFF_QLO   65536
#define OFF_KHI   98304     /* K bf16 hi  [112 rows (2x56)][256B]    */
#define OFF_KLO   126976
#define OFF_AFHI  155648    /* A full hi [128 rows][256B] (VT alias) */
#define OFF_AFLO  188416    /* A full lo                             */
#define OFF_VTHI  155648    /* VT fp16   [256 rows][128B]            */
#define OFF_PHI   32768     /* proj A' fp16 hi (alias Q hi)          */
#define OFF_PLO   65536
#define SMEM_BYTES 221184

__device__ __align__(16) unsigned char g_wq[196608];  // bf16 hi/lo, 12 pieces
__device__ __align__(16) unsigned char g_wp[32768];   // fp16 single, 2 pieces
__device__ __align__(16) float g_bm[702464];

__device__ __forceinline__ u32 sw16(int ch, int r) {
    return (u32)((ch & 8) | ((ch ^ (r & 7)) & 7));
}

// ---------------- prep kernel ----------------
__global__ void prep_all(const float* __restrict__ qkv_w,
                         const float* __restrict__ proj_w,
                         const float* __restrict__ mask,
                         const float* __restrict__ bias_table,
                         const int*   __restrict__ rel_index,
                         int nW) {
    int e = blockIdx.x * 256 + threadIdx.x;
    if (e < 24576) {
        // QKV bf16 hi/lo fragment pieces (unchanged)
        int idx = e;
        int piece = idx >> 11;
        int rem = idx & 2047;
        int lane = rem & 31, ks = (rem >> 5) & 3, nt = rem >> 7;
        int chunk = piece >> 2;
        int kh = (piece >> 1) & 1;
        int part = piece & 1;
        int k0 = kh * 64 + ks * 16 + (lane & 3) * 2;
        int n  = chunk * 128 + nt * 8 + (lane >> 2);
        float v0 = qkv_w[k0 * 384 + n],       v1 = qkv_w[(k0 + 1) * 384 + n];
        float v2 = qkv_w[(k0 + 8) * 384 + n], v3 = qkv_w[(k0 + 9) * 384 + n];
        __nv_bfloat16 h0 = __float2bfloat16_rn(v0), h1 = __float2bfloat16_rn(v1);
        __nv_bfloat16 h2 = __float2bfloat16_rn(v2), h3 = __float2bfloat16_rn(v3);
        __nv_bfloat162 r0, r1;
        if (part == 0) {
            r0 = __halves2bfloat162(h0, h1);
            r1 = __halves2bfloat162(h2, h3);
        } else {
            r0 = __halves2bfloat162(__float2bfloat16_rn(v0 - __bfloat162float(h0)),
                                    __float2bfloat16_rn(v1 - __bfloat162float(h1)));
            r1 = __halves2bfloat162(__float2bfloat16_rn(v2 - __bfloat162float(h2)),
                                    __float2bfloat16_rn(v3 - __bfloat162float(h3)));
        }
        *(__nv_bfloat162*)(g_wq + (size_t)idx * 8)     = r0;
        *(__nv_bfloat162*)(g_wq + (size_t)idx * 8 + 4) = r1;
    } else if (e < 28672) {
        // proj fp16 single-precision pieces (2 x 16KB)
        int idx = e - 24576;              // < 4096
        int kh = idx >> 11;
        int rem = idx & 2047;
        int lane = rem & 31, ks = (rem >> 5) & 3, nt = rem >> 7;
        int k0 = kh * 64 + ks * 16 + (lane & 3) * 2;
        int n  = nt * 8 + (lane >> 2);
        float v0 = proj_w[k0 * 128 + n],       v1 = proj_w[(k0 + 1) * 128 + n];
        float v2 = proj_w[(k0 + 8) * 128 + n], v3 = proj_w[(k0 + 9) * 128 + n];
        __half2 r0 = __halves2half2(__float2half_rn(v0), __float2half_rn(v1));
        __half2 r1 = __halves2half2(__float2half_rn(v2), __float2half_rn(v3));
        *(__half2*)(g_wp + (size_t)idx * 8)     = r0;
        *(__half2*)(g_wp + (size_t)idx * 8 + 4) = r1;
    } else {
        int idx = e - 28672;
        if (idx < 702464) {
            int w = idx / 10976;
            int r = idx % 10976;
            int h = r / 2744;
            int r2 = r % 2744;
            int i = r2 / 56, j = r2 % 56;
            float val = 0.f;
            if (j < 49 && w < nW)
                val = bias_table[rel_index[i * 49 + j] * 4 + h] + mask[w * 2401 + i * 49 + j];
            g_bm[idx] = val;
        }
    }
}

// ---------------- PTX helpers ----------------
__device__ __forceinline__ void cp16(u32 dst, const void* src) {
    asm volatile("cp.async.cg.shared.global [%0], [%1], 16;" :: "r"(dst), "l"(src));
}
__device__ __forceinline__ void cp_commit() { asm volatile("cp.async.commit_group;"); }
template <int N> __device__ __forceinline__ void cp_wait() {
    asm volatile("cp.async.wait_group %0;" :: "n"(N));
}
__device__ __forceinline__ void ldm4(u32 r[4], u32 addr) {
    asm volatile("ldmatrix.sync.aligned.m8n8.x4.shared.b16 {%0,%1,%2,%3}, [%4];"
        : "=r"(r[0]), "=r"(r[1]), "=r"(r[2]), "=r"(r[3]) : "r"(addr));
}
__device__ __forceinline__ void ldm2(u32 r[2], u32 addr) {
    asm volatile("ldmatrix.sync.aligned.m8n8.x2.shared.b16 {%0,%1}, [%2];"
        : "=r"(r[0]), "=r"(r[1]) : "r"(addr));
}
__device__ __forceinline__ void mma16816(float c[4], const u32 a[4], u32 b0, u32 b1) {
    asm volatile("mma.sync.aligned.m16n8k16.row.col.f32.bf16.bf16.f32 "
        "{%0,%1,%2,%3}, {%4,%5,%6,%7}, {%8,%9}, {%0,%1,%2,%3};"
        : "+f"(c[0]), "+f"(c[1]), "+f"(c[2]), "+f"(c[3])
        : "r"(a[0]), "r"(a[1]), "r"(a[2]), "r"(a[3]), "r"(b0), "r"(b1));
}
__device__ __forceinline__ void mma16816h(float c[4], const u32 a[4], u32 b0, u32 b1) {
    asm volatile("mma.sync.aligned.m16n8k16.row.col.f32.f16.f16.f32 "
        "{%0,%1,%2,%3}, {%4,%5,%6,%7}, {%8,%9}, {%0,%1,%2,%3};"
        : "+f"(c[0]), "+f"(c[1]), "+f"(c[2]), "+f"(c[3])
        : "r"(a[0]), "r"(a[1]), "r"(a[2]), "r"(a[3]), "r"(b0), "r"(b1));
}
// bf16 truncation split (PRMT)
__device__ __forceinline__ u32 pk_hi(float a, float b) {
    u32 r;
    asm("prmt.b32 %0, %1, %2, 0x7632;" : "=r"(r)
        : "r"(__float_as_uint(a)), "r"(__float_as_uint(b)));
    return r;
}
__device__ __forceinline__ u32 pk_lo(float a, float b) {
    float ah = __uint_as_float(__float_as_uint(a) & 0xFFFF0000u);
    float bh = __uint_as_float(__float_as_uint(b) & 0xFFFF0000u);
    return pk_hi(a - ah, b - bh);
}
// fp16 RN split
__device__ __forceinline__ u32 pkh_f16(float a, float b) {
    u32 r;
    asm("cvt.rn.f16x2.f32 %0, %1, %2;" : "=r"(r) : "f"(b), "f"(a));
    return r;
}
__device__ __forceinline__ u32 pkl_f16(float a, float b, u32 h) {
    float ah, bh;
    asm("{\n\t.reg .b16 x,y;\n\tmov.b32 {x,y}, %2;\n\t"
        "cvt.f32.f16 %0, x;\n\tcvt.f32.f16 %1, y;\n\t}"
        : "=f"(ah), "=f"(bh) : "r"(h));
    return pkh_f16(a - ah, b - bh);
}

// piece i: 0-11 qkv bf16 (hi/lo), 12-13 proj fp16
__device__ __forceinline__ void issue_piece(u32 sb, int i, int tid) {
    const unsigned char* src =
        (i < 12 ? g_wq + (u32)i * 16384 : g_wp + (u32)(i - 12) * 16384) + tid * 32;
    u32 dst = sb + OFF_WB + (u32)(i & 1) * 16384 + (u32)tid * 32;
    cp16(dst, src); cp16(dst + 16, src + 16);
    cp_commit();
}

// ---------------- main kernel ----------------
__global__ __launch_bounds__(512, 1)
void win_attn_fa5(const float* __restrict__ x,
                  const float* __restrict__ qkv_b,
                  const float* __restrict__ proj_b,
                  float* __restrict__ out, int nW)
{
    extern __shared__ __align__(1024) unsigned char sm[];
    const u32 sb = (u32)__cvta_generic_to_shared(sm);
    const int tid = threadIdx.x, lane = tid & 31, wid = tid >> 5;
    const int b = blockIdx.x;
    const int mg = wid >> 2, ng = wid & 3;

    issue_piece(sb, 0, tid);
    issue_piece(sb, 1, tid);

    const float* xw = x + (size_t)(2 * b) * 49 * 128;

    // ---- build FULL A hi/lo once (bf16 trunc split) ----
    {
        int row = tid >> 2, cg = tid & 3;
        int win = row >> 6, nr = row & 63;
        float xv[32];
        if (nr < 49) {
            const float4* src = (const float4*)(xw + ((size_t)win * 49 + nr) * 128 + cg * 32);
            #pragma unroll
            for (int q = 0; q < 8; ++q) {
                float4 t = src[q];
                xv[4*q] = t.x; xv[4*q+1] = t.y; xv[4*q+2] = t.z; xv[4*q+3] = t.w;
            }
        } else {
            #pragma unroll
            for (int q = 0; q < 32; ++q) xv[q] = 0.f;
        }
        #pragma unroll
        for (int h = 0; h < 4; ++h) {
            u32 hi[4], lo[4];
            #pragma unroll
            for (int p = 0; p < 4; ++p) {
                float a = xv[h*8 + 2*p], bb = xv[h*8 + 2*p + 1];
                hi[p] = pk_hi(a, bb);
                lo[p] = pk_lo(a, bb);
            }
            int ch = cg * 4 + h;
            u32 off = (u32)row * 256 + sw16(ch, row) * 16;
            *(uint4*)(sm + OFF_AFHI + off) = make_uint4(hi[0], hi[1], hi[2], hi[3]);
            *(uint4*)(sm + OFF_AFLO + off) = make_uint4(lo[0], lo[1], lo[2], lo[3]);
        }
    }
    __syncthreads();   // A visible before first ah hoist

    // ======== QKV GEMM: 3 chunks, A-hi frags hoisted per k-half ========
    #pragma unroll 1
    for (int c = 0; c < 3; ++c) {
        float acc[2][4][4];
        #pragma unroll
        for (int mt = 0; mt < 2; ++mt)
            #pragma unroll
            for (int nt = 0; nt < 4; ++nt)
                #pragma unroll
                for (int e = 0; e < 4; ++e) acc[mt][nt][e] = 0.f;

        #pragma unroll 1
        for (int kh = 0; kh < 2; ++kh) {
            int p = c * 4 + kh * 2;

            // hoist A-hi fragments for this k-half: [ks][mt]
            u32 ah[4][2][4];
            #pragma unroll
            for (int ks = 0; ks < 4; ++ks)
                #pragma unroll
                for (int mt = 0; mt < 2; ++mt) {
                    int row = mg * 32 + mt * 16 + (lane & 7) + ((lane >> 3) & 1) * 8;
                    int ch = kh * 8 + ks * 2 + (lane >> 4);
                    ldm4(ah[ks][mt], sb + OFF_AFHI + (u32)row * 256 + sw16(ch, row) * 16);
                }

            // --- W-hi piece: (A-hi + A-lo) x W-hi ---
            cp_wait<1>(); __syncthreads();
            {
                u32 bufB = sb + OFF_WB + (u32)(p & 1) * 16384;
                #pragma unroll
                for (int ks = 0; ks < 4; ++ks) {
                    u32 al[2][4];
                    #pragma unroll
                    for (int mt = 0; mt < 2; ++mt) {
                        int row = mg * 32 + mt * 16 + (lane & 7) + ((lane >> 3) & 1) * 8;
                        int ch = kh * 8 + ks * 2 + (lane >> 4);
                        ldm4(al[mt], sb + OFF_AFLO + (u32)row * 256 + sw16(ch, row) * 16);
                    }
                    u32 b0[4], b1[4];
                    #pragma unroll
                    for (int nt = 0; nt < 4; ++nt) {
                        u32 addr = bufB + (u32)((((ng * 4 + nt) * 4 + ks) * 32 + lane) * 8);
                        asm volatile("ld.shared.v2.b32 {%0,%1}, [%2];"
                            : "=r"(b0[nt]), "=r"(b1[nt]) : "r"(addr));
                    }
                    #pragma unroll
                    for (int mt = 0; mt < 2; ++mt)
                        #pragma unroll
                        for (int nt = 0; nt < 4; ++nt) {
                            mma16816(acc[mt][nt], ah[ks][mt], b0[nt], b1[nt]);
                            mma16816(acc[mt][nt], al[mt],     b0[nt], b1[nt]);
                        }
                }
            }
            __syncthreads();
            issue_piece(sb, p + 2, tid);

            // --- W-lo piece: A-hi x W-lo (ah reused from registers) ---
            cp_wait<1>(); __syncthreads();
            {
                u32 bufB = sb + OFF_WB + (u32)((p + 1) & 1) * 16384;
                #pragma unroll
                for (int ks = 0; ks < 4; ++ks) {
                    u32 b0[4], b1[4];
                    #pragma unroll
                    for (int nt = 0; nt < 4; ++nt) {
                        u32 addr = bufB + (u32)((((ng * 4 + nt) * 4 + ks) * 32 + lane) * 8);
                        asm volatile("ld.shared.v2.b32 {%0,%1}, [%2];"
                            : "=r"(b0[nt]), "=r"(b1[nt]) : "r"(addr));
                    }
                    #pragma unroll
                    for (int mt = 0; mt < 2; ++mt)
                        #pragma unroll
                        for (int nt = 0; nt < 4; ++nt)
                            mma16816(acc[mt][nt], ah[ks][mt], b0[nt], b1[nt]);
                }
            }
            __syncthreads();
            if (p + 3 <= 13) issue_piece(sb, p + 3, tid);
        }

        // epilogue: Q / K (bf16 hi/lo), VT (fp16 single; aliases AFHI, dead)
        {
            int rb = mg * 32 + (lane >> 2);
            int cb = ng * 32 + (lane & 3) * 2;
            #pragma unroll
            for (int mt = 0; mt < 2; ++mt)
                #pragma unroll
                for (int rh = 0; rh < 2; ++rh) {
                    int r = rb + mt * 16 + rh * 8;
                    int win = r >> 6, nr = r & 63;
                    bool ok = nr < 49;
                    #pragma unroll
                    for (int nt = 0; nt < 4; ++nt) {
                        int cc = cb + nt * 8;
                        float v0 = acc[mt][nt][rh*2]   + __ldg(qkv_b + c*128 + cc);
                        float v1 = acc[mt][nt][rh*2+1] + __ldg(qkv_b + c*128 + cc + 1);
                        if (c == 0) {
                            v0 = ok ? v0 * QSCALE : 0.f;
                            v1 = ok ? v1 * QSCALE : 0.f;
                            u32 byte = (u32)r * 256 + sw16(cc >> 3, r) * 16 + (cc & 7) * 2;
                            *(u32*)(sm + OFF_QHI + byte) = pk_hi(v0, v1);
                            *(u32*)(sm + OFF_QLO + byte) = pk_lo(v0, v1);
                        } else if (c == 1) {
                            if (nr < 56) {
                                v0 = ok ? v0 : 0.f; v1 = ok ? v1 : 0.f;
                                int kr = win * 56 + nr;
                                u32 byte = (u32)kr * 256 + sw16(cc >> 3, kr) * 16 + (cc & 7) * 2;
                                *(u32*)(sm + OFF_KHI + byte) = pk_hi(v0, v1);
                                *(u32*)(sm + OFF_KLO + byte) = pk_lo(v0, v1);
                            }
                        } else {
                            v0 = ok ? v0 : 0.f; v1 = ok ? v1 : 0.f;
                            #pragma unroll
                            for (int e = 0; e < 2; ++e) {
                                float vv = e ? v1 : v0;
                                int vr = win * 128 + cc + e;
                                u32 byte = (u32)vr * 128
                                         + (u32)((((nr >> 3) ^ (vr & 7)) & 7) << 4)
                                         + (nr & 7) * 2;
                                *(__half*)(sm + OFF_VTHI + byte) = __float2half_rn(vv);
                            }
                        }
                    }
                }
        }
        if (c == 1) __syncthreads();
    }
    __syncthreads();

    // ======== attention: warp = (win, head, m-pair), 2 m-tiles joint ========
    {
        const int win = wid >> 3, h = (wid >> 1) & 3, mp = wid & 1;
        const int g = lane >> 2, t = lane & 3;
        const float* bm = g_bm + ((size_t)((2 * b + win) % nW) * 4 + h) * 2744;

        // ---- S = Q K^T (bf16 3-pass), K frags loaded once per ks ----
        float s[2][7][4];
        #pragma unroll
        for (int m = 0; m < 2; ++m)
            #pragma unroll
            for (int nt = 0; nt < 7; ++nt)
                #pragma unroll
                for (int e = 0; e < 4; ++e) s[m][nt][e] = 0.f;

        #pragma unroll
        for (int ks = 0; ks < 2; ++ks) {
            u32 aqh[2][4], aql[2][4];
            #pragma unroll
            for (int m = 0; m < 2; ++m) {
                int mt = mp * 2 + m;
                int rr = win * 64 + mt * 16 + (lane & 7) + ((lane >> 3) & 1) * 8;
                int ch = h * 4 + ks * 2 + (lane >> 4);
                u32 off = (u32)rr * 256 + sw16(ch, rr) * 16;
                ldm4(aqh[m], sb + OFF_QHI + off);
                ldm4(aql[m], sb + OFF_QLO + off);
            }
            u32 bkh[7][2], bkl[7][2];
            #pragma unroll
            for (int ntp = 0; ntp < 3; ++ntp) {
                int kr = win * 56 + ntp * 16 + ((lane >> 4) << 3) + (lane & 7);
                int ch = h * 4 + ks * 2 + ((lane >> 3) & 1);
                u32 off = (u32)kr * 256 + sw16(ch, kr) * 16;
                u32 r4[4];
                ldm4(r4, sb + OFF_KHI + off);
                bkh[2*ntp][0] = r4[0]; bkh[2*ntp][1] = r4[1];
                bkh[2*ntp+1][0] = r4[2]; bkh[2*ntp+1][1] = r4[3];
                ldm4(r4, sb + OFF_KLO + off);
                bkl[2*ntp][0] = r4[0]; bkl[2*ntp][1] = r4[1];
                bkl[2*ntp+1][0] = r4[2]; bkl[2*ntp+1][1] = r4[3];
            }
            {
                int kr = win * 56 + 48 + (lane & 7);
                int ch = h * 4 + ks * 2 + ((lane >> 3) & 1);
                u32 off = (u32)kr * 256 + sw16(ch, kr) * 16;
                ldm2(bkh[6], sb + OFF_KHI + off);
                ldm2(bkl[6], sb + OFF_KLO + off);
            }
            #pragma unroll
            for (int nt = 0; nt < 7; ++nt)
                #pragma unroll
                for (int m = 0; m < 2; ++m) {
                    mma16816(s[m][nt], aqh[m], bkh[nt][0], bkh[nt][1]);
                    mma16816(s[m][nt], aql[m], bkh[nt][0], bkh[nt][1]);
                    mma16816(s[m][nt], aqh[m], bkl[nt][0], bkl[nt][1]);
                }
        }

        // ---- softmax per m-tile, pack P as fp16 hi/lo ----
        u32 ph[2][4][4], pl[2][4][4];
        #pragma unroll
        for (int m = 0; m < 2; ++m) {
            const int mt = mp * 2 + m;
            int i0 = mt * 16 + g;
            int o0 = min(i0, 48) * 56, o1 = min(i0 + 8, 48) * 56;
            #pragma unroll
            for (int nt = 0; nt < 7; ++nt) {
                int jj = nt * 8 + 2 * t;
                float2 b0 = *(const float2*)(bm + o0 + jj);
                float2 b1 = *(const float2*)(bm + o1 + jj);
                s[m][nt][0] = (jj     < 49) ? s[m][nt][0] + b0.x : -1e30f;
                s[m][nt][1] = (jj + 1 < 49) ? s[m][nt][1] + b0.y : -1e30f;
                s[m][nt][2] = (jj     < 49) ? s[m][nt][2] + b1.x : -1e30f;
                s[m][nt][3] = (jj + 1 < 49) ? s[m][nt][3] + b1.y : -1e30f;
            }
            float m0 = -1e30f, m1 = -1e30f;
            #pragma unroll
            for (int nt = 0; nt < 7; ++nt) {
                m0 = fmaxf(m0, fmaxf(s[m][nt][0], s[m][nt][1]));
                m1 = fmaxf(m1, fmaxf(s[m][nt][2], s[m][nt][3]));
            }
            m0 = fmaxf(m0, __shfl_xor_sync(0xffffffffu, m0, 1));
            m1 = fmaxf(m1, __shfl_xor_sync(0xffffffffu, m1, 1));
            m0 = fmaxf(m0, __shfl_xor_sync(0xffffffffu, m0, 2));
            m1 = fmaxf(m1, __shfl_xor_sync(0xffffffffu, m1, 2));
            float s0 = 0.f, s1 = 0.f;
            #pragma unroll
            for (int nt = 0; nt < 7; ++nt) {
                s[m][nt][0] = __expf(s[m][nt][0] - m0); s0 += s[m][nt][0];
                s[m][nt][1] = __expf(s[m][nt][1] - m0); s0 += s[m][nt][1];
                s[m][nt][2] = __expf(s[m][nt][2] - m1); s1 += s[m][nt][2];
                s[m][nt][3] = __expf(s[m][nt][3] - m1); s1 += s[m][nt][3];
            }
            s0 += __shfl_xor_sync(0xffffffffu, s0, 1);
            s1 += __shfl_xor_sync(0xffffffffu, s1, 1);
            s0 += __shfl_xor_sync(0xffffffffu, s0, 2);
            s1 += __shfl_xor_sync(0xffffffffu, s1, 2);
            float i0v = 1.f / s0, i1v = 1.f / s1;
            #pragma unroll
            for (int nt = 0; nt < 7; ++nt) {
                s[m][nt][0] *= i0v; s[m][nt][1] *= i0v;
                s[m][nt][2] *= i1v; s[m][nt][3] *= i1v;
            }
            #pragma unroll
            for (int k2 = 0; k2 < 4; ++k2) {
                int na = 2 * k2, nb = 2 * k2 + 1;
                ph[m][k2][0] = pkh_f16(s[m][na][0], s[m][na][1]);
                pl[m][k2][0] = pkl_f16(s[m][na][0], s[m][na][1], ph[m][k2][0]);
                ph[m][k2][1] = pkh_f16(s[m][na][2], s[m][na][3]);
                pl[m][k2][1] = pkl_f16(s[m][na][2], s[m][na][3], ph[m][k2][1]);
                if (nb < 7) {
                    ph[m][k2][2] = pkh_f16(s[m][nb][0], s[m][nb][1]);
                    pl[m][k2][2] = pkl_f16(s[m][nb][0], s[m][nb][1], ph[m][k2][2]);
                    ph[m][k2][3] = pkh_f16(s[m][nb][2], s[m][nb][3]);
                    pl[m][k2][3] = pkl_f16(s[m][nb][2], s[m][nb][3], ph[m][k2][3]);
                } else {
                    ph[m][k2][2] = ph[m][k2][3] = pl[m][k2][2] = pl[m][k2][3] = 0u;
                }
            }
        }

        // ---- O = P @ V (fp16 2-pass: Ph*V + Pl*V), V frags once per k2 ----
        float o[2][4][4];
        #pragma unroll
        for (int m = 0; m < 2; ++m)
            #pragma unroll
            for (int nt = 0; nt < 4; ++nt)
                #pragma unroll
                for (int e = 0; e < 4; ++e) o[m][nt][e] = 0.f;
        #pragma unroll
        for (int k2 = 0; k2 < 4; ++k2) {
            u32 bvh[4][2];
            #pragma unroll
            for (int dp = 0; dp < 2; ++dp) {
                int vr = win * 128 + h * 32 + dp * 16 + ((lane >> 4) << 3) + (lane & 7);
                int ch = k2 * 2 + ((lane >> 3) & 1);
                u32 off = (u32)vr * 128 + (u32)(((ch ^ (vr & 7)) & 7) << 4);
                u32 r4[4];
                ldm4(r4, sb + OFF_VTHI + off);
                bvh[2*dp][0] = r4[0]; bvh[2*dp][1] = r4[1];
                bvh[2*dp+1][0] = r4[2]; bvh[2*dp+1][1] = r4[3];
            }
            #pragma unroll
            for (int nt = 0; nt < 4; ++nt)
                #pragma unroll
                for (int m = 0; m < 2; ++m) {
                    mma16816h(o[m][nt], ph[m][k2], bvh[nt][0], bvh[nt][1]);
                    mma16816h(o[m][nt], pl[m][k2], bvh[nt][0], bvh[nt][1]);
                }
        }

        // ---- write O fp16 hi/lo into proj-A layout ----
        #pragma unroll
        for (int m = 0; m < 2; ++m) {
            const int mt = mp * 2 + m;
            #pragma unroll
            for (int nt = 0; nt < 4; ++nt)
                #pragma unroll
                for (int rh = 0; rh < 2; ++rh) {
                    int r = win * 64 + mt * 16 + g + rh * 8;
                    int col = h * 32 + nt * 8 + 2 * t;
                    u32 byte = (u32)r * 256 + sw16(col >> 3, r) * 16 + (col & 7) * 2;
                    u32 hi = pkh_f16(o[m][nt][rh*2], o[m][nt][rh*2+1]);
                    *(u32*)(sm + OFF_PHI + byte) = hi;
                    *(u32*)(sm + OFF_PLO + byte) = pkl_f16(o[m][nt][rh*2], o[m][nt][rh*2+1], hi);
                }
        }
    }
    __syncthreads();

    // ======== proj GEMM: fp16 2-pass, 2 pieces (prefetched) ========
    float pacc[2][4][4];
    #pragma unroll
    for (int mt = 0; mt < 2; ++mt)
        #pragma unroll
        for (int nt = 0; nt < 4; ++nt)
            #pragma unroll
            for (int e = 0; e < 4; ++e) pacc[mt][nt][e] = 0.f;

    #pragma unroll 1
    for (int kh = 0; kh < 2; ++kh) {
        if (kh == 0) cp_wait<1>(); else cp_wait<0>();
        __syncthreads();
        u32 bufB = sb + OFF_WB + (u32)kh * 16384;
        #pragma unroll
        for (int ks = 0; ks < 4; ++ks) {
            u32 ah[2][4], al[2][4];
            #pragma unroll
            for (int mt = 0; mt < 2; ++mt) {
                int row = mg * 32 + mt * 16 + (lane & 7) + ((lane >> 3) & 1) * 8;
                int ch = kh * 8 + ks * 2 + (lane >> 4);
                u32 off = (u32)row * 256 + sw16(ch, row) * 16;
                ldm4(ah[mt], sb + OFF_PHI + off);
                ldm4(al[mt], sb + OFF_PLO + off);
            }
            u32 b0[4], b1[4];
            #pragma unroll
            for (int nt = 0; nt < 4; ++nt) {
                u32 addr = bufB + (u32)((((ng * 4 + nt) * 4 + ks) * 32 + lane) * 8);
                asm volatile("ld.shared.v2.b32 {%0,%1}, [%2];"
                    : "=r"(b0[nt]), "=r"(b1[nt]) : "r"(addr));
            }
            #pragma unroll
            for (int mt = 0; mt < 2; ++mt)
                #pragma unroll
                for (int nt = 0; nt < 4; ++nt) {
                    mma16816h(pacc[mt][nt], ah[mt], b0[nt], b1[nt]);
                    mma16816h(pacc[mt][nt], al[mt], b0[nt], b1[nt]);
                }
        }
    }

    // proj epilogue -> gmem (+bias)
    {
        int rb = mg * 32 + (lane >> 2);
        int cb = ng * 32 + (lane & 3) * 2;
        #pragma unroll
        for (int mt = 0; mt < 2; ++mt)
            #pragma unroll
            for (int rh = 0; rh < 2; ++rh) {
                int r = rb + mt * 16 + rh * 8;
                int win = r >> 6, nr = r & 63;
                if (nr < 49) {
                    float* go = out + ((size_t)(2*b + win) * 49 + nr) * 128;
                    #pragma unroll
                    for (int nt = 0; nt < 4; ++nt) {
                        int cc = cb + nt * 8;
                        float v0 = pacc[mt][nt][rh*2]   + __ldg(proj_b + cc);
                        float v1 = pacc[mt][nt][rh*2+1] + __ldg(proj_b + cc + 1);
                        *(float2*)(go + cc) = make_float2(v0, v1);
                    }
                }
            }
    }
}

extern "C" void kernel_launch(void* const* d_in, const int* in_sizes, int n_in,
                              void* d_out, int out_size)
{
    const float* x      = (const float*)d_in[0];
    const float* mask   = (const float*)d_in[1];
    const float* qkv_w  = (const float*)d_in[2];
    const float* qkv_b  = (const float*)d_in[3];
    const float* proj_w = (const float*)d_in[4];
    const float* proj_b = (const float*)d_in[5];
    const float* table  = (const float*)d_in[6];
    const int*   relidx = (const int*)d_in[7];
    float*       out    = (float*)d_out;

    const int B  = in_sizes[0] / (49 * 128);
    const int nW = in_sizes[1] / (49 * 49);

    prep_all<<<2856, 256>>>(qkv_w, proj_w, mask, table, relidx, nW);

    cudaFuncSetAttribute(win_attn_fa5,
                         cudaFuncAttributeMaxDynamicSharedMemorySize, SMEM_BYTES);
    win_attn_fa5<<<B / 2, 512, SMEM_BYTES>>>(x, qkv_b, proj_b, out, nW);
}

// round 12
// speedup vs baseline: 1.2689x; 1.1178x over previous
#include <cuda_runtime.h>
#include <cuda_fp16.h>
#include <cstdint>

typedef unsigned int u32;

#define QSCALE 0.17677669529663687f

// ---- smem byte offsets (2 windows per CTA, 221184 B) ----
#define OFF_WB    0         /* 2 x 16384 weight ping-pong            */
#define OFF_QHI   32768     /* Q fp16 hi  [128 rows][256B]           */
#define OFF_QLO   65536
#define OFF_KHI   98304     /* K fp16 hi  [112 rows (2x56)][256B]    */
#define OFF_KLO   126976
#define OFF_AFHI  155648    /* A full hi [128 rows][256B] (VT alias) */
#define OFF_AFLO  188416    /* A full lo                             */
#define OFF_VTHI  155648    /* VT fp16   [256 rows][128B]            */
#define OFF_PHI   32768     /* proj A' fp16 hi (alias Q hi)          */
#define OFF_PLO   65536
#define SMEM_BYTES 221184

// fp16 weight fragment pieces, v4-packed layout
// pieces 0-3: q chunk (kh0-hi, kh0-lo, kh1-hi, kh1-lo)
// pieces 4-7: k chunk (same)
// pieces 8-9: v chunk (kh0, kh1; single RN fp16)
__device__ __align__(16) unsigned char g_wq[163840];
// pieces 10-11: proj (kh0, kh1; single RN fp16)
__device__ __align__(16) unsigned char g_wp[32768];
// combined bias+mask table: [w<64][h<4][i<49][j stride 56]
__device__ __align__(16) float g_bm[702464];

__device__ __forceinline__ u32 sw16(int ch, int r) {
    return (u32)((ch & 8) | ((ch ^ (r & 7)) & 7));
}

// ---------------- prep kernel ----------------
__global__ void prep_all(const float* __restrict__ qkv_w,
                         const float* __restrict__ proj_w,
                         const float* __restrict__ mask,
                         const float* __restrict__ bias_table,
                         const int*   __restrict__ rel_index,
                         int nW) {
    int e = blockIdx.x * 256 + threadIdx.x;
    if (e < 24576) {
        int piece = e >> 11;           // 0..11
        int rem = e & 2047;
        int lane = rem & 31, ks = (rem >> 5) & 3, nt = rem >> 7;
        const float* W;
        unsigned char* dst;
        int ldw, nbase, kh, part;
        if (piece < 8) {               // q/k chunks, hi/lo pieces
            W = qkv_w; ldw = 384;
            nbase = (piece >> 2) * 128;
            kh = (piece >> 1) & 1;
            part = piece & 1;
            dst = g_wq + (size_t)piece * 16384;
        } else if (piece < 10) {       // v chunk, single fp16
            W = qkv_w; ldw = 384;
            nbase = 256;
            kh = piece - 8;
            part = 0;
            dst = g_wq + (size_t)piece * 16384;
        } else {                       // proj, single fp16
            W = proj_w; ldw = 128;
            nbase = 0;
            kh = piece - 10;
            part = 0;
            dst = g_wp + (size_t)(piece - 10) * 16384;
        }
        int k0 = kh * 64 + ks * 16 + (lane & 3) * 2;
        int n  = nbase + nt * 8 + (lane >> 2);
        float v0 = W[k0 * ldw + n],       v1 = W[(k0 + 1) * ldw + n];
        float v2 = W[(k0 + 8) * ldw + n], v3 = W[(k0 + 9) * ldw + n];
        __half h0 = __float2half_rn(v0), h1 = __float2half_rn(v1);
        __half h2 = __float2half_rn(v2), h3 = __float2half_rn(v3);
        __half2 r0, r1;
        if (part == 0) {
            r0 = __halves2half2(h0, h1);
            r1 = __halves2half2(h2, h3);
        } else {                       // residual (lo) piece
            r0 = __halves2half2(__float2half_rn(v0 - __half2float(h0)),
                                __float2half_rn(v1 - __half2float(h1)));
            r1 = __halves2half2(__float2half_rn(v2 - __half2float(h2)),
                                __float2half_rn(v3 - __half2float(h3)));
        }
        // v4-packed fragment layout: adjacent n-tiles contiguous
        int ng = nt >> 2, ntp = (nt >> 1) & 1, half = nt & 1;
        u32 off = (u32)((((ng * 2 + ntp) * 4 + ks) * 32 + lane) * 16 + half * 8);
        *(__half2*)(dst + off)     = r0;   // b0
        *(__half2*)(dst + off + 4) = r1;   // b1
    } else {
        int idx = e - 24576;
        if (idx < 702464) {
            int w = idx / 10976;
            int r = idx % 10976;
            int h = r / 2744;
            int r2 = r % 2744;
            int i = r2 / 56, j = r2 % 56;
            float val = 0.f;
            if (j < 49 && w < nW)
                val = bias_table[rel_index[i * 49 + j] * 4 + h] + mask[w * 2401 + i * 49 + j];
            g_bm[idx] = val;
        }
    }
}

// ---------------- PTX helpers ----------------
__device__ __forceinline__ void cp16(u32 dst, const void* src) {
    asm volatile("cp.async.cg.shared.global [%0], [%1], 16;" :: "r"(dst), "l"(src));
}
__device__ __forceinline__ void cp_commit() { asm volatile("cp.async.commit_group;"); }
template <int N> __device__ __forceinline__ void cp_wait() {
    asm volatile("cp.async.wait_group %0;" :: "n"(N));
}
__device__ __forceinline__ void ldm4(u32 r[4], u32 addr) {
    asm volatile("ldmatrix.sync.aligned.m8n8.x4.shared.b16 {%0,%1,%2,%3}, [%4];"
        : "=r"(r[0]), "=r"(r[1]), "=r"(r[2]), "=r"(r[3]) : "r"(addr));
}
__device__ __forceinline__ void ldm2(u32 r[2], u32 addr) {
    asm volatile("ldmatrix.sync.aligned.m8n8.x2.shared.b16 {%0,%1}, [%2];"
        : "=r"(r[0]), "=r"(r[1]) : "r"(addr));
}
__device__ __forceinline__ void mma16816h(float c[4], const u32 a[4], u32 b0, u32 b1) {
    asm volatile("mma.sync.aligned.m16n8k16.row.col.f32.f16.f16.f32 "
        "{%0,%1,%2,%3}, {%4,%5,%6,%7}, {%8,%9}, {%0,%1,%2,%3};"
        : "+f"(c[0]), "+f"(c[1]), "+f"(c[2]), "+f"(c[3])
        : "r"(a[0]), "r"(a[1]), "r"(a[2]), "r"(a[3]), "r"(b0), "r"(b1));
}
// fp16 RN split
__device__ __forceinline__ u32 pkh_f16(float a, float b) {
    u32 r;
    asm("cvt.rn.f16x2.f32 %0, %1, %2;" : "=r"(r) : "f"(b), "f"(a));
    return r;
}
__device__ __forceinline__ u32 pkl_f16(float a, float b, u32 h) {
    float ah, bh;
    asm("{\n\t.reg .b16 x,y;\n\tmov.b32 {x,y}, %2;\n\t"
        "cvt.f32.f16 %0, x;\n\tcvt.f32.f16 %1, y;\n\t}"
        : "=f"(ah), "=f"(bh) : "r"(h));
    return pkh_f16(a - ah, b - bh);
}

// piece i: 0-9 in g_wq, 10-11 in g_wp; buffer = i&1
__device__ __forceinline__ void issue_piece(u32 sb, int i, int tid) {
    const unsigned char* src =
        (i < 10 ? g_wq + (u32)i * 16384 : g_wp + (u32)(i - 10) * 16384) + tid * 32;
    u32 dst = sb + OFF_WB + (u32)(i & 1) * 16384 + (u32)tid * 32;
    cp16(dst, src); cp16(dst + 16, src + 16);
    cp_commit();
}

// v4-packed B fragment load: 2 x LDS.128 per ks
__device__ __forceinline__ void ldB(u32 b0[4], u32 b1[4], u32 bufB, int ng, int ks, int lane) {
    #pragma unroll
    for (int ntp = 0; ntp < 2; ++ntp) {
        u32 addr = bufB + (u32)((((ng * 2 + ntp) * 4 + ks) * 32 + lane) * 16);
        asm volatile("ld.shared.v4.b32 {%0,%1,%2,%3}, [%4];"
            : "=r"(b0[2*ntp]), "=r"(b1[2*ntp]), "=r"(b0[2*ntp+1]), "=r"(b1[2*ntp+1])
            : "r"(addr));
    }
}

// ---------------- main kernel: 2 windows per CTA, all-fp16 HMMA ----------------
__global__ __launch_bounds__(512, 1)
void win_attn_fa6(const float* __restrict__ x,
                  const float* __restrict__ qkv_b,
                  const float* __restrict__ proj_b,
                  float* __restrict__ out, int nW)
{
    extern __shared__ __align__(1024) unsigned char sm[];
    const u32 sb = (u32)__cvta_generic_to_shared(sm);
    const int tid = threadIdx.x, lane = tid & 31, wid = tid >> 5;
    const int b = blockIdx.x;
    const int mg = wid >> 2, ng = wid & 3;

    issue_piece(sb, 0, tid);
    issue_piece(sb, 1, tid);

    const float* xw = x + (size_t)(2 * b) * 49 * 128;

    // ---- build FULL A hi/lo once (fp16 RN split) ----
    {
        int row = tid >> 2, cg = tid & 3;
        int win = row >> 6, nr = row & 63;
        float xv[32];
        if (nr < 49) {
            const float4* src = (const float4*)(xw + ((size_t)win * 49 + nr) * 128 + cg * 32);
            #pragma unroll
            for (int q = 0; q < 8; ++q) {
                float4 t = src[q];
                xv[4*q] = t.x; xv[4*q+1] = t.y; xv[4*q+2] = t.z; xv[4*q+3] = t.w;
            }
        } else {
            #pragma unroll
            for (int q = 0; q < 32; ++q) xv[q] = 0.f;
        }
        #pragma unroll
        for (int h = 0; h < 4; ++h) {
            u32 hi[4], lo[4];
            #pragma unroll
            for (int p = 0; p < 4; ++p) {
                float a = xv[h*8 + 2*p], bb = xv[h*8 + 2*p + 1];
                hi[p] = pkh_f16(a, bb);
                lo[p] = pkl_f16(a, bb, hi[p]);
            }
            int ch = cg * 4 + h;
            u32 off = (u32)row * 256 + sw16(ch, row) * 16;
            *(uint4*)(sm + OFF_AFHI + off) = make_uint4(hi[0], hi[1], hi[2], hi[3]);
            *(uint4*)(sm + OFF_AFLO + off) = make_uint4(lo[0], lo[1], lo[2], lo[3]);
        }
    }
    __syncthreads();

    // ======== q/k chunks (c=0,1): fp16 3-pass, A-hi hoisted per k-half ========
    #pragma unroll 1
    for (int c = 0; c < 2; ++c) {
        float acc[2][4][4];
        #pragma unroll
        for (int mt = 0; mt < 2; ++mt)
            #pragma unroll
            for (int nt = 0; nt < 4; ++nt)
                #pragma unroll
                for (int e = 0; e < 4; ++e) acc[mt][nt][e] = 0.f;

        #pragma unroll 1
        for (int kh = 0; kh < 2; ++kh) {
            int p = c * 4 + kh * 2;

            u32 ah[4][2][4];
            #pragma unroll
            for (int ks = 0; ks < 4; ++ks)
                #pragma unroll
                for (int mt = 0; mt < 2; ++mt) {
                    int row = mg * 32 + mt * 16 + (lane & 7) + ((lane >> 3) & 1) * 8;
                    int ch = kh * 8 + ks * 2 + (lane >> 4);
                    ldm4(ah[ks][mt], sb + OFF_AFHI + (u32)row * 256 + sw16(ch, row) * 16);
                }

            // --- W-hi piece: (A-hi + A-lo) x W-hi ---
            cp_wait<1>(); __syncthreads();
            {
                u32 bufB = sb + OFF_WB + (u32)(p & 1) * 16384;
                #pragma unroll
                for (int ks = 0; ks < 4; ++ks) {
                    u32 al[2][4];
                    #pragma unroll
                    for (int mt = 0; mt < 2; ++mt) {
                        int row = mg * 32 + mt * 16 + (lane & 7) + ((lane >> 3) & 1) * 8;
                        int ch = kh * 8 + ks * 2 + (lane >> 4);
                        ldm4(al[mt], sb + OFF_AFLO + (u32)row * 256 + sw16(ch, row) * 16);
                    }
                    u32 b0[4], b1[4];
                    ldB(b0, b1, bufB, ng, ks, lane);
                    #pragma unroll
                    for (int mt = 0; mt < 2; ++mt)
                        #pragma unroll
                        for (int nt = 0; nt < 4; ++nt) {
                            mma16816h(acc[mt][nt], ah[ks][mt], b0[nt], b1[nt]);
                            mma16816h(acc[mt][nt], al[mt],     b0[nt], b1[nt]);
                        }
                }
            }
            __syncthreads();
            issue_piece(sb, p + 2, tid);

            // --- W-lo piece: A-hi x W-lo ---
            cp_wait<1>(); __syncthreads();
            {
                u32 bufB = sb + OFF_WB + (u32)((p + 1) & 1) * 16384;
                #pragma unroll
                for (int ks = 0; ks < 4; ++ks) {
                    u32 b0[4], b1[4];
                    ldB(b0, b1, bufB, ng, ks, lane);
                    #pragma unroll
                    for (int mt = 0; mt < 2; ++mt)
                        #pragma unroll
                        for (int nt = 0; nt < 4; ++nt)
                            mma16816h(acc[mt][nt], ah[ks][mt], b0[nt], b1[nt]);
                }
            }
            __syncthreads();
            issue_piece(sb, p + 3, tid);
        }

        // epilogue: Q (c==0) / K (c==1) as fp16 hi/lo
        {
            int rb = mg * 32 + (lane >> 2);
            int cb = ng * 32 + (lane & 3) * 2;
            #pragma unroll
            for (int mt = 0; mt < 2; ++mt)
                #pragma unroll
                for (int rh = 0; rh < 2; ++rh) {
                    int r = rb + mt * 16 + rh * 8;
                    int win = r >> 6, nr = r & 63;
                    bool ok = nr < 49;
                    #pragma unroll
                    for (int nt = 0; nt < 4; ++nt) {
                        int cc = cb + nt * 8;
                        float v0 = acc[mt][nt][rh*2]   + __ldg(qkv_b + c*128 + cc);
                        float v1 = acc[mt][nt][rh*2+1] + __ldg(qkv_b + c*128 + cc + 1);
                        if (c == 0) {
                            v0 = ok ? v0 * QSCALE : 0.f;
                            v1 = ok ? v1 * QSCALE : 0.f;
                            u32 byte = (u32)r * 256 + sw16(cc >> 3, r) * 16 + (cc & 7) * 2;
                            u32 hi = pkh_f16(v0, v1);
                            *(u32*)(sm + OFF_QHI + byte) = hi;
                            *(u32*)(sm + OFF_QLO + byte) = pkl_f16(v0, v1, hi);
                        } else {
                            if (nr < 56) {
                                v0 = ok ? v0 : 0.f; v1 = ok ? v1 : 0.f;
                                int kr = win * 56 + nr;
                                u32 byte = (u32)kr * 256 + sw16(cc >> 3, kr) * 16 + (cc & 7) * 2;
                                u32 hi = pkh_f16(v0, v1);
                                *(u32*)(sm + OFF_KHI + byte) = hi;
                                *(u32*)(sm + OFF_KLO + byte) = pkl_f16(v0, v1, hi);
                            }
                        }
                    }
                }
        }
    }

    // ======== v chunk: fp16 2-pass, single W piece per k-half (pieces 8,9) ========
    {
        float acc[2][4][4];
        #pragma unroll
        for (int mt = 0; mt < 2; ++mt)
            #pragma unroll
            for (int nt = 0; nt < 4; ++nt)
                #pragma unroll
                for (int e = 0; e < 4; ++e) acc[mt][nt][e] = 0.f;

        #pragma unroll 1
        for (int kh = 0; kh < 2; ++kh) {
            cp_wait<1>(); __syncthreads();
            u32 bufB = sb + OFF_WB + (u32)((8 + kh) & 1) * 16384;
            #pragma unroll
            for (int ks = 0; ks < 4; ++ks) {
                u32 ah[2][4], al[2][4];
                #pragma unroll
                for (int mt = 0; mt < 2; ++mt) {
                    int row = mg * 32 + mt * 16 + (lane & 7) + ((lane >> 3) & 1) * 8;
                    int ch = kh * 8 + ks * 2 + (lane >> 4);
                    u32 off = (u32)row * 256 + sw16(ch, row) * 16;
                    ldm4(ah[mt], sb + OFF_AFHI + off);
                    ldm4(al[mt], sb + OFF_AFLO + off);
                }
                u32 b0[4], b1[4];
                ldB(b0, b1, bufB, ng, ks, lane);
                #pragma unroll
                for (int mt = 0; mt < 2; ++mt)
                    #pragma unroll
                    for (int nt = 0; nt < 4; ++nt) {
                        mma16816h(acc[mt][nt], ah[mt], b0[nt], b1[nt]);
                        mma16816h(acc[mt][nt], al[mt], b0[nt], b1[nt]);
                    }
            }
            __syncthreads();
            issue_piece(sb, 10 + kh, tid);
        }

        // epilogue: VT fp16 single (aliases A region, dead after the sync above)
        {
            int rb = mg * 32 + (lane >> 2);
            int cb = ng * 32 + (lane & 3) * 2;
            #pragma unroll
            for (int mt = 0; mt < 2; ++mt)
                #pragma unroll
                for (int rh = 0; rh < 2; ++rh) {
                    int r = rb + mt * 16 + rh * 8;
                    int win = r >> 6, nr = r & 63;
                    bool ok = nr < 49;
                    #pragma unroll
                    for (int nt = 0; nt < 4; ++nt) {
                        int cc = cb + nt * 8;
                        float v0 = acc[mt][nt][rh*2]   + __ldg(qkv_b + 256 + cc);
                        float v1 = acc[mt][nt][rh*2+1] + __ldg(qkv_b + 256 + cc + 1);
                        v0 = ok ? v0 : 0.f; v1 = ok ? v1 : 0.f;
                        #pragma unroll
                        for (int e = 0; e < 2; ++e) {
                            float vv = e ? v1 : v0;
                            int vr = win * 128 + cc + e;
                            u32 byte = (u32)vr * 128
                                     + (u32)((((nr >> 3) ^ (vr & 7)) & 7) << 4)
                                     + (nr & 7) * 2;
                            *(__half*)(sm + OFF_VTHI + byte) = __float2half_rn(vv);
                        }
                    }
                }
        }
    }
    __syncthreads();   // Q/K/VT visible to all warps

    // ======== attention: warp = (win, head, m-pair), 2 m-tiles joint ========
    {
        const int win = wid >> 3, h = (wid >> 1) & 3, mp = wid & 1;
        const int g = lane >> 2, t = lane & 3;
        const float* bm = g_bm + ((size_t)((2 * b + win) % nW) * 4 + h) * 2744;

        // ---- S = Q K^T (fp16 3-pass), K frags loaded once per ks ----
        float s[2][7][4];
        #pragma unroll
        for (int m = 0; m < 2; ++m)
            #pragma unroll
            for (int nt = 0; nt < 7; ++nt)
                #pragma unroll
                for (int e = 0; e < 4; ++e) s[m][nt][e] = 0.f;

        #pragma unroll
        for (int ks = 0; ks < 2; ++ks) {
            u32 aqh[2][4], aql[2][4];
            #pragma unroll
            for (int m = 0; m < 2; ++m) {
                int mt = mp * 2 + m;
                int rr = win * 64 + mt * 16 + (lane & 7) + ((lane >> 3) & 1) * 8;
                int ch = h * 4 + ks * 2 + (lane >> 4);
                u32 off = (u32)rr * 256 + sw16(ch, rr) * 16;
                ldm4(aqh[m], sb + OFF_QHI + off);
                ldm4(aql[m], sb + OFF_QLO + off);
            }
            u32 bkh[7][2], bkl[7][2];
            #pragma unroll
            for (int ntp = 0; ntp < 3; ++ntp) {
                int kr = win * 56 + ntp * 16 + ((lane >> 4) << 3) + (lane & 7);
                int ch = h * 4 + ks * 2 + ((lane >> 3) & 1);
                u32 off = (u32)kr * 256 + sw16(ch, kr) * 16;
                u32 r4[4];
                ldm4(r4, sb + OFF_KHI + off);
                bkh[2*ntp][0] = r4[0]; bkh[2*ntp][1] = r4[1];
                bkh[2*ntp+1][0] = r4[2]; bkh[2*ntp+1][1] = r4[3];
                ldm4(r4, sb + OFF_KLO + off);
                bkl[2*ntp][0] = r4[0]; bkl[2*ntp][1] = r4[1];
                bkl[2*ntp+1][0] = r4[2]; bkl[2*ntp+1][1] = r4[3];
            }
            {
                int kr = win * 56 + 48 + (lane & 7);
                int ch = h * 4 + ks * 2 + ((lane >> 3) & 1);
                u32 off = (u32)kr * 256 + sw16(ch, kr) * 16;
                ldm2(bkh[6], sb + OFF_KHI + off);
                ldm2(bkl[6], sb + OFF_KLO + off);
            }
            #pragma unroll
            for (int nt = 0; nt < 7; ++nt)
                #pragma unroll
                for (int m = 0; m < 2; ++m) {
                    mma16816h(s[m][nt], aqh[m], bkh[nt][0], bkh[nt][1]);
                    mma16816h(s[m][nt], aql[m], bkh[nt][0], bkh[nt][1]);
                    mma16816h(s[m][nt], aqh[m], bkl[nt][0], bkl[nt][1]);
                }
        }

        // ---- softmax per m-tile, pack P as fp16 hi/lo ----
        u32 ph[2][4][4], pl[2][4][4];
        #pragma unroll
        for (int m = 0; m < 2; ++m) {
            const int mt = mp * 2 + m;
            int i0 = mt * 16 + g;
            int o0 = min(i0, 48) * 56, o1 = min(i0 + 8, 48) * 56;
            #pragma unroll
            for (int nt = 0; nt < 7; ++nt) {
                int jj = nt * 8 + 2 * t;
                float2 b0 = *(const float2*)(bm + o0 + jj);
                float2 b1 = *(const float2*)(bm + o1 + jj);
                s[m][nt][0] = (jj     < 49) ? s[m][nt][0] + b0.x : -1e30f;
                s[m][nt][1] = (jj + 1 < 49) ? s[m][nt][1] + b0.y : -1e30f;
                s[m][nt][2] = (jj     < 49) ? s[m][nt][2] + b1.x : -1e30f;
                s[m][nt][3] = (jj + 1 < 49) ? s[m][nt][3] + b1.y : -1e30f;
            }
            float m0 = -1e30f, m1 = -1e30f;
            #pragma unroll
            for (int nt = 0; nt < 7; ++nt) {
                m0 = fmaxf(m0, fmaxf(s[m][nt][0], s[m][nt][1]));
                m1 = fmaxf(m1, fmaxf(s[m][nt][2], s[m][nt][3]));
            }
            m0 = fmaxf(m0, __shfl_xor_sync(0xffffffffu, m0, 1));
            m1 = fmaxf(m1, __shfl_xor_sync(0xffffffffu, m1, 1));
            m0 = fmaxf(m0, __shfl_xor_sync(0xffffffffu, m0, 2));
            m1 = fmaxf(m1, __shfl_xor_sync(0xffffffffu, m1, 2));
            float s0 = 0.f, s1 = 0.f;
            #pragma unroll
            for (int nt = 0; nt < 7; ++nt) {
                s[m][nt][0] = __expf(s[m][nt][0] - m0); s0 += s[m][nt][0];
                s[m][nt][1] = __expf(s[m][nt][1] - m0); s0 += s[m][nt][1];
                s[m][nt][2] = __expf(s[m][nt][2] - m1); s1 += s[m][nt][2];
                s[m][nt][3] = __expf(s[m][nt][3] - m1); s1 += s[m][nt][3];
            }
            s0 += __shfl_xor_sync(0xffffffffu, s0, 1);
            s1 += __shfl_xor_sync(0xffffffffu, s1, 1);
            s0 += __shfl_xor_sync(0xffffffffu, s0, 2);
            s1 += __shfl_xor_sync(0xffffffffu, s1, 2);
            float i0v = 1.f / s0, i1v = 1.f / s1;
            #pragma unroll
            for (int nt = 0; nt < 7; ++nt) {
                s[m][nt][0] *= i0v; s[m][nt][1] *= i0v;
                s[m][nt][2] *= i1v; s[m][nt][3] *= i1v;
            }
            #pragma unroll
            for (int k2 = 0; k2 < 4; ++k2) {
                int na = 2 * k2, nb = 2 * k2 + 1;
                ph[m][k2][0] = pkh_f16(s[m][na][0], s[m][na][1]);
                pl[m][k2][0] = pkl_f16(s[m][na][0], s[m][na][1], ph[m][k2][0]);
                ph[m][k2][1] = pkh_f16(s[m][na][2], s[m][na][3]);
                pl[m][k2][1] = pkl_f16(s[m][na][2], s[m][na][3], ph[m][k2][1]);
                if (nb < 7) {
                    ph[m][k2][2] = pkh_f16(s[m][nb][0], s[m][nb][1]);
                    pl[m][k2][2] = pkl_f16(s[m][nb][0], s[m][nb][1], ph[m][k2][2]);
                    ph[m][k2][3] = pkh_f16(s[m][nb][2], s[m][nb][3]);
                    pl[m][k2][3] = pkl_f16(s[m][nb][2], s[m][nb][3], ph[m][k2][3]);
                } else {
                    ph[m][k2][2] = ph[m][k2][3] = pl[m][k2][2] = pl[m][k2][3] = 0u;
                }
            }
        }

        // ---- O = P @ V (fp16 2-pass), V frags once per k2 ----
        float o[2][4][4];
        #pragma unroll
        for (int m = 0; m < 2; ++m)
            #pragma unroll
            for (int nt = 0; nt < 4; ++nt)
                #pragma unroll
                for (int e = 0; e < 4; ++e) o[m][nt][e] = 0.f;
        #pragma unroll
        for (int k2 = 0; k2 < 4; ++k2) {
            u32 bvh[4][2];
            #pragma unroll
            for (int dp = 0; dp < 2; ++dp) {
                int vr = win * 128 + h * 32 + dp * 16 + ((lane >> 4) << 3) + (lane & 7);
                int ch = k2 * 2 + ((lane >> 3) & 1);
                u32 off = (u32)vr * 128 + (u32)(((ch ^ (vr & 7)) & 7) << 4);
                u32 r4[4];
                ldm4(r4, sb + OFF_VTHI + off);
                bvh[2*dp][0] = r4[0]; bvh[2*dp][1] = r4[1];
                bvh[2*dp+1][0] = r4[2]; bvh[2*dp+1][1] = r4[3];
            }
            #pragma unroll
            for (int nt = 0; nt < 4; ++nt)
                #pragma unroll
                for (int m = 0; m < 2; ++m) {
                    mma16816h(o[m][nt], ph[m][k2], bvh[nt][0], bvh[nt][1]);
                    mma16816h(o[m][nt], pl[m][k2], bvh[nt][0], bvh[nt][1]);
                }
        }

        // ---- write O fp16 hi/lo into proj-A layout ----
        #pragma unroll
        for (int m = 0; m < 2; ++m) {
            const int mt = mp * 2 + m;
            #pragma unroll
            for (int nt = 0; nt < 4; ++nt)
                #pragma unroll
                for (int rh = 0; rh < 2; ++rh) {
                    int r = win * 64 + mt * 16 + g + rh * 8;
                    int col = h * 32 + nt * 8 + 2 * t;
                    u32 byte = (u32)r * 256 + sw16(col >> 3, r) * 16 + (col & 7) * 2;
                    u32 hi = pkh_f16(o[m][nt][rh*2], o[m][nt][rh*2+1]);
                    *(u32*)(sm + OFF_PHI + byte) = hi;
                    *(u32*)(sm + OFF_PLO + byte) = pkl_f16(o[m][nt][rh*2], o[m][nt][rh*2+1], hi);
                }
        }
    }
    __syncthreads();

    // ======== proj GEMM: fp16 2-pass, pieces 10,11 (prefetched) ========
    float pacc[2][4][4];
    #pragma unroll
    for (int mt = 0; mt < 2; ++mt)
        #pragma unroll
        for (int nt = 0; nt < 4; ++nt)
            #pragma unroll
            for (int e = 0; e < 4; ++e) pacc[mt][nt][e] = 0.f;

    #pragma unroll 1
    for (int kh = 0; kh < 2; ++kh) {
        if (kh == 0) cp_wait<1>(); else cp_wait<0>();
        __syncthreads();
        u32 bufB = sb + OFF_WB + (u32)kh * 16384;
        #pragma unroll
        for (int ks = 0; ks < 4; ++ks) {
            u32 ah[2][4], al[2][4];
            #pragma unroll
            for (int mt = 0; mt < 2; ++mt) {
                int row = mg * 32 + mt * 16 + (lane & 7) + ((lane >> 3) & 1) * 8;
                int ch = kh * 8 + ks * 2 + (lane >> 4);
                u32 off = (u32)row * 256 + sw16(ch, row) * 16;
                ldm4(ah[mt], sb + OFF_PHI + off);
                ldm4(al[mt], sb + OFF_PLO + off);
            }
            u32 b0[4], b1[4];
            ldB(b0, b1, bufB, ng, ks, lane);
            #pragma unroll
            for (int mt = 0; mt < 2; ++mt)
                #pragma unroll
                for (int nt = 0; nt < 4; ++nt) {
                    mma16816h(pacc[mt][nt], ah[mt], b0[nt], b1[nt]);
                    mma16816h(pacc[mt][nt], al[mt], b0[nt], b1[nt]);
                }
        }
    }

    // proj epilogue -> gmem (+bias)
    {
        int rb = mg * 32 + (lane >> 2);
        int cb = ng * 32 + (lane & 3) * 2;
        #pragma unroll
        for (int mt = 0; mt < 2; ++mt)
            #pragma unroll
            for (int rh = 0; rh < 2; ++rh) {
                int r = rb + mt * 16 + rh * 8;
                int win = r >> 6, nr = r & 63;
                if (nr < 49) {
                    float* go = out + ((size_t)(2*b + win) * 49 + nr) * 128;
                    #pragma unroll
                    for (int nt = 0; nt < 4; ++nt) {
                        int cc = cb + nt * 8;
                        float v0 = pacc[mt][nt][rh*2]   + __ldg(proj_b + cc);
                        float v1 = pacc[mt][nt][rh*2+1] + __ldg(proj_b + cc + 1);
                        *(float2*)(go + cc) = make_float2(v0, v1);
                    }
                }
            }
    }
}

extern "C" void kernel_launch(void* const* d_in, const int* in_sizes, int n_in,
                              void* d_out, int out_size)
{
    const float* x      = (const float*)d_in[0];
    const float* mask   = (const float*)d_in[1];
    const float* qkv_w  = (const float*)d_in[2];
    const float* qkv_b  = (const float*)d_in[3];
    const float* proj_w = (const float*)d_in[4];
    const float* proj_b = (const float*)d_in[5];
    const float* table  = (const float*)d_in[6];
    const int*   relidx = (const int*)d_in[7];
    float*       out    = (float*)d_out;

    const int B  = in_sizes[0] / (49 * 128);
    const int nW = in_sizes[1] / (49 * 49);

    prep_all<<<2840, 256>>>(qkv_w, proj_w, mask, table, relidx, nW);

    cudaFuncSetAttribute(win_attn_fa6,
                         cudaFuncAttributeMaxDynamicSharedMemorySize, SMEM_BYTES);
    win_attn_fa6<<<B / 2, 512, SMEM_BYTES>>>(x, qkv_b, proj_b, out, nW);
}

// round 13
// speedup vs baseline: 1.3949x; 1.0993x over previous
#include <cuda_runtime.h>
#include <cuda_fp16.h>
#include <cstdint>

typedef unsigned int u32;

#define QSCALE 0.17677669529663687f

// ---- smem byte offsets (2 windows per CTA, 188416 B; no weight buffer) ----
#define OFF_QHI   0         /* Q fp16 hi  [128 rows][256B]           */
#define OFF_QLO   32768
#define OFF_KHI   65536     /* K fp16 hi  [112 rows (2x56)][256B]    */
#define OFF_KLO   94208
#define OFF_AFHI  122880    /* A full hi [128 rows][256B] (VT alias) */
#define OFF_AFLO  155648
#define OFF_VTHI  122880    /* VT fp16 [256 rows][128B]              */
#define OFF_PHI   0         /* proj A' fp16 hi (alias Q hi)          */
#define OFF_PLO   32768
#define SMEM_BYTES 188416

// fp16 weight fragment pieces, v4-packed (read directly via LDG at mma time)
// g_wq pieces 0-3: q (kh0-hi, kh0-lo, kh1-hi, kh1-lo); 4-7: k (same); 8-9: v single
__device__ __align__(16) unsigned char g_wq[163840];
// g_wp pieces 0-1: proj single (kh0, kh1)
__device__ __align__(16) unsigned char g_wp[32768];
// combined bias+mask table: [w<64][h<4][i<49][j stride 56]
__device__ __align__(16) float g_bm[702464];

__device__ __forceinline__ u32 sw16(int ch, int r) {
    return (u32)((ch & 8) | ((ch ^ (r & 7)) & 7));
}

// ---------------- prep kernel (same fragment layout as round 12) ----------------
__global__ void prep_all(const float* __restrict__ qkv_w,
                         const float* __restrict__ proj_w,
                         const float* __restrict__ mask,
                         const float* __restrict__ bias_table,
                         const int*   __restrict__ rel_index,
                         int nW) {
    int e = blockIdx.x * 256 + threadIdx.x;
    if (e < 24576) {
        int piece = e >> 11;           // 0..11
        int rem = e & 2047;
        int lane = rem & 31, ks = (rem >> 5) & 3, nt = rem >> 7;
        const float* W;
        unsigned char* dst;
        int ldw, nbase, kh, part;
        if (piece < 8) {
            W = qkv_w; ldw = 384;
            nbase = (piece >> 2) * 128;
            kh = (piece >> 1) & 1;
            part = piece & 1;
            dst = g_wq + (size_t)piece * 16384;
        } else if (piece < 10) {
            W = qkv_w; ldw = 384;
            nbase = 256;
            kh = piece - 8;
            part = 0;
            dst = g_wq + (size_t)piece * 16384;
        } else {
            W = proj_w; ldw = 128;
            nbase = 0;
            kh = piece - 10;
            part = 0;
            dst = g_wp + (size_t)(piece - 10) * 16384;
        }
        int k0 = kh * 64 + ks * 16 + (lane & 3) * 2;
        int n  = nbase + nt * 8 + (lane >> 2);
        float v0 = W[k0 * ldw + n],       v1 = W[(k0 + 1) * ldw + n];
        float v2 = W[(k0 + 8) * ldw + n], v3 = W[(k0 + 9) * ldw + n];
        __half h0 = __float2half_rn(v0), h1 = __float2half_rn(v1);
        __half h2 = __float2half_rn(v2), h3 = __float2half_rn(v3);
        __half2 r0, r1;
        if (part == 0) {
            r0 = __halves2half2(h0, h1);
            r1 = __halves2half2(h2, h3);
        } else {
            r0 = __halves2half2(__float2half_rn(v0 - __half2float(h0)),
                                __float2half_rn(v1 - __half2float(h1)));
            r1 = __halves2half2(__float2half_rn(v2 - __half2float(h2)),
                                __float2half_rn(v3 - __half2float(h3)));
        }
        int ng = nt >> 2, ntp = (nt >> 1) & 1, half = nt & 1;
        u32 off = (u32)((((ng * 2 + ntp) * 4 + ks) * 32 + lane) * 16 + half * 8);
        *(__half2*)(dst + off)     = r0;
        *(__half2*)(dst + off + 4) = r1;
    } else {
        int idx = e - 24576;
        if (idx < 702464) {
            int w = idx / 10976;
            int r = idx % 10976;
            int h = r / 2744;
            int r2 = r % 2744;
            int i = r2 / 56, j = r2 % 56;
            float val = 0.f;
            if (j < 49 && w < nW)
                val = bias_table[rel_index[i * 49 + j] * 4 + h] + mask[w * 2401 + i * 49 + j];
            g_bm[idx] = val;
        }
    }
}

// ---------------- PTX helpers ----------------
__device__ __forceinline__ void ldm4(u32 r[4], u32 addr) {
    asm volatile("ldmatrix.sync.aligned.m8n8.x4.shared.b16 {%0,%1,%2,%3}, [%4];"
        : "=r"(r[0]), "=r"(r[1]), "=r"(r[2]), "=r"(r[3]) : "r"(addr));
}
__device__ __forceinline__ void ldm2(u32 r[2], u32 addr) {
    asm volatile("ldmatrix.sync.aligned.m8n8.x2.shared.b16 {%0,%1}, [%2];"
        : "=r"(r[0]), "=r"(r[1]) : "r"(addr));
}
__device__ __forceinline__ void mma16816h(float c[4], const u32 a[4], u32 b0, u32 b1) {
    asm volatile("mma.sync.aligned.m16n8k16.row.col.f32.f16.f16.f32 "
        "{%0,%1,%2,%3}, {%4,%5,%6,%7}, {%8,%9}, {%0,%1,%2,%3};"
        : "+f"(c[0]), "+f"(c[1]), "+f"(c[2]), "+f"(c[3])
        : "r"(a[0]), "r"(a[1]), "r"(a[2]), "r"(a[3]), "r"(b0), "r"(b1));
}
__device__ __forceinline__ u32 pkh_f16(float a, float b) {
    u32 r;
    asm("cvt.rn.f16x2.f32 %0, %1, %2;" : "=r"(r) : "f"(b), "f"(a));
    return r;
}
__device__ __forceinline__ u32 pkl_f16(float a, float b, u32 h) {
    float ah, bh;
    asm("{\n\t.reg .b16 x,y;\n\tmov.b32 {x,y}, %2;\n\t"
        "cvt.f32.f16 %0, x;\n\tcvt.f32.f16 %1, y;\n\t}"
        : "=f"(ah), "=f"(bh) : "r"(h));
    return pkh_f16(a - ah, b - bh);
}

// direct-LDG of v4-packed B fragments (L2-resident weights)
__device__ __forceinline__ void ldgB(u32 b0[4], u32 b1[4],
                                     const unsigned char* base, int ng, int ks, int lane) {
    #pragma unroll
    for (int ntp = 0; ntp < 2; ++ntp) {
        const uint4* p = (const uint4*)(base + (u32)((((ng * 2 + ntp) * 4 + ks) * 32 + lane) * 16));
        uint4 v = __ldg(p);
        b0[2*ntp] = v.x; b1[2*ntp] = v.y; b0[2*ntp+1] = v.z; b1[2*ntp+1] = v.w;
    }
}

// ---------------- main kernel: 2 windows/CTA, all-fp16 HMMA, barrier-free GEMMs ----------------
__global__ __launch_bounds__(512, 1)
void win_attn_fa7(const float* __restrict__ x,
                  const float* __restrict__ qkv_b,
                  const float* __restrict__ proj_b,
                  float* __restrict__ out, int nW)
{
    extern __shared__ __align__(1024) unsigned char sm[];
    const u32 sb = (u32)__cvta_generic_to_shared(sm);
    const int tid = threadIdx.x, lane = tid & 31, wid = tid >> 5;
    const int b = blockIdx.x;
    const int mg = wid >> 2, ng = wid & 3;

    const float* xw = x + (size_t)(2 * b) * 49 * 128;

    // ---- build FULL A hi/lo once (fp16 RN split) ----
    {
        int row = tid >> 2, cg = tid & 3;
        int win = row >> 6, nr = row & 63;
        float xv[32];
        if (nr < 49) {
            const float4* src = (const float4*)(xw + ((size_t)win * 49 + nr) * 128 + cg * 32);
            #pragma unroll
            for (int q = 0; q < 8; ++q) {
                float4 t = src[q];
                xv[4*q] = t.x; xv[4*q+1] = t.y; xv[4*q+2] = t.z; xv[4*q+3] = t.w;
            }
        } else {
            #pragma unroll
            for (int q = 0; q < 32; ++q) xv[q] = 0.f;
        }
        #pragma unroll
        for (int h = 0; h < 4; ++h) {
            u32 hi[4], lo[4];
            #pragma unroll
            for (int p = 0; p < 4; ++p) {
                float a = xv[h*8 + 2*p], bb = xv[h*8 + 2*p + 1];
                hi[p] = pkh_f16(a, bb);
                lo[p] = pkl_f16(a, bb, hi[p]);
            }
            int ch = cg * 4 + h;
            u32 off = (u32)row * 256 + sw16(ch, row) * 16;
            *(uint4*)(sm + OFF_AFHI + off) = make_uint4(hi[0], hi[1], hi[2], hi[3]);
            *(uint4*)(sm + OFF_AFLO + off) = make_uint4(lo[0], lo[1], lo[2], lo[3]);
        }
    }
    __syncthreads();   // sync #1: A visible

    // ======== q/k chunks (c=0,1): fp16 3-pass, merged hi/lo ks-loop, NO barriers ========
    #pragma unroll 1
    for (int c = 0; c < 2; ++c) {
        float acc[2][4][4];
        #pragma unroll
        for (int mt = 0; mt < 2; ++mt)
            #pragma unroll
            for (int nt = 0; nt < 4; ++nt)
                #pragma unroll
                for (int e = 0; e < 4; ++e) acc[mt][nt][e] = 0.f;

        #pragma unroll 1
        for (int kh = 0; kh < 2; ++kh) {
            const unsigned char* base_hi = g_wq + (size_t)(c * 4 + kh * 2) * 16384;
            const unsigned char* base_lo = base_hi + 16384;
            #pragma unroll
            for (int ks = 0; ks < 4; ++ks) {
                u32 bh0[4], bh1[4], bl0[4], bl1[4];
                ldgB(bh0, bh1, base_hi, ng, ks, lane);
                ldgB(bl0, bl1, base_lo, ng, ks, lane);
                u32 ah[2][4], al[2][4];
                #pragma unroll
                for (int mt = 0; mt < 2; ++mt) {
                    int row = mg * 32 + mt * 16 + (lane & 7) + ((lane >> 3) & 1) * 8;
                    int ch = kh * 8 + ks * 2 + (lane >> 4);
                    u32 off = (u32)row * 256 + sw16(ch, row) * 16;
                    ldm4(ah[mt], sb + OFF_AFHI + off);
                    ldm4(al[mt], sb + OFF_AFLO + off);
                }
                #pragma unroll
                for (int mt = 0; mt < 2; ++mt)
                    #pragma unroll
                    for (int nt = 0; nt < 4; ++nt) {
                        mma16816h(acc[mt][nt], ah[mt], bh0[nt], bh1[nt]);
                        mma16816h(acc[mt][nt], al[mt], bh0[nt], bh1[nt]);
                        mma16816h(acc[mt][nt], ah[mt], bl0[nt], bl1[nt]);
                    }
            }
        }

        // epilogue: Q (c==0) / K (c==1) as fp16 hi/lo
        {
            int rb = mg * 32 + (lane >> 2);
            int cb = ng * 32 + (lane & 3) * 2;
            #pragma unroll
            for (int mt = 0; mt < 2; ++mt)
                #pragma unroll
                for (int rh = 0; rh < 2; ++rh) {
                    int r = rb + mt * 16 + rh * 8;
                    int win = r >> 6, nr = r & 63;
                    bool ok = nr < 49;
                    #pragma unroll
                    for (int nt = 0; nt < 4; ++nt) {
                        int cc = cb + nt * 8;
                        float v0 = acc[mt][nt][rh*2]   + __ldg(qkv_b + c*128 + cc);
                        float v1 = acc[mt][nt][rh*2+1] + __ldg(qkv_b + c*128 + cc + 1);
                        if (c == 0) {
                            v0 = ok ? v0 * QSCALE : 0.f;
                            v1 = ok ? v1 * QSCALE : 0.f;
                            u32 byte = (u32)r * 256 + sw16(cc >> 3, r) * 16 + (cc & 7) * 2;
                            u32 hi = pkh_f16(v0, v1);
                            *(u32*)(sm + OFF_QHI + byte) = hi;
                            *(u32*)(sm + OFF_QLO + byte) = pkl_f16(v0, v1, hi);
                        } else {
                            if (nr < 56) {
                                v0 = ok ? v0 : 0.f; v1 = ok ? v1 : 0.f;
                                int kr = win * 56 + nr;
                                u32 byte = (u32)kr * 256 + sw16(cc >> 3, kr) * 16 + (cc & 7) * 2;
                                u32 hi = pkh_f16(v0, v1);
                                *(u32*)(sm + OFF_KHI + byte) = hi;
                                *(u32*)(sm + OFF_KLO + byte) = pkl_f16(v0, v1, hi);
                            }
                        }
                    }
                }
        }
    }

    // ======== v chunk: fp16 2-pass, single W per k-half ========
    {
        float acc[2][4][4];
        #pragma unroll
        for (int mt = 0; mt < 2; ++mt)
            #pragma unroll
            for (int nt = 0; nt < 4; ++nt)
                #pragma unroll
                for (int e = 0; e < 4; ++e) acc[mt][nt][e] = 0.f;

        #pragma unroll 1
        for (int kh = 0; kh < 2; ++kh) {
            const unsigned char* base = g_wq + (size_t)(8 + kh) * 16384;
            #pragma unroll
            for (int ks = 0; ks < 4; ++ks) {
                u32 b0[4], b1[4];
                ldgB(b0, b1, base, ng, ks, lane);
                u32 ah[2][4], al[2][4];
                #pragma unroll
                for (int mt = 0; mt < 2; ++mt) {
                    int row = mg * 32 + mt * 16 + (lane & 7) + ((lane >> 3) & 1) * 8;
                    int ch = kh * 8 + ks * 2 + (lane >> 4);
                    u32 off = (u32)row * 256 + sw16(ch, row) * 16;
                    ldm4(ah[mt], sb + OFF_AFHI + off);
                    ldm4(al[mt], sb + OFF_AFLO + off);
                }
                #pragma unroll
                for (int mt = 0; mt < 2; ++mt)
                    #pragma unroll
                    for (int nt = 0; nt < 4; ++nt) {
                        mma16816h(acc[mt][nt], ah[mt], b0[nt], b1[nt]);
                        mma16816h(acc[mt][nt], al[mt], b0[nt], b1[nt]);
                    }
            }
        }
        __syncthreads();   // sync #2: all A reads done before VT overwrites A

        // epilogue: VT fp16 single (aliases A-hi region)
        {
            int rb = mg * 32 + (lane >> 2);
            int cb = ng * 32 + (lane & 3) * 2;
            #pragma unroll
            for (int mt = 0; mt < 2; ++mt)
                #pragma unroll
                for (int rh = 0; rh < 2; ++rh) {
                    int r = rb + mt * 16 + rh * 8;
                    int win = r >> 6, nr = r & 63;
                    bool ok = nr < 49;
                    #pragma unroll
                    for (int nt = 0; nt < 4; ++nt) {
                        int cc = cb + nt * 8;
                        float v0 = acc[mt][nt][rh*2]   + __ldg(qkv_b + 256 + cc);
                        float v1 = acc[mt][nt][rh*2+1] + __ldg(qkv_b + 256 + cc + 1);
                        v0 = ok ? v0 : 0.f; v1 = ok ? v1 : 0.f;
                        #pragma unroll
                        for (int e = 0; e < 2; ++e) {
                            float vv = e ? v1 : v0;
                            int vr = win * 128 + cc + e;
                            u32 byte = (u32)vr * 128
                                     + (u32)((((nr >> 3) ^ (vr & 7)) & 7) << 4)
                                     + (nr & 7) * 2;
                            *(__half*)(sm + OFF_VTHI + byte) = __float2half_rn(vv);
                        }
                    }
                }
        }
    }
    __syncthreads();   // sync #3: Q/K/VT visible

    // ======== attention: warp = (win, head, m-pair), 2 m-tiles joint ========
    {
        const int win = wid >> 3, h = (wid >> 1) & 3, mp = wid & 1;
        const int g = lane >> 2, t = lane & 3;
        const float* bm = g_bm + ((size_t)((2 * b + win) % nW) * 4 + h) * 2744;

        float s[2][7][4];
        #pragma unroll
        for (int m = 0; m < 2; ++m)
            #pragma unroll
            for (int nt = 0; nt < 7; ++nt)
                #pragma unroll
                for (int e = 0; e < 4; ++e) s[m][nt][e] = 0.f;

        #pragma unroll
        for (int ks = 0; ks < 2; ++ks) {
            u32 aqh[2][4], aql[2][4];
            #pragma unroll
            for (int m = 0; m < 2; ++m) {
                int mt = mp * 2 + m;
                int rr = win * 64 + mt * 16 + (lane & 7) + ((lane >> 3) & 1) * 8;
                int ch = h * 4 + ks * 2 + (lane >> 4);
                u32 off = (u32)rr * 256 + sw16(ch, rr) * 16;
                ldm4(aqh[m], sb + OFF_QHI + off);
                ldm4(aql[m], sb + OFF_QLO + off);
            }
            u32 bkh[7][2], bkl[7][2];
            #pragma unroll
            for (int ntp = 0; ntp < 3; ++ntp) {
                int kr = win * 56 + ntp * 16 + ((lane >> 4) << 3) + (lane & 7);
                int ch = h * 4 + ks * 2 + ((lane >> 3) & 1);
                u32 off = (u32)kr * 256 + sw16(ch, kr) * 16;
                u32 r4[4];
                ldm4(r4, sb + OFF_KHI + off);
                bkh[2*ntp][0] = r4[0]; bkh[2*ntp][1] = r4[1];
                bkh[2*ntp+1][0] = r4[2]; bkh[2*ntp+1][1] = r4[3];
                ldm4(r4, sb + OFF_KLO + off);
                bkl[2*ntp][0] = r4[0]; bkl[2*ntp][1] = r4[1];
                bkl[2*ntp+1][0] = r4[2]; bkl[2*ntp+1][1] = r4[3];
            }
            {
                int kr = win * 56 + 48 + (lane & 7);
                int ch = h * 4 + ks * 2 + ((lane >> 3) & 1);
                u32 off = (u32)kr * 256 + sw16(ch, kr) * 16;
                ldm2(bkh[6], sb + OFF_KHI + off);
                ldm2(bkl[6], sb + OFF_KLO + off);
            }
            #pragma unroll
            for (int nt = 0; nt < 7; ++nt)
                #pragma unroll
                for (int m = 0; m < 2; ++m) {
                    mma16816h(s[m][nt], aqh[m], bkh[nt][0], bkh[nt][1]);
                    mma16816h(s[m][nt], aql[m], bkh[nt][0], bkh[nt][1]);
                    mma16816h(s[m][nt], aqh[m], bkl[nt][0], bkl[nt][1]);
                }
        }

        // softmax per m-tile, pack P as fp16 hi/lo
        u32 ph[2][4][4], pl[2][4][4];
        #pragma unroll
        for (int m = 0; m < 2; ++m) {
            const int mt = mp * 2 + m;
            int i0 = mt * 16 + g;
            int o0 = min(i0, 48) * 56, o1 = min(i0 + 8, 48) * 56;
            #pragma unroll
            for (int nt = 0; nt < 7; ++nt) {
                int jj = nt * 8 + 2 * t;
                float2 b0 = *(const float2*)(bm + o0 + jj);
                float2 b1 = *(const float2*)(bm + o1 + jj);
                s[m][nt][0] = (jj     < 49) ? s[m][nt][0] + b0.x : -1e30f;
                s[m][nt][1] = (jj + 1 < 49) ? s[m][nt][1] + b0.y : -1e30f;
                s[m][nt][2] = (jj     < 49) ? s[m][nt][2] + b1.x : -1e30f;
                s[m][nt][3] = (jj + 1 < 49) ? s[m][nt][3] + b1.y : -1e30f;
            }
            float m0 = -1e30f, m1 = -1e30f;
            #pragma unroll
            for (int nt = 0; nt < 7; ++nt) {
                m0 = fmaxf(m0, fmaxf(s[m][nt][0], s[m][nt][1]));
                m1 = fmaxf(m1, fmaxf(s[m][nt][2], s[m][nt][3]));
            }
            m0 = fmaxf(m0, __shfl_xor_sync(0xffffffffu, m0, 1));
            m1 = fmaxf(m1, __shfl_xor_sync(0xffffffffu, m1, 1));
            m0 = fmaxf(m0, __shfl_xor_sync(0xffffffffu, m0, 2));
            m1 = fmaxf(m1, __shfl_xor_sync(0xffffffffu, m1, 2));
            float s0 = 0.f, s1 = 0.f;
            #pragma unroll
            for (int nt = 0; nt < 7; ++nt) {
                s[m][nt][0] = __expf(s[m][nt][0] - m0); s0 += s[m][nt][0];
                s[m][nt][1] = __expf(s[m][nt][1] - m0); s0 += s[m][nt][1];
                s[m][nt][2] = __expf(s[m][nt][2] - m1); s1 += s[m][nt][2];
                s[m][nt][3] = __expf(s[m][nt][3] - m1); s1 += s[m][nt][3];
            }
            s0 += __shfl_xor_sync(0xffffffffu, s0, 1);
            s1 += __shfl_xor_sync(0xffffffffu, s1, 1);
            s0 += __shfl_xor_sync(0xffffffffu, s0, 2);
            s1 += __shfl_xor_sync(0xffffffffu, s1, 2);
            float i0v = 1.f / s0, i1v = 1.f / s1;
            #pragma unroll
            for (int nt = 0; nt < 7; ++nt) {
                s[m][nt][0] *= i0v; s[m][nt][1] *= i0v;
                s[m][nt][2] *= i1v; s[m][nt][3] *= i1v;
            }
            #pragma unroll
            for (int k2 = 0; k2 < 4; ++k2) {
                int na = 2 * k2, nb = 2 * k2 + 1;
                ph[m][k2][0] = pkh_f16(s[m][na][0], s[m][na][1]);
                pl[m][k2][0] = pkl_f16(s[m][na][0], s[m][na][1], ph[m][k2][0]);
                ph[m][k2][1] = pkh_f16(s[m][na][2], s[m][na][3]);
                pl[m][k2][1] = pkl_f16(s[m][na][2], s[m][na][3], ph[m][k2][1]);
                if (nb < 7) {
                    ph[m][k2][2] = pkh_f16(s[m][nb][0], s[m][nb][1]);
                    pl[m][k2][2] = pkl_f16(s[m][nb][0], s[m][nb][1], ph[m][k2][2]);
                    ph[m][k2][3] = pkh_f16(s[m][nb][2], s[m][nb][3]);
                    pl[m][k2][3] = pkl_f16(s[m][nb][2], s[m][nb][3], ph[m][k2][3]);
                } else {
                    ph[m][k2][2] = ph[m][k2][3] = pl[m][k2][2] = pl[m][k2][3] = 0u;
                }
            }
        }

        // O = P @ V (fp16 2-pass), V frags once per k2
        float o[2][4][4];
        #pragma unroll
        for (int m = 0; m < 2; ++m)
            #pragma unroll
            for (int nt = 0; nt < 4; ++nt)
                #pragma unroll
                for (int e = 0; e < 4; ++e) o[m][nt][e] = 0.f;
        #pragma unroll
        for (int k2 = 0; k2 < 4; ++k2) {
            u32 bvh[4][2];
            #pragma unroll
            for (int dp = 0; dp < 2; ++dp) {
                int vr = win * 128 + h * 32 + dp * 16 + ((lane >> 4) << 3) + (lane & 7);
                int ch = k2 * 2 + ((lane >> 3) & 1);
                u32 off = (u32)vr * 128 + (u32)(((ch ^ (vr & 7)) & 7) << 4);
                u32 r4[4];
                ldm4(r4, sb + OFF_VTHI + off);
                bvh[2*dp][0] = r4[0]; bvh[2*dp][1] = r4[1];
                bvh[2*dp+1][0] = r4[2]; bvh[2*dp+1][1] = r4[3];
            }
            #pragma unroll
            for (int nt = 0; nt < 4; ++nt)
                #pragma unroll
                for (int m = 0; m < 2; ++m) {
                    mma16816h(o[m][nt], ph[m][k2], bvh[nt][0], bvh[nt][1]);
                    mma16816h(o[m][nt], pl[m][k2], bvh[nt][0], bvh[nt][1]);
                }
        }

        // write O fp16 hi/lo into proj-A layout (self-owned byte ranges)
        #pragma unroll
        for (int m = 0; m < 2; ++m) {
            const int mt = mp * 2 + m;
            #pragma unroll
            for (int nt = 0; nt < 4; ++nt)
                #pragma unroll
                for (int rh = 0; rh < 2; ++rh) {
                    int r = win * 64 + mt * 16 + g + rh * 8;
                    int col = h * 32 + nt * 8 + 2 * t;
                    u32 byte = (u32)r * 256 + sw16(col >> 3, r) * 16 + (col & 7) * 2;
                    u32 hi = pkh_f16(o[m][nt][rh*2], o[m][nt][rh*2+1]);
                    *(u32*)(sm + OFF_PHI + byte) = hi;
                    *(u32*)(sm + OFF_PLO + byte) = pkl_f16(o[m][nt][rh*2], o[m][nt][rh*2+1], hi);
                }
        }
    }
    __syncthreads();   // sync #4: O visible for proj

    // ======== proj GEMM: fp16 2-pass, direct-LDG weights ========
    float pacc[2][4][4];
    #pragma unroll
    for (int mt = 0; mt < 2; ++mt)
        #pragma unroll
        for (int nt = 0; nt < 4; ++nt)
            #pragma unroll
            for (int e = 0; e < 4; ++e) pacc[mt][nt][e] = 0.f;

    #pragma unroll 1
    for (int kh = 0; kh < 2; ++kh) {
        const unsigned char* base = g_wp + (size_t)kh * 16384;
        #pragma unroll
        for (int ks = 0; ks < 4; ++ks) {
            u32 b0[4], b1[4];
            ldgB(b0, b1, base, ng, ks, lane);
            u32 ah[2][4], al[2][4];
            #pragma unroll
            for (int mt = 0; mt < 2; ++mt) {
                int row = mg * 32 + mt * 16 + (lane & 7) + ((lane >> 3) & 1) * 8;
                int ch = kh * 8 + ks * 2 + (lane >> 4);
                u32 off = (u32)row * 256 + sw16(ch, row) * 16;
                ldm4(ah[mt], sb + OFF_PHI + off);
                ldm4(al[mt], sb + OFF_PLO + off);
            }
            #pragma unroll
            for (int mt = 0; mt < 2; ++mt)
                #pragma unroll
                for (int nt = 0; nt < 4; ++nt) {
                    mma16816h(pacc[mt][nt], ah[mt], b0[nt], b1[nt]);
                    mma16816h(pacc[mt][nt], al[mt], b0[nt], b1[nt]);
                }
        }
    }

    // proj epilogue -> gmem (+bias)
    {
        int rb = mg * 32 + (lane >> 2);
        int cb = ng * 32 + (lane & 3) * 2;
        #pragma unroll
        for (int mt = 0; mt < 2; ++mt)
            #pragma unroll
            for (int rh = 0; rh < 2; ++rh) {
                int r = rb + mt * 16 + rh * 8;
                int win = r >> 6, nr = r & 63;
                if (nr < 49) {
                    float* go = out + ((size_t)(2*b + win) * 49 + nr) * 128;
                    #pragma unroll
                    for (int nt = 0; nt < 4; ++nt) {
                        int cc = cb + nt * 8;
                        float v0 = pacc[mt][nt][rh*2]   + __ldg(proj_b + cc);
                        float v1 = pacc[mt][nt][rh*2+1] + __ldg(proj_b + cc + 1);
                        *(float2*)(go + cc) = make_float2(v0, v1);
                    }
                }
            }
    }
}

extern "C" void kernel_launch(void* const* d_in, const int* in_sizes, int n_in,
                              void* d_out, int out_size)
{
    const float* x      = (const float*)d_in[0];
    const float* mask   = (const float*)d_in[1];
    const float* qkv_w  = (const float*)d_in[2];
    const float* qkv_b  = (const float*)d_in[3];
    const float* proj_w = (const float*)d_in[4];
    const float* proj_b = (const float*)d_in[5];
    const float* table  = (const float*)d_in[6];
    const int*   relidx = (const int*)d_in[7];
    float*       out    = (float*)d_out;

    const int B  = in_sizes[0] / (49 * 128);
    const int nW = in_sizes[1] / (49 * 49);

    prep_all<<<2840, 256>>>(qkv_w, proj_w, mask, table, relidx, nW);

    cudaFuncSetAttribute(win_attn_fa7,
                         cudaFuncAttributeMaxDynamicSharedMemorySize, SMEM_BYTES);
    win_attn_fa7<<<B / 2, 512, SMEM_BYTES>>>(x, qkv_b, proj_b, out, nW);
}

// round 14
// speedup vs baseline: 1.5660x; 1.1226x over previous
#include <cuda_runtime.h>
#include <cuda_fp16.h>
#include <cstdint>

typedef unsigned int u32;

#define QSCALE 0.17677669529663687f

// ---- smem byte offsets (2 windows per CTA, 188416 B) ----
#define OFF_QHI   0
#define OFF_QLO   32768
#define OFF_KHI   65536
#define OFF_KLO   94208
#define OFF_AFHI  122880
#define OFF_AFLO  155648
#define OFF_VTHI  122880    /* aliases AFHI after v-MMA */
#define OFF_PHI   0         /* proj A' single fp16 (alias Q hi) */
#define SMEM_BYTES 188416

// fp16 weight fragment pieces, v4-packed (direct LDG at mma time)
__device__ __align__(16) unsigned char g_wq[163840];
__device__ __align__(16) unsigned char g_wp[32768];
__device__ __align__(16) float g_bm[702464];

__device__ __forceinline__ u32 sw16(int ch, int r) {
    return (u32)((ch & 8) | ((ch ^ (r & 7)) & 7));
}

// ---------------- prep kernel (unchanged layout) ----------------
__global__ void prep_all(const float* __restrict__ qkv_w,
                         const float* __restrict__ proj_w,
                         const float* __restrict__ mask,
                         const float* __restrict__ bias_table,
                         const int*   __restrict__ rel_index,
                         int nW) {
    int e = blockIdx.x * 256 + threadIdx.x;
    if (e < 24576) {
        int piece = e >> 11;
        int rem = e & 2047;
        int lane = rem & 31, ks = (rem >> 5) & 3, nt = rem >> 7;
        const float* W;
        unsigned char* dst;
        int ldw, nbase, kh, part;
        if (piece < 8) {
            W = qkv_w; ldw = 384;
            nbase = (piece >> 2) * 128;
            kh = (piece >> 1) & 1;
            part = piece & 1;
            dst = g_wq + (size_t)piece * 16384;
        } else if (piece < 10) {
            W = qkv_w; ldw = 384;
            nbase = 256;
            kh = piece - 8;
            part = 0;
            dst = g_wq + (size_t)piece * 16384;
        } else {
            W = proj_w; ldw = 128;
            nbase = 0;
            kh = piece - 10;
            part = 0;
            dst = g_wp + (size_t)(piece - 10) * 16384;
        }
        int k0 = kh * 64 + ks * 16 + (lane & 3) * 2;
        int n  = nbase + nt * 8 + (lane >> 2);
        float v0 = W[k0 * ldw + n],       v1 = W[(k0 + 1) * ldw + n];
        float v2 = W[(k0 + 8) * ldw + n], v3 = W[(k0 + 9) * ldw + n];
        __half h0 = __float2half_rn(v0), h1 = __float2half_rn(v1);
        __half h2 = __float2half_rn(v2), h3 = __float2half_rn(v3);
        __half2 r0, r1;
        if (part == 0) {
            r0 = __halves2half2(h0, h1);
            r1 = __halves2half2(h2, h3);
        } else {
            r0 = __halves2half2(__float2half_rn(v0 - __half2float(h0)),
                                __float2half_rn(v1 - __half2float(h1)));
            r1 = __halves2half2(__float2half_rn(v2 - __half2float(h2)),
                                __float2half_rn(v3 - __half2float(h3)));
        }
        int ng = nt >> 2, ntp = (nt >> 1) & 1, half = nt & 1;
        u32 off = (u32)((((ng * 2 + ntp) * 4 + ks) * 32 + lane) * 16 + half * 8);
        *(__half2*)(dst + off)     = r0;
        *(__half2*)(dst + off + 4) = r1;
    } else {
        int idx = e - 24576;
        if (idx < 702464) {
            int w = idx / 10976;
            int r = idx % 10976;
            int h = r / 2744;
            int r2 = r % 2744;
            int i = r2 / 56, j = r2 % 56;
            float val = 0.f;
            if (j < 49 && w < nW)
                val = bias_table[rel_index[i * 49 + j] * 4 + h] + mask[w * 2401 + i * 49 + j];
            g_bm[idx] = val;
        }
    }
}

// ---------------- PTX helpers ----------------
__device__ __forceinline__ void ldm4(u32 r[4], u32 addr) {
    asm volatile("ldmatrix.sync.aligned.m8n8.x4.shared.b16 {%0,%1,%2,%3}, [%4];"
        : "=r"(r[0]), "=r"(r[1]), "=r"(r[2]), "=r"(r[3]) : "r"(addr));
}
__device__ __forceinline__ void ldm2(u32 r[2], u32 addr) {
    asm volatile("ldmatrix.sync.aligned.m8n8.x2.shared.b16 {%0,%1}, [%2];"
        : "=r"(r[0]), "=r"(r[1]) : "r"(addr));
}
__device__ __forceinline__ void mma16816h(float c[4], const u32 a[4], u32 b0, u32 b1) {
    asm volatile("mma.sync.aligned.m16n8k16.row.col.f32.f16.f16.f32 "
        "{%0,%1,%2,%3}, {%4,%5,%6,%7}, {%8,%9}, {%0,%1,%2,%3};"
        : "+f"(c[0]), "+f"(c[1]), "+f"(c[2]), "+f"(c[3])
        : "r"(a[0]), "r"(a[1]), "r"(a[2]), "r"(a[3]), "r"(b0), "r"(b1));
}
__device__ __forceinline__ u32 pkh_f16(float a, float b) {
    u32 r;
    asm("cvt.rn.f16x2.f32 %0, %1, %2;" : "=r"(r) : "f"(b), "f"(a));
    return r;
}
__device__ __forceinline__ u32 pkl_f16(float a, float b, u32 h) {
    float ah, bh;
    asm("{\n\t.reg .b16 x,y;\n\tmov.b32 {x,y}, %2;\n\t"
        "cvt.f32.f16 %0, x;\n\tcvt.f32.f16 %1, y;\n\t}"
        : "=f"(ah), "=f"(bh) : "r"(h));
    return pkh_f16(a - ah, b - bh);
}
__device__ __forceinline__ void ldgB(u32 b0[4], u32 b1[4],
                                     const unsigned char* base, int ng, int ks, int lane) {
    #pragma unroll
    for (int ntp = 0; ntp < 2; ++ntp) {
        const uint4* p = (const uint4*)(base + (u32)((((ng * 2 + ntp) * 4 + ks) * 32 + lane) * 16));
        uint4 v = __ldg(p);
        b0[2*ntp] = v.x; b1[2*ntp] = v.y; b0[2*ntp+1] = v.z; b1[2*ntp+1] = v.w;
    }
}

// ---------------- main kernel ----------------
__global__ __launch_bounds__(512, 1)
void win_attn_fa8(const float* __restrict__ x,
                  const float* __restrict__ qkv_b,
                  const float* __restrict__ proj_b,
                  float* __restrict__ out, int nW)
{
    extern __shared__ __align__(1024) unsigned char sm[];
    const u32 sb = (u32)__cvta_generic_to_shared(sm);
    const int tid = threadIdx.x, lane = tid & 31, wid = tid >> 5;
    const int b = blockIdx.x;
    const int mg = wid >> 2, ng = wid & 3;
    // hoisted per-warp A-fragment row constants
    const int arow0 = mg * 32 + (lane & 7) + ((lane >> 3) & 1) * 8;  // mt=0
    const int arow1 = arow0 + 16;                                     // mt=1
    const int achsel = lane >> 4;                                     // A frag ch parity

    const float* xw = x + (size_t)(2 * b) * 49 * 128;

    // ---- build FULL A hi/lo once (fp16 RN split) ----
    {
        int row = tid >> 2, cg = tid & 3;
        int win = row >> 6, nr = row & 63;
        float xv[32];
        if (nr < 49) {
            const float4* src = (const float4*)(xw + ((size_t)win * 49 + nr) * 128 + cg * 32);
            #pragma unroll
            for (int q = 0; q < 8; ++q) {
                float4 t = src[q];
                xv[4*q] = t.x; xv[4*q+1] = t.y; xv[4*q+2] = t.z; xv[4*q+3] = t.w;
            }
        } else {
            #pragma unroll
            for (int q = 0; q < 32; ++q) xv[q] = 0.f;
        }
        #pragma unroll
        for (int h = 0; h < 4; ++h) {
            u32 hi[4], lo[4];
            #pragma unroll
            for (int p = 0; p < 4; ++p) {
                float a = xv[h*8 + 2*p], bb = xv[h*8 + 2*p + 1];
                hi[p] = pkh_f16(a, bb);
                lo[p] = pkl_f16(a, bb, hi[p]);
            }
            int ch = cg * 4 + h;
            u32 off = (u32)row * 256 + sw16(ch, row) * 16;
            *(uint4*)(sm + OFF_AFHI + off) = make_uint4(hi[0], hi[1], hi[2], hi[3]);
            *(uint4*)(sm + OFF_AFLO + off) = make_uint4(lo[0], lo[1], lo[2], lo[3]);
        }
    }
    __syncthreads();   // sync #1

    // ======== FUSED q+k GEMM: fp16 3-pass, A frags loaded once per (kh,ks) ========
    {
        float accQ[2][4][4], accK[2][4][4];
        #pragma unroll
        for (int mt = 0; mt < 2; ++mt)
            #pragma unroll
            for (int nt = 0; nt < 4; ++nt)
                #pragma unroll
                for (int e = 0; e < 4; ++e) { accQ[mt][nt][e] = 0.f; accK[mt][nt][e] = 0.f; }

        #pragma unroll 1
        for (int kh = 0; kh < 2; ++kh) {
            const unsigned char* bq_hi = g_wq + (size_t)(kh * 2) * 16384;
            const unsigned char* bq_lo = bq_hi + 16384;
            const unsigned char* bk_hi = g_wq + (size_t)(4 + kh * 2) * 16384;
            const unsigned char* bk_lo = bk_hi + 16384;
            #pragma unroll
            for (int ks = 0; ks < 4; ++ks) {
                int ch = kh * 8 + ks * 2 + achsel;
                u32 off0 = (u32)arow0 * 256 + sw16(ch, arow0) * 16;
                u32 off1 = (u32)arow1 * 256 + sw16(ch, arow1) * 16;
                u32 ah[2][4], al[2][4];
                ldm4(ah[0], sb + OFF_AFHI + off0);
                ldm4(ah[1], sb + OFF_AFHI + off1);
                ldm4(al[0], sb + OFF_AFLO + off0);
                ldm4(al[1], sb + OFF_AFLO + off1);
                {
                    u32 bh0[4], bh1[4], bl0[4], bl1[4];
                    ldgB(bh0, bh1, bq_hi, ng, ks, lane);
                    ldgB(bl0, bl1, bq_lo, ng, ks, lane);
                    #pragma unroll
                    for (int mt = 0; mt < 2; ++mt)
                        #pragma unroll
                        for (int nt = 0; nt < 4; ++nt) {
                            mma16816h(accQ[mt][nt], ah[mt], bh0[nt], bh1[nt]);
                            mma16816h(accQ[mt][nt], al[mt], bh0[nt], bh1[nt]);
                            mma16816h(accQ[mt][nt], ah[mt], bl0[nt], bl1[nt]);
                        }
                }
                {
                    u32 bh0[4], bh1[4], bl0[4], bl1[4];
                    ldgB(bh0, bh1, bk_hi, ng, ks, lane);
                    ldgB(bl0, bl1, bk_lo, ng, ks, lane);
                    #pragma unroll
                    for (int mt = 0; mt < 2; ++mt)
                        #pragma unroll
                        for (int nt = 0; nt < 4; ++nt) {
                            mma16816h(accK[mt][nt], ah[mt], bh0[nt], bh1[nt]);
                            mma16816h(accK[mt][nt], al[mt], bh0[nt], bh1[nt]);
                            mma16816h(accK[mt][nt], ah[mt], bl0[nt], bl1[nt]);
                        }
                }
            }
        }

        // epilogue: Q and K as fp16 hi/lo
        {
            int rb = mg * 32 + (lane >> 2);
            int cb = ng * 32 + (lane & 3) * 2;
            #pragma unroll
            for (int mt = 0; mt < 2; ++mt)
                #pragma unroll
                for (int rh = 0; rh < 2; ++rh) {
                    int r = rb + mt * 16 + rh * 8;
                    int win = r >> 6, nr = r & 63;
                    bool ok = nr < 49;
                    #pragma unroll
                    for (int nt = 0; nt < 4; ++nt) {
                        int cc = cb + nt * 8;
                        {   // Q
                            float v0 = accQ[mt][nt][rh*2]   + __ldg(qkv_b + cc);
                            float v1 = accQ[mt][nt][rh*2+1] + __ldg(qkv_b + cc + 1);
                            v0 = ok ? v0 * QSCALE : 0.f;
                            v1 = ok ? v1 * QSCALE : 0.f;
                            u32 byte = (u32)r * 256 + sw16(cc >> 3, r) * 16 + (cc & 7) * 2;
                            u32 hi = pkh_f16(v0, v1);
                            *(u32*)(sm + OFF_QHI + byte) = hi;
                            *(u32*)(sm + OFF_QLO + byte) = pkl_f16(v0, v1, hi);
                        }
                        if (nr < 56) {  // K
                            float v0 = accK[mt][nt][rh*2]   + __ldg(qkv_b + 128 + cc);
                            float v1 = accK[mt][nt][rh*2+1] + __ldg(qkv_b + 128 + cc + 1);
                            v0 = ok ? v0 : 0.f; v1 = ok ? v1 : 0.f;
                            int kr = win * 56 + nr;
                            u32 byte = (u32)kr * 256 + sw16(cc >> 3, kr) * 16 + (cc & 7) * 2;
                            u32 hi = pkh_f16(v0, v1);
                            *(u32*)(sm + OFF_KHI + byte) = hi;
                            *(u32*)(sm + OFF_KLO + byte) = pkl_f16(v0, v1, hi);
                        }
                    }
                }
        }
    }

    // ======== v chunk: fp16 2-pass ========
    {
        float acc[2][4][4];
        #pragma unroll
        for (int mt = 0; mt < 2; ++mt)
            #pragma unroll
            for (int nt = 0; nt < 4; ++nt)
                #pragma unroll
                for (int e = 0; e < 4; ++e) acc[mt][nt][e] = 0.f;

        #pragma unroll 1
        for (int kh = 0; kh < 2; ++kh) {
            const unsigned char* base = g_wq + (size_t)(8 + kh) * 16384;
            #pragma unroll
            for (int ks = 0; ks < 4; ++ks) {
                u32 b0[4], b1[4];
                ldgB(b0, b1, base, ng, ks, lane);
                int ch = kh * 8 + ks * 2 + achsel;
                u32 off0 = (u32)arow0 * 256 + sw16(ch, arow0) * 16;
                u32 off1 = (u32)arow1 * 256 + sw16(ch, arow1) * 16;
                u32 ah[2][4], al[2][4];
                ldm4(ah[0], sb + OFF_AFHI + off0);
                ldm4(ah[1], sb + OFF_AFHI + off1);
                ldm4(al[0], sb + OFF_AFLO + off0);
                ldm4(al[1], sb + OFF_AFLO + off1);
                #pragma unroll
                for (int mt = 0; mt < 2; ++mt)
                    #pragma unroll
                    for (int nt = 0; nt < 4; ++nt) {
                        mma16816h(acc[mt][nt], ah[mt], b0[nt], b1[nt]);
                        mma16816h(acc[mt][nt], al[mt], b0[nt], b1[nt]);
                    }
            }
        }
        __syncthreads();   // sync #2: A reads done before VT overwrite

        // epilogue: VT fp16 single
        {
            int rb = mg * 32 + (lane >> 2);
            int cb = ng * 32 + (lane & 3) * 2;
            #pragma unroll
            for (int mt = 0; mt < 2; ++mt)
                #pragma unroll
                for (int rh = 0; rh < 2; ++rh) {
                    int r = rb + mt * 16 + rh * 8;
                    int win = r >> 6, nr = r & 63;
                    bool ok = nr < 49;
                    #pragma unroll
                    for (int nt = 0; nt < 4; ++nt) {
                        int cc = cb + nt * 8;
                        float v0 = acc[mt][nt][rh*2]   + __ldg(qkv_b + 256 + cc);
                        float v1 = acc[mt][nt][rh*2+1] + __ldg(qkv_b + 256 + cc + 1);
                        v0 = ok ? v0 : 0.f; v1 = ok ? v1 : 0.f;
                        #pragma unroll
                        for (int e = 0; e < 2; ++e) {
                            float vv = e ? v1 : v0;
                            int vr = win * 128 + cc + e;
                            u32 byte = (u32)vr * 128
                                     + (u32)((((nr >> 3) ^ (vr & 7)) & 7) << 4)
                                     + (nr & 7) * 2;
                            *(__half*)(sm + OFF_VTHI + byte) = __float2half_rn(vv);
                        }
                    }
                }
        }
    }
    __syncthreads();   // sync #3

    // ======== attention ========
    {
        const int win = wid >> 3, h = (wid >> 1) & 3, mp = wid & 1;
        const int g = lane >> 2, t = lane & 3;
        const float* bm = g_bm + ((size_t)((2 * b + win) % nW) * 4 + h) * 2744;

        float s[2][7][4];
        #pragma unroll
        for (int m = 0; m < 2; ++m)
            #pragma unroll
            for (int nt = 0; nt < 7; ++nt)
                #pragma unroll
                for (int e = 0; e < 4; ++e) s[m][nt][e] = 0.f;

        #pragma unroll
        for (int ks = 0; ks < 2; ++ks) {
            u32 aqh[2][4], aql[2][4];
            #pragma unroll
            for (int m = 0; m < 2; ++m) {
                int mt = mp * 2 + m;
                int rr = win * 64 + mt * 16 + (lane & 7) + ((lane >> 3) & 1) * 8;
                int ch = h * 4 + ks * 2 + (lane >> 4);
                u32 off = (u32)rr * 256 + sw16(ch, rr) * 16;
                ldm4(aqh[m], sb + OFF_QHI + off);
                ldm4(aql[m], sb + OFF_QLO + off);
            }
            u32 bkh[7][2], bkl[7][2];
            #pragma unroll
            for (int ntp = 0; ntp < 3; ++ntp) {
                int kr = win * 56 + ntp * 16 + ((lane >> 4) << 3) + (lane & 7);
                int ch = h * 4 + ks * 2 + ((lane >> 3) & 1);
                u32 off = (u32)kr * 256 + sw16(ch, kr) * 16;
                u32 r4[4];
                ldm4(r4, sb + OFF_KHI + off);
                bkh[2*ntp][0] = r4[0]; bkh[2*ntp][1] = r4[1];
                bkh[2*ntp+1][0] = r4[2]; bkh[2*ntp+1][1] = r4[3];
                ldm4(r4, sb + OFF_KLO + off);
                bkl[2*ntp][0] = r4[0]; bkl[2*ntp][1] = r4[1];
                bkl[2*ntp+1][0] = r4[2]; bkl[2*ntp+1][1] = r4[3];
            }
            {
                int kr = win * 56 + 48 + (lane & 7);
                int ch = h * 4 + ks * 2 + ((lane >> 3) & 1);
                u32 off = (u32)kr * 256 + sw16(ch, kr) * 16;
                ldm2(bkh[6], sb + OFF_KHI + off);
                ldm2(bkl[6], sb + OFF_KLO + off);
            }
            #pragma unroll
            for (int nt = 0; nt < 7; ++nt)
                #pragma unroll
                for (int m = 0; m < 2; ++m) {
                    mma16816h(s[m][nt], aqh[m], bkh[nt][0], bkh[nt][1]);
                    mma16816h(s[m][nt], aql[m], bkh[nt][0], bkh[nt][1]);
                    mma16816h(s[m][nt], aqh[m], bkl[nt][0], bkl[nt][1]);
                }
        }

        // softmax + pack P fp16 hi/lo
        u32 ph[2][4][4], pl[2][4][4];
        #pragma unroll
        for (int m = 0; m < 2; ++m) {
            const int mt = mp * 2 + m;
            int i0 = mt * 16 + g;
            int o0 = min(i0, 48) * 56, o1 = min(i0 + 8, 48) * 56;
            #pragma unroll
            for (int nt = 0; nt < 7; ++nt) {
                int jj = nt * 8 + 2 * t;
                float2 b0 = *(const float2*)(bm + o0 + jj);
                float2 b1 = *(const float2*)(bm + o1 + jj);
                s[m][nt][0] = (jj     < 49) ? s[m][nt][0] + b0.x : -1e30f;
                s[m][nt][1] = (jj + 1 < 49) ? s[m][nt][1] + b0.y : -1e30f;
                s[m][nt][2] = (jj     < 49) ? s[m][nt][2] + b1.x : -1e30f;
                s[m][nt][3] = (jj + 1 < 49) ? s[m][nt][3] + b1.y : -1e30f;
            }
            float m0 = -1e30f, m1 = -1e30f;
            #pragma unroll
            for (int nt = 0; nt < 7; ++nt) {
                m0 = fmaxf(m0, fmaxf(s[m][nt][0], s[m][nt][1]));
                m1 = fmaxf(m1, fmaxf(s[m][nt][2], s[m][nt][3]));
            }
            m0 = fmaxf(m0, __shfl_xor_sync(0xffffffffu, m0, 1));
            m1 = fmaxf(m1, __shfl_xor_sync(0xffffffffu, m1, 1));
            m0 = fmaxf(m0, __shfl_xor_sync(0xffffffffu, m0, 2));
            m1 = fmaxf(m1, __shfl_xor_sync(0xffffffffu, m1, 2));
            float s0 = 0.f, s1 = 0.f;
            #pragma unroll
            for (int nt = 0; nt < 7; ++nt) {
                s[m][nt][0] = __expf(s[m][nt][0] - m0); s0 += s[m][nt][0];
                s[m][nt][1] = __expf(s[m][nt][1] - m0); s0 += s[m][nt][1];
                s[m][nt][2] = __expf(s[m][nt][2] - m1); s1 += s[m][nt][2];
                s[m][nt][3] = __expf(s[m][nt][3] - m1); s1 += s[m][nt][3];
            }
            s0 += __shfl_xor_sync(0xffffffffu, s0, 1);
            s1 += __shfl_xor_sync(0xffffffffu, s1, 1);
            s0 += __shfl_xor_sync(0xffffffffu, s0, 2);
            s1 += __shfl_xor_sync(0xffffffffu, s1, 2);
            float i0v = 1.f / s0, i1v = 1.f / s1;
            #pragma unroll
            for (int nt = 0; nt < 7; ++nt) {
                s[m][nt][0] *= i0v; s[m][nt][1] *= i0v;
                s[m][nt][2] *= i1v; s[m][nt][3] *= i1v;
            }
            #pragma unroll
            for (int k2 = 0; k2 < 4; ++k2) {
                int na = 2 * k2, nb = 2 * k2 + 1;
                ph[m][k2][0] = pkh_f16(s[m][na][0], s[m][na][1]);
                pl[m][k2][0] = pkl_f16(s[m][na][0], s[m][na][1], ph[m][k2][0]);
                ph[m][k2][1] = pkh_f16(s[m][na][2], s[m][na][3]);
                pl[m][k2][1] = pkl_f16(s[m][na][2], s[m][na][3], ph[m][k2][1]);
                if (nb < 7) {
                    ph[m][k2][2] = pkh_f16(s[m][nb][0], s[m][nb][1]);
                    pl[m][k2][2] = pkl_f16(s[m][nb][0], s[m][nb][1], ph[m][k2][2]);
                    ph[m][k2][3] = pkh_f16(s[m][nb][2], s[m][nb][3]);
                    pl[m][k2][3] = pkl_f16(s[m][nb][2], s[m][nb][3], ph[m][k2][3]);
                } else {
                    ph[m][k2][2] = ph[m][k2][3] = pl[m][k2][2] = pl[m][k2][3] = 0u;
                }
            }
        }

        // O = P @ V (fp16 2-pass)
        float o[2][4][4];
        #pragma unroll
        for (int m = 0; m < 2; ++m)
            #pragma unroll
            for (int nt = 0; nt < 4; ++nt)
                #pragma unroll
                for (int e = 0; e < 4; ++e) o[m][nt][e] = 0.f;
        #pragma unroll
        for (int k2 = 0; k2 < 4; ++k2) {
            u32 bvh[4][2];
            #pragma unroll
            for (int dp = 0; dp < 2; ++dp) {
                int vr = win * 128 + h * 32 + dp * 16 + ((lane >> 4) << 3) + (lane & 7);
                int ch = k2 * 2 + ((lane >> 3) & 1);
                u32 off = (u32)vr * 128 + (u32)(((ch ^ (vr & 7)) & 7) << 4);
                u32 r4[4];
                ldm4(r4, sb + OFF_VTHI + off);
                bvh[2*dp][0] = r4[0]; bvh[2*dp][1] = r4[1];
                bvh[2*dp+1][0] = r4[2]; bvh[2*dp+1][1] = r4[3];
            }
            #pragma unroll
            for (int nt = 0; nt < 4; ++nt)
                #pragma unroll
                for (int m = 0; m < 2; ++m) {
                    mma16816h(o[m][nt], ph[m][k2], bvh[nt][0], bvh[nt][1]);
                    mma16816h(o[m][nt], pl[m][k2], bvh[nt][0], bvh[nt][1]);
                }
        }

        // write O as SINGLE fp16 into proj-A layout (1-pass proj)
        #pragma unroll
        for (int m = 0; m < 2; ++m) {
            const int mt = mp * 2 + m;
            #pragma unroll
            for (int nt = 0; nt < 4; ++nt)
                #pragma unroll
                for (int rh = 0; rh < 2; ++rh) {
                    int r = win * 64 + mt * 16 + g + rh * 8;
                    int col = h * 32 + nt * 8 + 2 * t;
                    u32 byte = (u32)r * 256 + sw16(col >> 3, r) * 16 + (col & 7) * 2;
                    *(u32*)(sm + OFF_PHI + byte) = pkh_f16(o[m][nt][rh*2], o[m][nt][rh*2+1]);
                }
        }
    }
    __syncthreads();   // sync #4

    // ======== proj GEMM: fp16 SINGLE-pass ========
    float pacc[2][4][4];
    #pragma unroll
    for (int mt = 0; mt < 2; ++mt)
        #pragma unroll
        for (int nt = 0; nt < 4; ++nt)
            #pragma unroll
            for (int e = 0; e < 4; ++e) pacc[mt][nt][e] = 0.f;

    #pragma unroll 1
    for (int kh = 0; kh < 2; ++kh) {
        const unsigned char* base = g_wp + (size_t)kh * 16384;
        #pragma unroll
        for (int ks = 0; ks < 4; ++ks) {
            u32 b0[4], b1[4];
            ldgB(b0, b1, base, ng, ks, lane);
            int ch = kh * 8 + ks * 2 + achsel;
            u32 ah[2][4];
            ldm4(ah[0], sb + OFF_PHI + (u32)arow0 * 256 + sw16(ch, arow0) * 16);
            ldm4(ah[1], sb + OFF_PHI + (u32)arow1 * 256 + sw16(ch, arow1) * 16);
            #pragma unroll
            for (int mt = 0; mt < 2; ++mt)
                #pragma unroll
                for (int nt = 0; nt < 4; ++nt)
                    mma16816h(pacc[mt][nt], ah[mt], b0[nt], b1[nt]);
        }
    }

    // proj epilogue -> gmem (+bias)
    {
        int rb = mg * 32 + (lane >> 2);
        int cb = ng * 32 + (lane & 3) * 2;
        #pragma unroll
        for (int mt = 0; mt < 2; ++mt)
            #pragma unroll
            for (int rh = 0; rh < 2; ++rh) {
                int r = rb + mt * 16 + rh * 8;
                int win = r >> 6, nr = r & 63;
                if (nr < 49) {
                    float* go = out + ((size_t)(2*b + win) * 49 + nr) * 128;
                    #pragma unroll
                    for (int nt = 0; nt < 4; ++nt) {
                        int cc = cb + nt * 8;
                        float v0 = pacc[mt][nt][rh*2]   + __ldg(proj_b + cc);
                        float v1 = pacc[mt][nt][rh*2+1] + __ldg(proj_b + cc + 1);
                        *(float2*)(go + cc) = make_float2(v0, v1);
                    }
                }
            }
    }
}

extern "C" void kernel_launch(void* const* d_in, const int* in_sizes, int n_in,
                              void* d_out, int out_size)
{
    const float* x      = (const float*)d_in[0];
    const float* mask   = (const float*)d_in[1];
    const float* qkv_w  = (const float*)d_in[2];
    const float* qkv_b  = (const float*)d_in[3];
    const float* proj_w = (const float*)d_in[4];
    const float* proj_b = (const float*)d_in[5];
    const float* table  = (const float*)d_in[6];
    const int*   relidx = (const int*)d_in[7];
    float*       out    = (float*)d_out;

    const int B  = in_sizes[0] / (49 * 128);
    const int nW = in_sizes[1] / (49 * 49);

    prep_all<<<2840, 256>>>(qkv_w, proj_w, mask, table, relidx, nW);

    cudaFuncSetAttribute(win_attn_fa8,
                         cudaFuncAttributeMaxDynamicSharedMemorySize, SMEM_BYTES);
    win_attn_fa8<<<B / 2, 512, SMEM_BYTES>>>(x, qkv_b, proj_b, out, nW);
}

// round 15
// speedup vs baseline: 1.7569x; 1.1219x over previous
#include <cuda_runtime.h>
#include <cuda_fp16.h>
#include <cstdint>

typedef unsigned int u32;

#define QSCALE 0.17677669529663687f

// ---- smem byte offsets (1 window per CTA, 94208 B -> 2 CTAs/SM) ----
#define OFF_QHI   0         /* Q fp16 hi  [64 rows][256B]  */
#define OFF_QLO   16384
#define OFF_KHI   32768     /* K fp16 hi  [56 rows][256B]  */
#define OFF_KLO   47104
#define OFF_AFHI  61440     /* A hi [64 rows][256B] (VT alias) */
#define OFF_AFLO  77824
#define OFF_VTHI  61440     /* VT fp16 [128 rows][128B]    */
#define OFF_PHI   0         /* proj A' single fp16 (alias Q hi) */
#define SMEM_BYTES 94208

// fp16 weight fragment pieces, v4-packed (direct LDG at mma time)
__device__ __align__(16) unsigned char g_wq[163840];
__device__ __align__(16) unsigned char g_wp[32768];
__device__ __align__(16) float g_bm[702464];

__device__ __forceinline__ u32 sw16(int ch, int r) {
    return (u32)((ch & 8) | ((ch ^ (r & 7)) & 7));
}

// ---------------- prep kernel (unchanged layout) ----------------
__global__ void prep_all(const float* __restrict__ qkv_w,
                         const float* __restrict__ proj_w,
                         const float* __restrict__ mask,
                         const float* __restrict__ bias_table,
                         const int*   __restrict__ rel_index,
                         int nW) {
    int e = blockIdx.x * 256 + threadIdx.x;
    if (e < 24576) {
        int piece = e >> 11;
        int rem = e & 2047;
        int lane = rem & 31, ks = (rem >> 5) & 3, nt = rem >> 7;
        const float* W;
        unsigned char* dst;
        int ldw, nbase, kh, part;
        if (piece < 8) {
            W = qkv_w; ldw = 384;
            nbase = (piece >> 2) * 128;
            kh = (piece >> 1) & 1;
            part = piece & 1;
            dst = g_wq + (size_t)piece * 16384;
        } else if (piece < 10) {
            W = qkv_w; ldw = 384;
            nbase = 256;
            kh = piece - 8;
            part = 0;
            dst = g_wq + (size_t)piece * 16384;
        } else {
            W = proj_w; ldw = 128;
            nbase = 0;
            kh = piece - 10;
            part = 0;
            dst = g_wp + (size_t)(piece - 10) * 16384;
        }
        int k0 = kh * 64 + ks * 16 + (lane & 3) * 2;
        int n  = nbase + nt * 8 + (lane >> 2);
        float v0 = W[k0 * ldw + n],       v1 = W[(k0 + 1) * ldw + n];
        float v2 = W[(k0 + 8) * ldw + n], v3 = W[(k0 + 9) * ldw + n];
        __half h0 = __float2half_rn(v0), h1 = __float2half_rn(v1);
        __half h2 = __float2half_rn(v2), h3 = __float2half_rn(v3);
        __half2 r0, r1;
        if (part == 0) {
            r0 = __halves2half2(h0, h1);
            r1 = __halves2half2(h2, h3);
        } else {
            r0 = __halves2half2(__float2half_rn(v0 - __half2float(h0)),
                                __float2half_rn(v1 - __half2float(h1)));
            r1 = __halves2half2(__float2half_rn(v2 - __half2float(h2)),
                                __float2half_rn(v3 - __half2float(h3)));
        }
        int ng = nt >> 2, ntp = (nt >> 1) & 1, half = nt & 1;
        u32 off = (u32)((((ng * 2 + ntp) * 4 + ks) * 32 + lane) * 16 + half * 8);
        *(__half2*)(dst + off)     = r0;
        *(__half2*)(dst + off + 4) = r1;
    } else {
        int idx = e - 24576;
        if (idx < 702464) {
            int w = idx / 10976;
            int r = idx % 10976;
            int h = r / 2744;
            int r2 = r % 2744;
            int i = r2 / 56, j = r2 % 56;
            float val = 0.f;
            if (j < 49 && w < nW)
                val = bias_table[rel_index[i * 49 + j] * 4 + h] + mask[w * 2401 + i * 49 + j];
            g_bm[idx] = val;
        }
    }
}

// ---------------- PTX helpers ----------------
__device__ __forceinline__ void ldm4(u32 r[4], u32 addr) {
    asm volatile("ldmatrix.sync.aligned.m8n8.x4.shared.b16 {%0,%1,%2,%3}, [%4];"
        : "=r"(r[0]), "=r"(r[1]), "=r"(r[2]), "=r"(r[3]) : "r"(addr));
}
__device__ __forceinline__ void ldm2(u32 r[2], u32 addr) {
    asm volatile("ldmatrix.sync.aligned.m8n8.x2.shared.b16 {%0,%1}, [%2];"
        : "=r"(r[0]), "=r"(r[1]) : "r"(addr));
}
__device__ __forceinline__ void mma16816h(float c[4], const u32 a[4], u32 b0, u32 b1) {
    asm volatile("mma.sync.aligned.m16n8k16.row.col.f32.f16.f16.f32 "
        "{%0,%1,%2,%3}, {%4,%5,%6,%7}, {%8,%9}, {%0,%1,%2,%3};"
        : "+f"(c[0]), "+f"(c[1]), "+f"(c[2]), "+f"(c[3])
        : "r"(a[0]), "r"(a[1]), "r"(a[2]), "r"(a[3]), "r"(b0), "r"(b1));
}
__device__ __forceinline__ u32 pkh_f16(float a, float b) {
    u32 r;
    asm("cvt.rn.f16x2.f32 %0, %1, %2;" : "=r"(r) : "f"(b), "f"(a));
    return r;
}
__device__ __forceinline__ u32 pkl_f16(float a, float b, u32 h) {
    float ah, bh;
    asm("{\n\t.reg .b16 x,y;\n\tmov.b32 {x,y}, %2;\n\t"
        "cvt.f32.f16 %0, x;\n\tcvt.f32.f16 %1, y;\n\t}"
        : "=f"(ah), "=f"(bh) : "r"(h));
    return pkh_f16(a - ah, b - bh);
}
__device__ __forceinline__ void ldgB(u32 b0[4], u32 b1[4],
                                     const unsigned char* base, int ng, int ks, int lane) {
    #pragma unroll
    for (int ntp = 0; ntp < 2; ++ntp) {
        const uint4* p = (const uint4*)(base + (u32)((((ng * 2 + ntp) * 4 + ks) * 32 + lane) * 16));
        uint4 v = __ldg(p);
        b0[2*ntp] = v.x; b1[2*ntp] = v.y; b0[2*ntp+1] = v.z; b1[2*ntp+1] = v.w;
    }
}

// ---------------- main kernel: 1 window/CTA, 256 threads, 2 CTAs/SM ----------------
__global__ __launch_bounds__(256, 2)
void win_attn_fa9(const float* __restrict__ x,
                  const float* __restrict__ qkv_b,
                  const float* __restrict__ proj_b,
                  float* __restrict__ out, int nW)
{
    extern __shared__ __align__(1024) unsigned char sm[];
    const u32 sb = (u32)__cvta_generic_to_shared(sm);
    const int tid = threadIdx.x, lane = tid & 31, wid = tid >> 5;
    const int b = blockIdx.x;
    const int mg = wid >> 2, ng = wid & 3;     // mg in {0,1}
    const int arow0 = mg * 32 + (lane & 7) + ((lane >> 3) & 1) * 8;
    const int arow1 = arow0 + 16;
    const int achsel = lane >> 4;

    const float* xw = x + (size_t)b * 49 * 128;

    // ---- build A hi/lo once [64 rows][K=128] ----
    {
        int row = tid >> 2, cg = tid & 3;       // row 0..63
        float xv[32];
        if (row < 49) {
            const float4* src = (const float4*)(xw + (size_t)row * 128 + cg * 32);
            #pragma unroll
            for (int q = 0; q < 8; ++q) {
                float4 t = src[q];
                xv[4*q] = t.x; xv[4*q+1] = t.y; xv[4*q+2] = t.z; xv[4*q+3] = t.w;
            }
        } else {
            #pragma unroll
            for (int q = 0; q < 32; ++q) xv[q] = 0.f;
        }
        #pragma unroll
        for (int h = 0; h < 4; ++h) {
            u32 hi[4], lo[4];
            #pragma unroll
            for (int p = 0; p < 4; ++p) {
                float a = xv[h*8 + 2*p], bb = xv[h*8 + 2*p + 1];
                hi[p] = pkh_f16(a, bb);
                lo[p] = pkl_f16(a, bb, hi[p]);
            }
            int ch = cg * 4 + h;
            u32 off = (u32)row * 256 + sw16(ch, row) * 16;
            *(uint4*)(sm + OFF_AFHI + off) = make_uint4(hi[0], hi[1], hi[2], hi[3]);
            *(uint4*)(sm + OFF_AFLO + off) = make_uint4(lo[0], lo[1], lo[2], lo[3]);
        }
    }
    __syncthreads();   // sync #1

    // ======== FUSED q+k GEMM: fp16 3-pass ========
    {
        float accQ[2][4][4], accK[2][4][4];
        #pragma unroll
        for (int mt = 0; mt < 2; ++mt)
            #pragma unroll
            for (int nt = 0; nt < 4; ++nt)
                #pragma unroll
                for (int e = 0; e < 4; ++e) { accQ[mt][nt][e] = 0.f; accK[mt][nt][e] = 0.f; }

        #pragma unroll 1
        for (int kh = 0; kh < 2; ++kh) {
            const unsigned char* bq_hi = g_wq + (size_t)(kh * 2) * 16384;
            const unsigned char* bq_lo = bq_hi + 16384;
            const unsigned char* bk_hi = g_wq + (size_t)(4 + kh * 2) * 16384;
            const unsigned char* bk_lo = bk_hi + 16384;
            #pragma unroll
            for (int ks = 0; ks < 4; ++ks) {
                int ch = kh * 8 + ks * 2 + achsel;
                u32 off0 = (u32)arow0 * 256 + sw16(ch, arow0) * 16;
                u32 off1 = (u32)arow1 * 256 + sw16(ch, arow1) * 16;
                u32 ah[2][4], al[2][4];
                ldm4(ah[0], sb + OFF_AFHI + off0);
                ldm4(ah[1], sb + OFF_AFHI + off1);
                ldm4(al[0], sb + OFF_AFLO + off0);
                ldm4(al[1], sb + OFF_AFLO + off1);
                {
                    u32 bh0[4], bh1[4], bl0[4], bl1[4];
                    ldgB(bh0, bh1, bq_hi, ng, ks, lane);
                    ldgB(bl0, bl1, bq_lo, ng, ks, lane);
                    #pragma unroll
                    for (int mt = 0; mt < 2; ++mt)
                        #pragma unroll
                        for (int nt = 0; nt < 4; ++nt) {
                            mma16816h(accQ[mt][nt], ah[mt], bh0[nt], bh1[nt]);
                            mma16816h(accQ[mt][nt], al[mt], bh0[nt], bh1[nt]);
                            mma16816h(accQ[mt][nt], ah[mt], bl0[nt], bl1[nt]);
                        }
                }
                {
                    u32 bh0[4], bh1[4], bl0[4], bl1[4];
                    ldgB(bh0, bh1, bk_hi, ng, ks, lane);
                    ldgB(bl0, bl1, bk_lo, ng, ks, lane);
                    #pragma unroll
                    for (int mt = 0; mt < 2; ++mt)
                        #pragma unroll
                        for (int nt = 0; nt < 4; ++nt) {
                            mma16816h(accK[mt][nt], ah[mt], bh0[nt], bh1[nt]);
                            mma16816h(accK[mt][nt], al[mt], bh0[nt], bh1[nt]);
                            mma16816h(accK[mt][nt], ah[mt], bl0[nt], bl1[nt]);
                        }
                }
            }
        }

        // epilogue: Q and K as fp16 hi/lo
        {
            int rb = mg * 32 + (lane >> 2);
            int cb = ng * 32 + (lane & 3) * 2;
            #pragma unroll
            for (int mt = 0; mt < 2; ++mt)
                #pragma unroll
                for (int rh = 0; rh < 2; ++rh) {
                    int r = rb + mt * 16 + rh * 8;     // 0..63
                    bool ok = r < 49;
                    #pragma unroll
                    for (int nt = 0; nt < 4; ++nt) {
                        int cc = cb + nt * 8;
                        {   // Q
                            float v0 = accQ[mt][nt][rh*2]   + __ldg(qkv_b + cc);
                            float v1 = accQ[mt][nt][rh*2+1] + __ldg(qkv_b + cc + 1);
                            v0 = ok ? v0 * QSCALE : 0.f;
                            v1 = ok ? v1 * QSCALE : 0.f;
                            u32 byte = (u32)r * 256 + sw16(cc >> 3, r) * 16 + (cc & 7) * 2;
                            u32 hi = pkh_f16(v0, v1);
                            *(u32*)(sm + OFF_QHI + byte) = hi;
                            *(u32*)(sm + OFF_QLO + byte) = pkl_f16(v0, v1, hi);
                        }
                        if (r < 56) {  // K
                            float v0 = accK[mt][nt][rh*2]   + __ldg(qkv_b + 128 + cc);
                            float v1 = accK[mt][nt][rh*2+1] + __ldg(qkv_b + 128 + cc + 1);
                            v0 = ok ? v0 : 0.f; v1 = ok ? v1 : 0.f;
                            u32 byte = (u32)r * 256 + sw16(cc >> 3, r) * 16 + (cc & 7) * 2;
                            u32 hi = pkh_f16(v0, v1);
                            *(u32*)(sm + OFF_KHI + byte) = hi;
                            *(u32*)(sm + OFF_KLO + byte) = pkl_f16(v0, v1, hi);
                        }
                    }
                }
        }
    }

    // ======== v chunk: fp16 2-pass ========
    {
        float acc[2][4][4];
        #pragma unroll
        for (int mt = 0; mt < 2; ++mt)
            #pragma unroll
            for (int nt = 0; nt < 4; ++nt)
                #pragma unroll
                for (int e = 0; e < 4; ++e) acc[mt][nt][e] = 0.f;

        #pragma unroll 1
        for (int kh = 0; kh < 2; ++kh) {
            const unsigned char* base = g_wq + (size_t)(8 + kh) * 16384;
            #pragma unroll
            for (int ks = 0; ks < 4; ++ks) {
                u32 b0[4], b1[4];
                ldgB(b0, b1, base, ng, ks, lane);
                int ch = kh * 8 + ks * 2 + achsel;
                u32 off0 = (u32)arow0 * 256 + sw16(ch, arow0) * 16;
                u32 off1 = (u32)arow1 * 256 + sw16(ch, arow1) * 16;
                u32 ah[2][4], al[2][4];
                ldm4(ah[0], sb + OFF_AFHI + off0);
                ldm4(ah[1], sb + OFF_AFHI + off1);
                ldm4(al[0], sb + OFF_AFLO + off0);
                ldm4(al[1], sb + OFF_AFLO + off1);
                #pragma unroll
                for (int mt = 0; mt < 2; ++mt)
                    #pragma unroll
                    for (int nt = 0; nt < 4; ++nt) {
                        mma16816h(acc[mt][nt], ah[mt], b0[nt], b1[nt]);
                        mma16816h(acc[mt][nt], al[mt], b0[nt], b1[nt]);
                    }
            }
        }
        __syncthreads();   // sync #2: A reads done before VT overwrite

        // epilogue: VT fp16 single [128 rows][128B]
        {
            int rb = mg * 32 + (lane >> 2);
            int cb = ng * 32 + (lane & 3) * 2;
            #pragma unroll
            for (int mt = 0; mt < 2; ++mt)
                #pragma unroll
                for (int rh = 0; rh < 2; ++rh) {
                    int r = rb + mt * 16 + rh * 8;
                    bool ok = r < 49;
                    #pragma unroll
                    for (int nt = 0; nt < 4; ++nt) {
                        int cc = cb + nt * 8;
                        float v0 = acc[mt][nt][rh*2]   + __ldg(qkv_b + 256 + cc);
                        float v1 = acc[mt][nt][rh*2+1] + __ldg(qkv_b + 256 + cc + 1);
                        v0 = ok ? v0 : 0.f; v1 = ok ? v1 : 0.f;
                        #pragma unroll
                        for (int e = 0; e < 2; ++e) {
                            float vv = e ? v1 : v0;
                            int vr = cc + e;               // 0..127
                            u32 byte = (u32)vr * 128
                                     + (u32)((((r >> 3) ^ (vr & 7)) & 7) << 4)
                                     + (r & 7) * 2;
                            *(__half*)(sm + OFF_VTHI + byte) = __float2half_rn(vv);
                        }
                    }
                }
        }
    }
    __syncthreads();   // sync #3

    // ======== attention: warp = (head, m-pair); 8 warps ========
    {
        const int h = wid >> 1, mp = wid & 1;
        const int g = lane >> 2, t = lane & 3;
        const float* bm = g_bm + ((size_t)(b % nW) * 4 + h) * 2744;

        float s[2][7][4];
        #pragma unroll
        for (int m = 0; m < 2; ++m)
            #pragma unroll
            for (int nt = 0; nt < 7; ++nt)
                #pragma unroll
                for (int e = 0; e < 4; ++e) s[m][nt][e] = 0.f;

        #pragma unroll
        for (int ks = 0; ks < 2; ++ks) {
            u32 aqh[2][4], aql[2][4];
            #pragma unroll
            for (int m = 0; m < 2; ++m) {
                int mt = mp * 2 + m;
                int rr = mt * 16 + (lane & 7) + ((lane >> 3) & 1) * 8;
                int ch = h * 4 + ks * 2 + (lane >> 4);
                u32 off = (u32)rr * 256 + sw16(ch, rr) * 16;
                ldm4(aqh[m], sb + OFF_QHI + off);
                ldm4(aql[m], sb + OFF_QLO + off);
            }
            u32 bkh[7][2], bkl[7][2];
            #pragma unroll
            for (int ntp = 0; ntp < 3; ++ntp) {
                int kr = ntp * 16 + ((lane >> 4) << 3) + (lane & 7);
                int ch = h * 4 + ks * 2 + ((lane >> 3) & 1);
                u32 off = (u32)kr * 256 + sw16(ch, kr) * 16;
                u32 r4[4];
                ldm4(r4, sb + OFF_KHI + off);
                bkh[2*ntp][0] = r4[0]; bkh[2*ntp][1] = r4[1];
                bkh[2*ntp+1][0] = r4[2]; bkh[2*ntp+1][1] = r4[3];
                ldm4(r4, sb + OFF_KLO + off);
                bkl[2*ntp][0] = r4[0]; bkl[2*ntp][1] = r4[1];
                bkl[2*ntp+1][0] = r4[2]; bkl[2*ntp+1][1] = r4[3];
            }
            {
                int kr = 48 + (lane & 7);
                int ch = h * 4 + ks * 2 + ((lane >> 3) & 1);
                u32 off = (u32)kr * 256 + sw16(ch, kr) * 16;
                ldm2(bkh[6], sb + OFF_KHI + off);
                ldm2(bkl[6], sb + OFF_KLO + off);
            }
            #pragma unroll
            for (int nt = 0; nt < 7; ++nt)
                #pragma unroll
                for (int m = 0; m < 2; ++m) {
                    mma16816h(s[m][nt], aqh[m], bkh[nt][0], bkh[nt][1]);
                    mma16816h(s[m][nt], aql[m], bkh[nt][0], bkh[nt][1]);
                    mma16816h(s[m][nt], aqh[m], bkl[nt][0], bkl[nt][1]);
                }
        }

        // softmax + pack P fp16 hi/lo
        u32 ph[2][4][4], pl[2][4][4];
        #pragma unroll
        for (int m = 0; m < 2; ++m) {
            const int mt = mp * 2 + m;
            int i0 = mt * 16 + g;
            int o0 = min(i0, 48) * 56, o1 = min(i0 + 8, 48) * 56;
            #pragma unroll
            for (int nt = 0; nt < 7; ++nt) {
                int jj = nt * 8 + 2 * t;
                float2 b0 = *(const float2*)(bm + o0 + jj);
                float2 b1 = *(const float2*)(bm + o1 + jj);
                s[m][nt][0] = (jj     < 49) ? s[m][nt][0] + b0.x : -1e30f;
                s[m][nt][1] = (jj + 1 < 49) ? s[m][nt][1] + b0.y : -1e30f;
                s[m][nt][2] = (jj     < 49) ? s[m][nt][2] + b1.x : -1e30f;
                s[m][nt][3] = (jj + 1 < 49) ? s[m][nt][3] + b1.y : -1e30f;
            }
            float m0 = -1e30f, m1 = -1e30f;
            #pragma unroll
            for (int nt = 0; nt < 7; ++nt) {
                m0 = fmaxf(m0, fmaxf(s[m][nt][0], s[m][nt][1]));
                m1 = fmaxf(m1, fmaxf(s[m][nt][2], s[m][nt][3]));
            }
            m0 = fmaxf(m0, __shfl_xor_sync(0xffffffffu, m0, 1));
            m1 = fmaxf(m1, __shfl_xor_sync(0xffffffffu, m1, 1));
            m0 = fmaxf(m0, __shfl_xor_sync(0xffffffffu, m0, 2));
            m1 = fmaxf(m1, __shfl_xor_sync(0xffffffffu, m1, 2));
            float s0 = 0.f, s1 = 0.f;
            #pragma unroll
            for (int nt = 0; nt < 7; ++nt) {
                s[m][nt][0] = __expf(s[m][nt][0] - m0); s0 += s[m][nt][0];
                s[m][nt][1] = __expf(s[m][nt][1] - m0); s0 += s[m][nt][1];
                s[m][nt][2] = __expf(s[m][nt][2] - m1); s1 += s[m][nt][2];
                s[m][nt][3] = __expf(s[m][nt][3] - m1); s1 += s[m][nt][3];
            }
            s0 += __shfl_xor_sync(0xffffffffu, s0, 1);
            s1 += __shfl_xor_sync(0xffffffffu, s1, 1);
            s0 += __shfl_xor_sync(0xffffffffu, s0, 2);
            s1 += __shfl_xor_sync(0xffffffffu, s1, 2);
            float i0v = 1.f / s0, i1v = 1.f / s1;
            #pragma unroll
            for (int nt = 0; nt < 7; ++nt) {
                s[m][nt][0] *= i0v; s[m][nt][1] *= i0v;
                s[m][nt][2] *= i1v; s[m][nt][3] *= i1v;
            }
            #pragma unroll
            for (int k2 = 0; k2 < 4; ++k2) {
                int na = 2 * k2, nb = 2 * k2 + 1;
                ph[m][k2][0] = pkh_f16(s[m][na][0], s[m][na][1]);
                pl[m][k2][0] = pkl_f16(s[m][na][0], s[m][na][1], ph[m][k2][0]);
                ph[m][k2][1] = pkh_f16(s[m][na][2], s[m][na][3]);
                pl[m][k2][1] = pkl_f16(s[m][na][2], s[m][na][3], ph[m][k2][1]);
                if (nb < 7) {
                    ph[m][k2][2] = pkh_f16(s[m][nb][0], s[m][nb][1]);
                    pl[m][k2][2] = pkl_f16(s[m][nb][0], s[m][nb][1], ph[m][k2][2]);
                    ph[m][k2][3] = pkh_f16(s[m][nb][2], s[m][nb][3]);
                    pl[m][k2][3] = pkl_f16(s[m][nb][2], s[m][nb][3], ph[m][k2][3]);
                } else {
                    ph[m][k2][2] = ph[m][k2][3] = pl[m][k2][2] = pl[m][k2][3] = 0u;
                }
            }
        }

        // O = P @ V (fp16 2-pass)
        float o[2][4][4];
        #pragma unroll
        for (int m = 0; m < 2; ++m)
            #pragma unroll
            for (int nt = 0; nt < 4; ++nt)
                #pragma unroll
                for (int e = 0; e < 4; ++e) o[m][nt][e] = 0.f;
        #pragma unroll
        for (int k2 = 0; k2 < 4; ++k2) {
            u32 bvh[4][2];
            #pragma unroll
            for (int dp = 0; dp < 2; ++dp) {
                int vr = h * 32 + dp * 16 + ((lane >> 4) << 3) + (lane & 7);
                int ch = k2 * 2 + ((lane >> 3) & 1);
                u32 off = (u32)vr * 128 + (u32)(((ch ^ (vr & 7)) & 7) << 4);
                u32 r4[4];
                ldm4(r4, sb + OFF_VTHI + off);
                bvh[2*dp][0] = r4[0]; bvh[2*dp][1] = r4[1];
                bvh[2*dp+1][0] = r4[2]; bvh[2*dp+1][1] = r4[3];
            }
            #pragma unroll
            for (int nt = 0; nt < 4; ++nt)
                #pragma unroll
                for (int m = 0; m < 2; ++m) {
                    mma16816h(o[m][nt], ph[m][k2], bvh[nt][0], bvh[nt][1]);
                    mma16816h(o[m][nt], pl[m][k2], bvh[nt][0], bvh[nt][1]);
                }
        }

        // write O as SINGLE fp16 into proj-A layout
        #pragma unroll
        for (int m = 0; m < 2; ++m) {
            const int mt = mp * 2 + m;
            #pragma unroll
            for (int nt = 0; nt < 4; ++nt)
                #pragma unroll
                for (int rh = 0; rh < 2; ++rh) {
                    int r = mt * 16 + g + rh * 8;
                    int col = h * 32 + nt * 8 + 2 * t;
                    u32 byte = (u32)r * 256 + sw16(col >> 3, r) * 16 + (col & 7) * 2;
                    *(u32*)(sm + OFF_PHI + byte) = pkh_f16(o[m][nt][rh*2], o[m][nt][rh*2+1]);
                }
        }
    }
    __syncthreads();   // sync #4

    // ======== proj GEMM: fp16 single-pass ========
    float pacc[2][4][4];
    #pragma unroll
    for (int mt = 0; mt < 2; ++mt)
        #pragma unroll
        for (int nt = 0; nt < 4; ++nt)
            #pragma unroll
            for (int e = 0; e < 4; ++e) pacc[mt][nt][e] = 0.f;

    #pragma unroll 1
    for (int kh = 0; kh < 2; ++kh) {
        const unsigned char* base = g_wp + (size_t)kh * 16384;
        #pragma unroll
        for (int ks = 0; ks < 4; ++ks) {
            u32 b0[4], b1[4];
            ldgB(b0, b1, base, ng, ks, lane);
            int ch = kh * 8 + ks * 2 + achsel;
            u32 ah[2][4];
            ldm4(ah[0], sb + OFF_PHI + (u32)arow0 * 256 + sw16(ch, arow0) * 16);
            ldm4(ah[1], sb + OFF_PHI + (u32)arow1 * 256 + sw16(ch, arow1) * 16);
            #pragma unroll
            for (int mt = 0; mt < 2; ++mt)
                #pragma unroll
                for (int nt = 0; nt < 4; ++nt)
                    mma16816h(pacc[mt][nt], ah[mt], b0[nt], b1[nt]);
        }
    }

    // proj epilogue -> gmem (+bias)
    {
        int rb = mg * 32 + (lane >> 2);
        int cb = ng * 32 + (lane & 3) * 2;
        #pragma unroll
        for (int mt = 0; mt < 2; ++mt)
            #pragma unroll
            for (int rh = 0; rh < 2; ++rh) {
                int r = rb + mt * 16 + rh * 8;
                if (r < 49) {
                    float* go = out + ((size_t)b * 49 + r) * 128;
                    #pragma unroll
                    for (int nt = 0; nt < 4; ++nt) {
                        int cc = cb + nt * 8;
                        float v0 = pacc[mt][nt][rh*2]   + __ldg(proj_b + cc);
                        float v1 = pacc[mt][nt][rh*2+1] + __ldg(proj_b + cc + 1);
                        *(float2*)(go + cc) = make_float2(v0, v1);
                    }
                }
            }
    }
}

extern "C" void kernel_launch(void* const* d_in, const int* in_sizes, int n_in,
                              void* d_out, int out_size)
{
    const float* x      = (const float*)d_in[0];
    const float* mask   = (const float*)d_in[1];
    const float* qkv_w  = (const float*)d_in[2];
    const float* qkv_b  = (const float*)d_in[3];
    const float* proj_w = (const float*)d_in[4];
    const float* proj_b = (const float*)d_in[5];
    const float* table  = (const float*)d_in[6];
    const int*   relidx = (const int*)d_in[7];
    float*       out    = (float*)d_out;

    const int B  = in_sizes[0] / (49 * 128);
    const int nW = in_sizes[1] / (49 * 49);

    prep_all<<<2840, 256>>>(qkv_w, proj_w, mask, table, relidx, nW);

    cudaFuncSetAttribute(win_attn_fa9,
                         cudaFuncAttributeMaxDynamicSharedMemorySize, SMEM_BYTES);
    win_attn_fa9<<<B, 256, SMEM_BYTES>>>(x, qkv_b, proj_b, out, nW);
}

// round 16
// speedup vs baseline: 1.9286x; 1.0977x over previous
#include <cuda_runtime.h>
#include <cuda_fp16.h>
#include <cstdint>

typedef unsigned int u32;

#define QSCALE 0.17677669529663687f

// ---- smem byte offsets (1 window per CTA, 94208 B -> 2 CTAs/SM) ----
#define OFF_QHI   0         /* Q fp16 hi  [64 rows][256B]  */
#define OFF_QLO   16384
#define OFF_KHI   32768     /* K fp16 hi  [56 rows][256B]  */
#define OFF_KLO   47104
#define OFF_AFHI  61440     /* A hi [64 rows][256B] (VT alias) */
#define OFF_AFLO  77824
#define OFF_VTHI  61440     /* VT fp16 [128 rows][128B]    */
#define OFF_PHI   0         /* proj A' single fp16 (alias Q hi) */
#define SMEM_BYTES 94208

// fp16 weight fragment pieces, v4-packed (direct LDG at mma time)
__device__ __align__(16) unsigned char g_wq[163840];
__device__ __align__(16) unsigned char g_wp[32768];
__device__ __align__(16) float g_bm[702464];

__device__ __forceinline__ u32 sw16(int ch, int r) {
    return (u32)((ch & 8) | ((ch ^ (r & 7)) & 7));
}

// ---------------- prep kernel (unchanged layout) ----------------
__global__ void prep_all(const float* __restrict__ qkv_w,
                         const float* __restrict__ proj_w,
                         const float* __restrict__ mask,
                         const float* __restrict__ bias_table,
                         const int*   __restrict__ rel_index,
                         int nW) {
    int e = blockIdx.x * 256 + threadIdx.x;
    if (e < 24576) {
        int piece = e >> 11;
        int rem = e & 2047;
        int lane = rem & 31, ks = (rem >> 5) & 3, nt = rem >> 7;
        const float* W;
        unsigned char* dst;
        int ldw, nbase, kh, part;
        if (piece < 8) {
            W = qkv_w; ldw = 384;
            nbase = (piece >> 2) * 128;
            kh = (piece >> 1) & 1;
            part = piece & 1;
            dst = g_wq + (size_t)piece * 16384;
        } else if (piece < 10) {
            W = qkv_w; ldw = 384;
            nbase = 256;
            kh = piece - 8;
            part = 0;
            dst = g_wq + (size_t)piece * 16384;
        } else {
            W = proj_w; ldw = 128;
            nbase = 0;
            kh = piece - 10;
            part = 0;
            dst = g_wp + (size_t)(piece - 10) * 16384;
        }
        int k0 = kh * 64 + ks * 16 + (lane & 3) * 2;
        int n  = nbase + nt * 8 + (lane >> 2);
        float v0 = W[k0 * ldw + n],       v1 = W[(k0 + 1) * ldw + n];
        float v2 = W[(k0 + 8) * ldw + n], v3 = W[(k0 + 9) * ldw + n];
        __half h0 = __float2half_rn(v0), h1 = __float2half_rn(v1);
        __half h2 = __float2half_rn(v2), h3 = __float2half_rn(v3);
        __half2 r0, r1;
        if (part == 0) {
            r0 = __halves2half2(h0, h1);
            r1 = __halves2half2(h2, h3);
        } else {
            r0 = __halves2half2(__float2half_rn(v0 - __half2float(h0)),
                                __float2half_rn(v1 - __half2float(h1)));
            r1 = __halves2half2(__float2half_rn(v2 - __half2float(h2)),
                                __float2half_rn(v3 - __half2float(h3)));
        }
        int ng = nt >> 2, ntp = (nt >> 1) & 1, half = nt & 1;
        u32 off = (u32)((((ng * 2 + ntp) * 4 + ks) * 32 + lane) * 16 + half * 8);
        *(__half2*)(dst + off)     = r0;
        *(__half2*)(dst + off + 4) = r1;
    } else {
        int idx = e - 24576;
        if (idx < 702464) {
            int w = idx / 10976;
            int r = idx % 10976;
            int h = r / 2744;
            int r2 = r % 2744;
            int i = r2 / 56, j = r2 % 56;
            float val = 0.f;
            if (j < 49 && w < nW)
                val = bias_table[rel_index[i * 49 + j] * 4 + h] + mask[w * 2401 + i * 49 + j];
            g_bm[idx] = val;
        }
    }
}

// ---------------- PTX helpers ----------------
__device__ __forceinline__ void ldm4(u32 r[4], u32 addr) {
    asm volatile("ldmatrix.sync.aligned.m8n8.x4.shared.b16 {%0,%1,%2,%3}, [%4];"
        : "=r"(r[0]), "=r"(r[1]), "=r"(r[2]), "=r"(r[3]) : "r"(addr));
}
__device__ __forceinline__ void ldm2(u32 r[2], u32 addr) {
    asm volatile("ldmatrix.sync.aligned.m8n8.x2.shared.b16 {%0,%1}, [%2];"
        : "=r"(r[0]), "=r"(r[1]) : "r"(addr));
}
__device__ __forceinline__ void mma16816h(float c[4], const u32 a[4], u32 b0, u32 b1) {
    asm volatile("mma.sync.aligned.m16n8k16.row.col.f32.f16.f16.f32 "
        "{%0,%1,%2,%3}, {%4,%5,%6,%7}, {%8,%9}, {%0,%1,%2,%3};"
        : "+f"(c[0]), "+f"(c[1]), "+f"(c[2]), "+f"(c[3])
        : "r"(a[0]), "r"(a[1]), "r"(a[2]), "r"(a[3]), "r"(b0), "r"(b1));
}
__device__ __forceinline__ u32 pkh_f16(float a, float b) {
    u32 r;
    asm("cvt.rn.f16x2.f32 %0, %1, %2;" : "=r"(r) : "f"(b), "f"(a));
    return r;
}
__device__ __forceinline__ u32 pkl_f16(float a, float b, u32 h) {
    float ah, bh;
    asm("{\n\t.reg .b16 x,y;\n\tmov.b32 {x,y}, %2;\n\t"
        "cvt.f32.f16 %0, x;\n\tcvt.f32.f16 %1, y;\n\t}"
        : "=f"(ah), "=f"(bh) : "r"(h));
    return pkh_f16(a - ah, b - bh);
}
__device__ __forceinline__ void ldgB(u32 b0[4], u32 b1[4],
                                     const unsigned char* base, int ng, int ks, int lane) {
    #pragma unroll
    for (int ntp = 0; ntp < 2; ++ntp) {
        const uint4* p = (const uint4*)(base + (u32)((((ng * 2 + ntp) * 4 + ks) * 32 + lane) * 16));
        uint4 v = __ldg(p);
        b0[2*ntp] = v.x; b1[2*ntp] = v.y; b0[2*ntp+1] = v.z; b1[2*ntp+1] = v.w;
    }
}

// ---------------- main kernel: 1 window/CTA, 256 threads, 2 CTAs/SM ----------------
__global__ __launch_bounds__(256, 2)
void win_attn_fa10(const float* __restrict__ x,
                   const float* __restrict__ qkv_b,
                   const float* __restrict__ proj_b,
                   float* __restrict__ out, int nW)
{
    extern __shared__ __align__(1024) unsigned char sm[];
    const u32 sb = (u32)__cvta_generic_to_shared(sm);
    const int tid = threadIdx.x, lane = tid & 31, wid = tid >> 5;
    const int b = blockIdx.x;
    const int mg = wid >> 2, ng = wid & 3;
    const int arow0 = mg * 32 + (lane & 7) + ((lane >> 3) & 1) * 8;
    const int arow1 = arow0 + 16;
    const int achsel = lane >> 4;

    const float* xw = x + (size_t)b * 49 * 128;

    // ---- build A hi/lo once [64 rows][K=128] ----
    {
        int row = tid >> 2, cg = tid & 3;
        float xv[32];
        if (row < 49) {
            const float4* src = (const float4*)(xw + (size_t)row * 128 + cg * 32);
            #pragma unroll
            for (int q = 0; q < 8; ++q) {
                float4 t = src[q];
                xv[4*q] = t.x; xv[4*q+1] = t.y; xv[4*q+2] = t.z; xv[4*q+3] = t.w;
            }
        } else {
            #pragma unroll
            for (int q = 0; q < 32; ++q) xv[q] = 0.f;
        }
        #pragma unroll
        for (int h = 0; h < 4; ++h) {
            u32 hi[4], lo[4];
            #pragma unroll
            for (int p = 0; p < 4; ++p) {
                float a = xv[h*8 + 2*p], bb = xv[h*8 + 2*p + 1];
                hi[p] = pkh_f16(a, bb);
                lo[p] = pkl_f16(a, bb, hi[p]);
            }
            int ch = cg * 4 + h;
            u32 off = (u32)row * 256 + sw16(ch, row) * 16;
            *(uint4*)(sm + OFF_AFHI + off) = make_uint4(hi[0], hi[1], hi[2], hi[3]);
            *(uint4*)(sm + OFF_AFLO + off) = make_uint4(lo[0], lo[1], lo[2], lo[3]);
        }
    }
    __syncthreads();   // sync #1

    // ======== FUSED q+k GEMM: fp16 2-pass ((A-hi + A-lo) x W-hi) ========
    {
        float accQ[2][4][4], accK[2][4][4];
        #pragma unroll
        for (int mt = 0; mt < 2; ++mt)
            #pragma unroll
            for (int nt = 0; nt < 4; ++nt)
                #pragma unroll
                for (int e = 0; e < 4; ++e) { accQ[mt][nt][e] = 0.f; accK[mt][nt][e] = 0.f; }

        #pragma unroll 1
        for (int kh = 0; kh < 2; ++kh) {
            const unsigned char* bq_hi = g_wq + (size_t)(kh * 2) * 16384;
            const unsigned char* bk_hi = g_wq + (size_t)(4 + kh * 2) * 16384;
            #pragma unroll
            for (int ks = 0; ks < 4; ++ks) {
                int ch = kh * 8 + ks * 2 + achsel;
                u32 off0 = (u32)arow0 * 256 + sw16(ch, arow0) * 16;
                u32 off1 = (u32)arow1 * 256 + sw16(ch, arow1) * 16;
                u32 ah[2][4], al[2][4];
                ldm4(ah[0], sb + OFF_AFHI + off0);
                ldm4(ah[1], sb + OFF_AFHI + off1);
                ldm4(al[0], sb + OFF_AFLO + off0);
                ldm4(al[1], sb + OFF_AFLO + off1);
                {
                    u32 bh0[4], bh1[4];
                    ldgB(bh0, bh1, bq_hi, ng, ks, lane);
                    #pragma unroll
                    for (int mt = 0; mt < 2; ++mt)
                        #pragma unroll
                        for (int nt = 0; nt < 4; ++nt) {
                            mma16816h(accQ[mt][nt], ah[mt], bh0[nt], bh1[nt]);
                            mma16816h(accQ[mt][nt], al[mt], bh0[nt], bh1[nt]);
                        }
                }
                {
                    u32 bh0[4], bh1[4];
                    ldgB(bh0, bh1, bk_hi, ng, ks, lane);
                    #pragma unroll
                    for (int mt = 0; mt < 2; ++mt)
                        #pragma unroll
                        for (int nt = 0; nt < 4; ++nt) {
                            mma16816h(accK[mt][nt], ah[mt], bh0[nt], bh1[nt]);
                            mma16816h(accK[mt][nt], al[mt], bh0[nt], bh1[nt]);
                        }
                }
            }
        }

        // epilogue: Q and K as fp16 hi/lo
        {
            int rb = mg * 32 + (lane >> 2);
            int cb = ng * 32 + (lane & 3) * 2;
            #pragma unroll
            for (int mt = 0; mt < 2; ++mt)
                #pragma unroll
                for (int rh = 0; rh < 2; ++rh) {
                    int r = rb + mt * 16 + rh * 8;
                    bool ok = r < 49;
                    #pragma unroll
                    for (int nt = 0; nt < 4; ++nt) {
                        int cc = cb + nt * 8;
                        {   // Q
                            float v0 = accQ[mt][nt][rh*2]   + __ldg(qkv_b + cc);
                            float v1 = accQ[mt][nt][rh*2+1] + __ldg(qkv_b + cc + 1);
                            v0 = ok ? v0 * QSCALE : 0.f;
                            v1 = ok ? v1 * QSCALE : 0.f;
                            u32 byte = (u32)r * 256 + sw16(cc >> 3, r) * 16 + (cc & 7) * 2;
                            u32 hi = pkh_f16(v0, v1);
                            *(u32*)(sm + OFF_QHI + byte) = hi;
                            *(u32*)(sm + OFF_QLO + byte) = pkl_f16(v0, v1, hi);
                        }
                        if (r < 56) {  // K
                            float v0 = accK[mt][nt][rh*2]   + __ldg(qkv_b + 128 + cc);
                            float v1 = accK[mt][nt][rh*2+1] + __ldg(qkv_b + 128 + cc + 1);
                            v0 = ok ? v0 : 0.f; v1 = ok ? v1 : 0.f;
                            u32 byte = (u32)r * 256 + sw16(cc >> 3, r) * 16 + (cc & 7) * 2;
                            u32 hi = pkh_f16(v0, v1);
                            *(u32*)(sm + OFF_KHI + byte) = hi;
                            *(u32*)(sm + OFF_KLO + byte) = pkl_f16(v0, v1, hi);
                        }
                    }
                }
        }
    }

    // ======== v chunk: fp16 2-pass ========
    {
        float acc[2][4][4];
        #pragma unroll
        for (int mt = 0; mt < 2; ++mt)
            #pragma unroll
            for (int nt = 0; nt < 4; ++nt)
                #pragma unroll
                for (int e = 0; e < 4; ++e) acc[mt][nt][e] = 0.f;

        #pragma unroll 1
        for (int kh = 0; kh < 2; ++kh) {
            const unsigned char* base = g_wq + (size_t)(8 + kh) * 16384;
            #pragma unroll
            for (int ks = 0; ks < 4; ++ks) {
                u32 b0[4], b1[4];
                ldgB(b0, b1, base, ng, ks, lane);
                int ch = kh * 8 + ks * 2 + achsel;
                u32 off0 = (u32)arow0 * 256 + sw16(ch, arow0) * 16;
                u32 off1 = (u32)arow1 * 256 + sw16(ch, arow1) * 16;
                u32 ah[2][4], al[2][4];
                ldm4(ah[0], sb + OFF_AFHI + off0);
                ldm4(ah[1], sb + OFF_AFHI + off1);
                ldm4(al[0], sb + OFF_AFLO + off0);
                ldm4(al[1], sb + OFF_AFLO + off1);
                #pragma unroll
                for (int mt = 0; mt < 2; ++mt)
                    #pragma unroll
                    for (int nt = 0; nt < 4; ++nt) {
                        mma16816h(acc[mt][nt], ah[mt], b0[nt], b1[nt]);
                        mma16816h(acc[mt][nt], al[mt], b0[nt], b1[nt]);
                    }
            }
        }
        __syncthreads();   // sync #2: A reads done before VT overwrite

        // epilogue: VT fp16 single [128 rows][128B]
        {
            int rb = mg * 32 + (lane >> 2);
            int cb = ng * 32 + (lane & 3) * 2;
            #pragma unroll
            for (int mt = 0; mt < 2; ++mt)
                #pragma unroll
                for (int rh = 0; rh < 2; ++rh) {
                    int r = rb + mt * 16 + rh * 8;
                    bool ok = r < 49;
                    #pragma unroll
                    for (int nt = 0; nt < 4; ++nt) {
                        int cc = cb + nt * 8;
                        float v0 = acc[mt][nt][rh*2]   + __ldg(qkv_b + 256 + cc);
                        float v1 = acc[mt][nt][rh*2+1] + __ldg(qkv_b + 256 + cc + 1);
                        v0 = ok ? v0 : 0.f; v1 = ok ? v1 : 0.f;
                        #pragma unroll
                        for (int e = 0; e < 2; ++e) {
                            float vv = e ? v1 : v0;
                            int vr = cc + e;
                            u32 byte = (u32)vr * 128
                                     + (u32)((((r >> 3) ^ (vr & 7)) & 7) << 4)
                                     + (r & 7) * 2;
                            *(__half*)(sm + OFF_VTHI + byte) = __float2half_rn(vv);
                        }
                    }
                }
        }
    }
    __syncthreads();   // sync #3

    // ======== attention: warp = (head, m-pair); 8 warps ========
    {
        const int h = wid >> 1, mp = wid & 1;
        const int g = lane >> 2, t = lane & 3;
        const float* bm = g_bm + ((size_t)(b % nW) * 4 + h) * 2744;

        float s[2][7][4];
        #pragma unroll
        for (int m = 0; m < 2; ++m)
            #pragma unroll
            for (int nt = 0; nt < 7; ++nt)
                #pragma unroll
                for (int e = 0; e < 4; ++e) s[m][nt][e] = 0.f;

        #pragma unroll
        for (int ks = 0; ks < 2; ++ks) {
            u32 aqh[2][4], aql[2][4];
            #pragma unroll
            for (int m = 0; m < 2; ++m) {
                int mt = mp * 2 + m;
                int rr = mt * 16 + (lane & 7) + ((lane >> 3) & 1) * 8;
                int ch = h * 4 + ks * 2 + (lane >> 4);
                u32 off = (u32)rr * 256 + sw16(ch, rr) * 16;
                ldm4(aqh[m], sb + OFF_QHI + off);
                ldm4(aql[m], sb + OFF_QLO + off);
            }
            u32 bkh[7][2], bkl[7][2];
            #pragma unroll
            for (int ntp = 0; ntp < 3; ++ntp) {
                int kr = ntp * 16 + ((lane >> 4) << 3) + (lane & 7);
                int ch = h * 4 + ks * 2 + ((lane >> 3) & 1);
                u32 off = (u32)kr * 256 + sw16(ch, kr) * 16;
                u32 r4[4];
                ldm4(r4, sb + OFF_KHI + off);
                bkh[2*ntp][0] = r4[0]; bkh[2*ntp][1] = r4[1];
                bkh[2*ntp+1][0] = r4[2]; bkh[2*ntp+1][1] = r4[3];
                ldm4(r4, sb + OFF_KLO + off);
                bkl[2*ntp][0] = r4[0]; bkl[2*ntp][1] = r4[1];
                bkl[2*ntp+1][0] = r4[2]; bkl[2*ntp+1][1] = r4[3];
            }
            {
                int kr = 48 + (lane & 7);
                int ch = h * 4 + ks * 2 + ((lane >> 3) & 1);
                u32 off = (u32)kr * 256 + sw16(ch, kr) * 16;
                ldm2(bkh[6], sb + OFF_KHI + off);
                ldm2(bkl[6], sb + OFF_KLO + off);
            }
            #pragma unroll
            for (int nt = 0; nt < 7; ++nt)
                #pragma unroll
                for (int m = 0; m < 2; ++m) {
                    mma16816h(s[m][nt], aqh[m], bkh[nt][0], bkh[nt][1]);
                    mma16816h(s[m][nt], aql[m], bkh[nt][0], bkh[nt][1]);
                    mma16816h(s[m][nt], aqh[m], bkl[nt][0], bkl[nt][1]);
                }
        }

        // softmax + pack P fp16 hi/lo
        u32 ph[2][4][4], pl[2][4][4];
        #pragma unroll
        for (int m = 0; m < 2; ++m) {
            const int mt = mp * 2 + m;
            int i0 = mt * 16 + g;
            int o0 = min(i0, 48) * 56, o1 = min(i0 + 8, 48) * 56;
            #pragma unroll
            for (int nt = 0; nt < 7; ++nt) {
                int jj = nt * 8 + 2 * t;
                float2 b0 = *(const float2*)(bm + o0 + jj);
                float2 b1 = *(const float2*)(bm + o1 + jj);
                s[m][nt][0] = (jj     < 49) ? s[m][nt][0] + b0.x : -1e30f;
                s[m][nt][1] = (jj + 1 < 49) ? s[m][nt][1] + b0.y : -1e30f;
                s[m][nt][2] = (jj     < 49) ? s[m][nt][2] + b1.x : -1e30f;
                s[m][nt][3] = (jj + 1 < 49) ? s[m][nt][3] + b1.y : -1e30f;
            }
            float m0 = -1e30f, m1 = -1e30f;
            #pragma unroll
            for (int nt = 0; nt < 7; ++nt) {
                m0 = fmaxf(m0, fmaxf(s[m][nt][0], s[m][nt][1]));
                m1 = fmaxf(m1, fmaxf(s[m][nt][2], s[m][nt][3]));
            }
            m0 = fmaxf(m0, __shfl_xor_sync(0xffffffffu, m0, 1));
            m1 = fmaxf(m1, __shfl_xor_sync(0xffffffffu, m1, 1));
            m0 = fmaxf(m0, __shfl_xor_sync(0xffffffffu, m0, 2));
            m1 = fmaxf(m1, __shfl_xor_sync(0xffffffffu, m1, 2));
            float s0 = 0.f, s1 = 0.f;
            #pragma unroll
            for (int nt = 0; nt < 7; ++nt) {
                s[m][nt][0] = __expf(s[m][nt][0] - m0); s0 += s[m][nt][0];
                s[m][nt][1] = __expf(s[m][nt][1] - m0); s0 += s[m][nt][1];
                s[m][nt][2] = __expf(s[m][nt][2] - m1); s1 += s[m][nt][2];
                s[m][nt][3] = __expf(s[m][nt][3] - m1); s1 += s[m][nt][3];
            }
            s0 += __shfl_xor_sync(0xffffffffu, s0, 1);
            s1 += __shfl_xor_sync(0xffffffffu, s1, 1);
            s0 += __shfl_xor_sync(0xffffffffu, s0, 2);
            s1 += __shfl_xor_sync(0xffffffffu, s1, 2);
            float i0v = 1.f / s0, i1v = 1.f / s1;
            #pragma unroll
            for (int nt = 0; nt < 7; ++nt) {
                s[m][nt][0] *= i0v; s[m][nt][1] *= i0v;
                s[m][nt][2] *= i1v; s[m][nt][3] *= i1v;
            }
            #pragma unroll
            for (int k2 = 0; k2 < 4; ++k2) {
                int na = 2 * k2, nb = 2 * k2 + 1;
                ph[m][k2][0] = pkh_f16(s[m][na][0], s[m][na][1]);
                pl[m][k2][0] = pkl_f16(s[m][na][0], s[m][na][1], ph[m][k2][0]);
                ph[m][k2][1] = pkh_f16(s[m][na][2], s[m][na][3]);
                pl[m][k2][1] = pkl_f16(s[m][na][2], s[m][na][3], ph[m][k2][1]);
                if (nb < 7) {
                    ph[m][k2][2] = pkh_f16(s[m][nb][0], s[m][nb][1]);
                    pl[m][k2][2] = pkl_f16(s[m][nb][0], s[m][nb][1], ph[m][k2][2]);
                    ph[m][k2][3] = pkh_f16(s[m][nb][2], s[m][nb][3]);
                    pl[m][k2][3] = pkl_f16(s[m][nb][2], s[m][nb][3], ph[m][k2][3]);
                } else {
                    ph[m][k2][2] = ph[m][k2][3] = pl[m][k2][2] = pl[m][k2][3] = 0u;
                }
            }
        }

        // O = P @ V (fp16 2-pass)
        float o[2][4][4];
        #pragma unroll
        for (int m = 0; m < 2; ++m)
            #pragma unroll
            for (int nt = 0; nt < 4; ++nt)
                #pragma unroll
                for (int e = 0; e < 4; ++e) o[m][nt][e] = 0.f;
        #pragma unroll
        for (int k2 = 0; k2 < 4; ++k2) {
            u32 bvh[4][2];
            #pragma unroll
            for (int dp = 0; dp < 2; ++dp) {
                int vr = h * 32 + dp * 16 + ((lane >> 4) << 3) + (lane & 7);
                int ch = k2 * 2 + ((lane >> 3) & 1);
                u32 off = (u32)vr * 128 + (u32)(((ch ^ (vr & 7)) & 7) << 4);
                u32 r4[4];
                ldm4(r4, sb + OFF_VTHI + off);
                bvh[2*dp][0] = r4[0]; bvh[2*dp][1] = r4[1];
                bvh[2*dp+1][0] = r4[2]; bvh[2*dp+1][1] = r4[3];
            }
            #pragma unroll
            for (int nt = 0; nt < 4; ++nt)
                #pragma unroll
                for (int m = 0; m < 2; ++m) {
                    mma16816h(o[m][nt], ph[m][k2], bvh[nt][0], bvh[nt][1]);
                    mma16816h(o[m][nt], pl[m][k2], bvh[nt][0], bvh[nt][1]);
                }
        }

        // write O as SINGLE fp16 into proj-A layout
        #pragma unroll
        for (int m = 0; m < 2; ++m) {
            const int mt = mp * 2 + m;
            #pragma unroll
            for (int nt = 0; nt < 4; ++nt)
                #pragma unroll
                for (int rh = 0; rh < 2; ++rh) {
                    int r = mt * 16 + g + rh * 8;
                    int col = h * 32 + nt * 8 + 2 * t;
                    u32 byte = (u32)r * 256 + sw16(col >> 3, r) * 16 + (col & 7) * 2;
                    *(u32*)(sm + OFF_PHI + byte) = pkh_f16(o[m][nt][rh*2], o[m][nt][rh*2+1]);
                }
        }
    }
    __syncthreads();   // sync #4

    // ======== proj GEMM: fp16 single-pass ========
    float pacc[2][4][4];
    #pragma unroll
    for (int mt = 0; mt < 2; ++mt)
        #pragma unroll
        for (int nt = 0; nt < 4; ++nt)
            #pragma unroll
            for (int e = 0; e < 4; ++e) pacc[mt][nt][e] = 0.f;

    #pragma unroll 1
    for (int kh = 0; kh < 2; ++kh) {
        const unsigned char* base = g_wp + (size_t)kh * 16384;
        #pragma unroll
        for (int ks = 0; ks < 4; ++ks) {
            u32 b0[4], b1[4];
            ldgB(b0, b1, base, ng, ks, lane);
            int ch = kh * 8 + ks * 2 + achsel;
            u32 ah[2][4];
            ldm4(ah[0], sb + OFF_PHI + (u32)arow0 * 256 + sw16(ch, arow0) * 16);
            ldm4(ah[1], sb + OFF_PHI + (u32)arow1 * 256 + sw16(ch, arow1) * 16);
            #pragma unroll
            for (int mt = 0; mt < 2; ++mt)
                #pragma unroll
                for (int nt = 0; nt < 4; ++nt)
                    mma16816h(pacc[mt][nt], ah[mt], b0[nt], b1[nt]);
        }
    }

    // proj epilogue -> gmem (+bias)
    {
        int rb = mg * 32 + (lane >> 2);
        int cb = ng * 32 + (lane & 3) * 2;
        #pragma unroll
        for (int mt = 0; mt < 2; ++mt)
            #pragma unroll
            for (int rh = 0; rh < 2; ++rh) {
                int r = rb + mt * 16 + rh * 8;
                if (r < 49) {
                    float* go = out + ((size_t)b * 49 + r) * 128;
                    #pragma unroll
                    for (int nt = 0; nt < 4; ++nt) {
                        int cc = cb + nt * 8;
                        float v0 = pacc[mt][nt][rh*2]   + __ldg(proj_b + cc);
                        float v1 = pacc[mt][nt][rh*2+1] + __ldg(proj_b + cc + 1);
                        *(float2*)(go + cc) = make_float2(v0, v1);
                    }
                }
            }
    }
}

extern "C" void kernel_launch(void* const* d_in, const int* in_sizes, int n_in,
                              void* d_out, int out_size)
{
    const float* x      = (const float*)d_in[0];
    const float* mask   = (const float*)d_in[1];
    const float* qkv_w  = (const float*)d_in[2];
    const float* qkv_b  = (const float*)d_in[3];
    const float* proj_w = (const float*)d_in[4];
    const float* proj_b = (const float*)d_in[5];
    const float* table  = (const float*)d_in[6];
    const int*   relidx = (const int*)d_in[7];
    float*       out    = (float*)d_out;

    const int B  = in_sizes[0] / (49 * 128);
    const int nW = in_sizes[1] / (49 * 49);

    prep_all<<<2840, 256>>>(qkv_w, proj_w, mask, table, relidx, nW);

    cudaFuncSetAttribute(win_attn_fa10,
                         cudaFuncAttributeMaxDynamicSharedMemorySize, SMEM_BYTES);
    win_attn_fa10<<<B, 256, SMEM_BYTES>>>(x, qkv_b, proj_b, out, nW);
}

// round 17
// speedup vs baseline: 2.0052x; 1.0397x over previous
#include <cuda_runtime.h>
#include <cuda_fp16.h>
#include <cstdint>

typedef unsigned int u32;

#define QSCALE 0.17677669529663687f

// ---- smem byte offsets (1 window per CTA, 94208 B -> 2 CTAs/SM) ----
#define OFF_QHI   0
#define OFF_QLO   16384
#define OFF_KHI   32768
#define OFF_KLO   47104     /* kept for layout stability; unused in 2-pass S */
#define OFF_AFHI  61440
#define OFF_AFLO  77824
#define OFF_VTHI  61440
#define OFF_PHI   0
#define SMEM_BYTES 94208

__device__ __align__(16) unsigned char g_wq[163840];
__device__ __align__(16) unsigned char g_wp[32768];
__device__ __align__(16) float g_bm[702464];

__device__ __forceinline__ u32 sw16(int ch, int r) {
    return (u32)((ch & 8) | ((ch ^ (r & 7)) & 7));
}

// ---------------- prep kernel (unchanged layout) ----------------
__global__ void prep_all(const float* __restrict__ qkv_w,
                         const float* __restrict__ proj_w,
                         const float* __restrict__ mask,
                         const float* __restrict__ bias_table,
                         const int*   __restrict__ rel_index,
                         int nW) {
    int e = blockIdx.x * 256 + threadIdx.x;
    if (e < 24576) {
        int piece = e >> 11;
        int rem = e & 2047;
        int lane = rem & 31, ks = (rem >> 5) & 3, nt = rem >> 7;
        const float* W;
        unsigned char* dst;
        int ldw, nbase, kh, part;
        if (piece < 8) {
            W = qkv_w; ldw = 384;
            nbase = (piece >> 2) * 128;
            kh = (piece >> 1) & 1;
            part = piece & 1;
            dst = g_wq + (size_t)piece * 16384;
        } else if (piece < 10) {
            W = qkv_w; ldw = 384;
            nbase = 256;
            kh = piece - 8;
            part = 0;
            dst = g_wq + (size_t)piece * 16384;
        } else {
            W = proj_w; ldw = 128;
            nbase = 0;
            kh = piece - 10;
            part = 0;
            dst = g_wp + (size_t)(piece - 10) * 16384;
        }
        int k0 = kh * 64 + ks * 16 + (lane & 3) * 2;
        int n  = nbase + nt * 8 + (lane >> 2);
        float v0 = W[k0 * ldw + n],       v1 = W[(k0 + 1) * ldw + n];
        float v2 = W[(k0 + 8) * ldw + n], v3 = W[(k0 + 9) * ldw + n];
        __half h0 = __float2half_rn(v0), h1 = __float2half_rn(v1);
        __half h2 = __float2half_rn(v2), h3 = __float2half_rn(v3);
        __half2 r0, r1;
        if (part == 0) {
            r0 = __halves2half2(h0, h1);
            r1 = __halves2half2(h2, h3);
        } else {
            r0 = __halves2half2(__float2half_rn(v0 - __half2float(h0)),
                                __float2half_rn(v1 - __half2float(h1)));
            r1 = __halves2half2(__float2half_rn(v2 - __half2float(h2)),
                                __float2half_rn(v3 - __half2float(h3)));
        }
        int ng = nt >> 2, ntp = (nt >> 1) & 1, half = nt & 1;
        u32 off = (u32)((((ng * 2 + ntp) * 4 + ks) * 32 + lane) * 16 + half * 8);
        *(__half2*)(dst + off)     = r0;
        *(__half2*)(dst + off + 4) = r1;
    } else {
        int idx = e - 24576;
        if (idx < 702464) {
            int w = idx / 10976;
            int r = idx % 10976;
            int h = r / 2744;
            int r2 = r % 2744;
            int i = r2 / 56, j = r2 % 56;
            float val = 0.f;
            if (j < 49 && w < nW)
                val = bias_table[rel_index[i * 49 + j] * 4 + h] + mask[w * 2401 + i * 49 + j];
            g_bm[idx] = val;
        }
    }
}

// ---------------- PTX helpers ----------------
__device__ __forceinline__ void ldm4(u32 r[4], u32 addr) {
    asm volatile("ldmatrix.sync.aligned.m8n8.x4.shared.b16 {%0,%1,%2,%3}, [%4];"
        : "=r"(r[0]), "=r"(r[1]), "=r"(r[2]), "=r"(r[3]) : "r"(addr));
}
__device__ __forceinline__ void ldm2(u32 r[2], u32 addr) {
    asm volatile("ldmatrix.sync.aligned.m8n8.x2.shared.b16 {%0,%1}, [%2];"
        : "=r"(r[0]), "=r"(r[1]) : "r"(addr));
}
__device__ __forceinline__ void mma16816h(float c[4], const u32 a[4], u32 b0, u32 b1) {
    asm volatile("mma.sync.aligned.m16n8k16.row.col.f32.f16.f16.f32 "
        "{%0,%1,%2,%3}, {%4,%5,%6,%7}, {%8,%9}, {%0,%1,%2,%3};"
        : "+f"(c[0]), "+f"(c[1]), "+f"(c[2]), "+f"(c[3])
        : "r"(a[0]), "r"(a[1]), "r"(a[2]), "r"(a[3]), "r"(b0), "r"(b1));
}
__device__ __forceinline__ u32 pkh_f16(float a, float b) {
    u32 r;
    asm("cvt.rn.f16x2.f32 %0, %1, %2;" : "=r"(r) : "f"(b), "f"(a));
    return r;
}
__device__ __forceinline__ u32 pkl_f16(float a, float b, u32 h) {
    float ah, bh;
    asm("{\n\t.reg .b16 x,y;\n\tmov.b32 {x,y}, %2;\n\t"
        "cvt.f32.f16 %0, x;\n\tcvt.f32.f16 %1, y;\n\t}"
        : "=f"(ah), "=f"(bh) : "r"(h));
    return pkh_f16(a - ah, b - bh);
}
__device__ __forceinline__ void ldgB(u32 b0[4], u32 b1[4],
                                     const unsigned char* base, int ng, int ks, int lane) {
    #pragma unroll
    for (int ntp = 0; ntp < 2; ++ntp) {
        const uint4* p = (const uint4*)(base + (u32)((((ng * 2 + ntp) * 4 + ks) * 32 + lane) * 16));
        uint4 v = __ldg(p);
        b0[2*ntp] = v.x; b1[2*ntp] = v.y; b0[2*ntp+1] = v.z; b1[2*ntp+1] = v.w;
    }
}

// ---------------- main kernel: 1 window/CTA, 256 threads, 2 CTAs/SM ----------------
__global__ __launch_bounds__(256, 2)
void win_attn_fa11(const float* __restrict__ x,
                   const float* __restrict__ qkv_b,
                   const float* __restrict__ proj_b,
                   float* __restrict__ out, int nW)
{
    extern __shared__ __align__(1024) unsigned char sm[];
    const u32 sb = (u32)__cvta_generic_to_shared(sm);
    const int tid = threadIdx.x, lane = tid & 31, wid = tid >> 5;
    const int b = blockIdx.x;
    const int mg = wid >> 2, ng = wid & 3;
    const int arow0 = mg * 32 + (lane & 7) + ((lane >> 3) & 1) * 8;
    const int arow1 = arow0 + 16;
    const int achsel = lane >> 4;
    const int cb = ng * 32 + (lane & 3) * 2;

    const float* xw = x + (size_t)b * 49 * 128;

    // ---- build A hi/lo once [64 rows][K=128] ----
    {
        int row = tid >> 2, cg = tid & 3;
        float xv[32];
        if (row < 49) {
            const float4* src = (const float4*)(xw + (size_t)row * 128 + cg * 32);
            #pragma unroll
            for (int q = 0; q < 8; ++q) {
                float4 t = src[q];
                xv[4*q] = t.x; xv[4*q+1] = t.y; xv[4*q+2] = t.z; xv[4*q+3] = t.w;
            }
        } else {
            #pragma unroll
            for (int q = 0; q < 32; ++q) xv[q] = 0.f;
        }
        #pragma unroll
        for (int h = 0; h < 4; ++h) {
            u32 hi[4], lo[4];
            #pragma unroll
            for (int p = 0; p < 4; ++p) {
                float a = xv[h*8 + 2*p], bb = xv[h*8 + 2*p + 1];
                hi[p] = pkh_f16(a, bb);
                lo[p] = pkl_f16(a, bb, hi[p]);
            }
            int ch = cg * 4 + h;
            u32 off = (u32)row * 256 + sw16(ch, row) * 16;
            *(uint4*)(sm + OFF_AFHI + off) = make_uint4(hi[0], hi[1], hi[2], hi[3]);
            *(uint4*)(sm + OFF_AFLO + off) = make_uint4(lo[0], lo[1], lo[2], lo[3]);
        }
    }
    __syncthreads();   // sync #1

    // ======== FUSED q+k GEMM: fp16 2-pass ((A-hi + A-lo) x W-hi) ========
    {
        float accQ[2][4][4], accK[2][4][4];
        #pragma unroll
        for (int mt = 0; mt < 2; ++mt)
            #pragma unroll
            for (int nt = 0; nt < 4; ++nt)
                #pragma unroll
                for (int e = 0; e < 4; ++e) { accQ[mt][nt][e] = 0.f; accK[mt][nt][e] = 0.f; }

        #pragma unroll 1
        for (int kh = 0; kh < 2; ++kh) {
            const unsigned char* bq_hi = g_wq + (size_t)(kh * 2) * 16384;
            const unsigned char* bk_hi = g_wq + (size_t)(4 + kh * 2) * 16384;
            #pragma unroll
            for (int ks = 0; ks < 4; ++ks) {
                int ch = kh * 8 + ks * 2 + achsel;
                u32 off0 = (u32)arow0 * 256 + sw16(ch, arow0) * 16;
                u32 off1 = (u32)arow1 * 256 + sw16(ch, arow1) * 16;
                u32 ah[2][4], al[2][4];
                ldm4(ah[0], sb + OFF_AFHI + off0);
                ldm4(ah[1], sb + OFF_AFHI + off1);
                ldm4(al[0], sb + OFF_AFLO + off0);
                ldm4(al[1], sb + OFF_AFLO + off1);
                {
                    u32 bh0[4], bh1[4];
                    ldgB(bh0, bh1, bq_hi, ng, ks, lane);
                    #pragma unroll
                    for (int mt = 0; mt < 2; ++mt)
                        #pragma unroll
                        for (int nt = 0; nt < 4; ++nt) {
                            mma16816h(accQ[mt][nt], ah[mt], bh0[nt], bh1[nt]);
                            mma16816h(accQ[mt][nt], al[mt], bh0[nt], bh1[nt]);
                        }
                }
                {
                    u32 bh0[4], bh1[4];
                    ldgB(bh0, bh1, bk_hi, ng, ks, lane);
                    #pragma unroll
                    for (int mt = 0; mt < 2; ++mt)
                        #pragma unroll
                        for (int nt = 0; nt < 4; ++nt) {
                            mma16816h(accK[mt][nt], ah[mt], bh0[nt], bh1[nt]);
                            mma16816h(accK[mt][nt], al[mt], bh0[nt], bh1[nt]);
                        }
                }
            }
        }

        // epilogue: Q and K as fp16 hi/lo (bias hoisted)
        {
            int rb = mg * 32 + (lane >> 2);
            float qb0[4], qb1[4], kb0[4], kb1[4];
            #pragma unroll
            for (int nt = 0; nt < 4; ++nt) {
                qb0[nt] = __ldg(qkv_b + cb + nt * 8);
                qb1[nt] = __ldg(qkv_b + cb + nt * 8 + 1);
                kb0[nt] = __ldg(qkv_b + 128 + cb + nt * 8);
                kb1[nt] = __ldg(qkv_b + 128 + cb + nt * 8 + 1);
            }
            #pragma unroll
            for (int mt = 0; mt < 2; ++mt)
                #pragma unroll
                for (int rh = 0; rh < 2; ++rh) {
                    int r = rb + mt * 16 + rh * 8;
                    bool ok = r < 49;
                    #pragma unroll
                    for (int nt = 0; nt < 4; ++nt) {
                        int cc = cb + nt * 8;
                        {
                            float v0 = accQ[mt][nt][rh*2]   + qb0[nt];
                            float v1 = accQ[mt][nt][rh*2+1] + qb1[nt];
                            v0 = ok ? v0 * QSCALE : 0.f;
                            v1 = ok ? v1 * QSCALE : 0.f;
                            u32 byte = (u32)r * 256 + sw16(cc >> 3, r) * 16 + (cc & 7) * 2;
                            u32 hi = pkh_f16(v0, v1);
                            *(u32*)(sm + OFF_QHI + byte) = hi;
                            *(u32*)(sm + OFF_QLO + byte) = pkl_f16(v0, v1, hi);
                        }
                        if (r < 56) {
                            float v0 = accK[mt][nt][rh*2]   + kb0[nt];
                            float v1 = accK[mt][nt][rh*2+1] + kb1[nt];
                            v0 = ok ? v0 : 0.f; v1 = ok ? v1 : 0.f;
                            u32 byte = (u32)r * 256 + sw16(cc >> 3, r) * 16 + (cc & 7) * 2;
                            u32 hi = pkh_f16(v0, v1);
                            *(u32*)(sm + OFF_KHI + byte) = hi;
                            *(u32*)(sm + OFF_KLO + byte) = pkl_f16(v0, v1, hi);
                        }
                    }
                }
        }
    }

    // ======== v chunk: fp16 2-pass ========
    {
        float acc[2][4][4];
        #pragma unroll
        for (int mt = 0; mt < 2; ++mt)
            #pragma unroll
            for (int nt = 0; nt < 4; ++nt)
                #pragma unroll
                for (int e = 0; e < 4; ++e) acc[mt][nt][e] = 0.f;

        #pragma unroll 1
        for (int kh = 0; kh < 2; ++kh) {
            const unsigned char* base = g_wq + (size_t)(8 + kh) * 16384;
            #pragma unroll
            for (int ks = 0; ks < 4; ++ks) {
                u32 b0[4], b1[4];
                ldgB(b0, b1, base, ng, ks, lane);
                int ch = kh * 8 + ks * 2 + achsel;
                u32 off0 = (u32)arow0 * 256 + sw16(ch, arow0) * 16;
                u32 off1 = (u32)arow1 * 256 + sw16(ch, arow1) * 16;
                u32 ah[2][4], al[2][4];
                ldm4(ah[0], sb + OFF_AFHI + off0);
                ldm4(ah[1], sb + OFF_AFHI + off1);
                ldm4(al[0], sb + OFF_AFLO + off0);
                ldm4(al[1], sb + OFF_AFLO + off1);
                #pragma unroll
                for (int mt = 0; mt < 2; ++mt)
                    #pragma unroll
                    for (int nt = 0; nt < 4; ++nt) {
                        mma16816h(acc[mt][nt], ah[mt], b0[nt], b1[nt]);
                        mma16816h(acc[mt][nt], al[mt], b0[nt], b1[nt]);
                    }
            }
        }
        __syncthreads();   // sync #2: A reads done before VT overwrite

        // epilogue: VT fp16 single (bias hoisted)
        {
            int rb = mg * 32 + (lane >> 2);
            float vb0[4], vb1[4];
            #pragma unroll
            for (int nt = 0; nt < 4; ++nt) {
                vb0[nt] = __ldg(qkv_b + 256 + cb + nt * 8);
                vb1[nt] = __ldg(qkv_b + 256 + cb + nt * 8 + 1);
            }
            #pragma unroll
            for (int mt = 0; mt < 2; ++mt)
                #pragma unroll
                for (int rh = 0; rh < 2; ++rh) {
                    int r = rb + mt * 16 + rh * 8;
                    bool ok = r < 49;
                    #pragma unroll
                    for (int nt = 0; nt < 4; ++nt) {
                        int cc = cb + nt * 8;
                        float v0 = acc[mt][nt][rh*2]   + vb0[nt];
                        float v1 = acc[mt][nt][rh*2+1] + vb1[nt];
                        v0 = ok ? v0 : 0.f; v1 = ok ? v1 : 0.f;
                        #pragma unroll
                        for (int e = 0; e < 2; ++e) {
                            float vv = e ? v1 : v0;
                            int vr = cc + e;
                            u32 byte = (u32)vr * 128
                                     + (u32)((((r >> 3) ^ (vr & 7)) & 7) << 4)
                                     + (r & 7) * 2;
                            *(__half*)(sm + OFF_VTHI + byte) = __float2half_rn(vv);
                        }
                    }
                }
        }
    }
    __syncthreads();   // sync #3

    // ======== attention: warp = (head, m-pair); 8 warps ========
    {
        const int h = wid >> 1, mp = wid & 1;
        const int g = lane >> 2, t = lane & 3;
        const float* bm = g_bm + ((size_t)(b % nW) * 4 + h) * 2744;

        float s[2][7][4];
        #pragma unroll
        for (int m = 0; m < 2; ++m)
            #pragma unroll
            for (int nt = 0; nt < 7; ++nt)
                #pragma unroll
                for (int e = 0; e < 4; ++e) s[m][nt][e] = 0.f;

        // ---- S = Q K^T (fp16 2-pass: (Q-hi + Q-lo) x K-hi) ----
        #pragma unroll
        for (int ks = 0; ks < 2; ++ks) {
            u32 aqh[2][4], aql[2][4];
            #pragma unroll
            for (int m = 0; m < 2; ++m) {
                int mt = mp * 2 + m;
                int rr = mt * 16 + (lane & 7) + ((lane >> 3) & 1) * 8;
                int ch = h * 4 + ks * 2 + (lane >> 4);
                u32 off = (u32)rr * 256 + sw16(ch, rr) * 16;
                ldm4(aqh[m], sb + OFF_QHI + off);
                ldm4(aql[m], sb + OFF_QLO + off);
            }
            u32 bkh[7][2];
            #pragma unroll
            for (int ntp = 0; ntp < 3; ++ntp) {
                int kr = ntp * 16 + ((lane >> 4) << 3) + (lane & 7);
                int ch = h * 4 + ks * 2 + ((lane >> 3) & 1);
                u32 off = (u32)kr * 256 + sw16(ch, kr) * 16;
                u32 r4[4];
                ldm4(r4, sb + OFF_KHI + off);
                bkh[2*ntp][0] = r4[0]; bkh[2*ntp][1] = r4[1];
                bkh[2*ntp+1][0] = r4[2]; bkh[2*ntp+1][1] = r4[3];
            }
            {
                int kr = 48 + (lane & 7);
                int ch = h * 4 + ks * 2 + ((lane >> 3) & 1);
                u32 off = (u32)kr * 256 + sw16(ch, kr) * 16;
                ldm2(bkh[6], sb + OFF_KHI + off);
            }
            #pragma unroll
            for (int nt = 0; nt < 7; ++nt)
                #pragma unroll
                for (int m = 0; m < 2; ++m) {
                    mma16816h(s[m][nt], aqh[m], bkh[nt][0], bkh[nt][1]);
                    mma16816h(s[m][nt], aql[m], bkh[nt][0], bkh[nt][1]);
                }
        }

        // softmax (no max-subtraction; logits O(20), fp32-safe) + pack P fp16 hi/lo
        u32 ph[2][4][4], pl[2][4][4];
        #pragma unroll
        for (int m = 0; m < 2; ++m) {
            const int mt = mp * 2 + m;
            int i0 = mt * 16 + g;
            int o0 = min(i0, 48) * 56, o1 = min(i0 + 8, 48) * 56;
            float s0 = 0.f, s1 = 0.f;
            #pragma unroll
            for (int nt = 0; nt < 7; ++nt) {
                int jj = nt * 8 + 2 * t;
                float2 b0 = *(const float2*)(bm + o0 + jj);
                float2 b1 = *(const float2*)(bm + o1 + jj);
                s[m][nt][0] = (jj     < 49) ? __expf(s[m][nt][0] + b0.x) : 0.f;
                s[m][nt][1] = (jj + 1 < 49) ? __expf(s[m][nt][1] + b0.y) : 0.f;
                s[m][nt][2] = (jj     < 49) ? __expf(s[m][nt][2] + b1.x) : 0.f;
                s[m][nt][3] = (jj + 1 < 49) ? __expf(s[m][nt][3] + b1.y) : 0.f;
                s0 += s[m][nt][0] + s[m][nt][1];
                s1 += s[m][nt][2] + s[m][nt][3];
            }
            s0 += __shfl_xor_sync(0xffffffffu, s0, 1);
            s1 += __shfl_xor_sync(0xffffffffu, s1, 1);
            s0 += __shfl_xor_sync(0xffffffffu, s0, 2);
            s1 += __shfl_xor_sync(0xffffffffu, s1, 2);
            float i0v = 1.f / s0, i1v = 1.f / s1;
            #pragma unroll
            for (int nt = 0; nt < 7; ++nt) {
                s[m][nt][0] *= i0v; s[m][nt][1] *= i0v;
                s[m][nt][2] *= i1v; s[m][nt][3] *= i1v;
            }
            #pragma unroll
            for (int k2 = 0; k2 < 4; ++k2) {
                int na = 2 * k2, nb = 2 * k2 + 1;
                ph[m][k2][0] = pkh_f16(s[m][na][0], s[m][na][1]);
                pl[m][k2][0] = pkl_f16(s[m][na][0], s[m][na][1], ph[m][k2][0]);
                ph[m][k2][1] = pkh_f16(s[m][na][2], s[m][na][3]);
                pl[m][k2][1] = pkl_f16(s[m][na][2], s[m][na][3], ph[m][k2][1]);
                if (nb < 7) {
                    ph[m][k2][2] = pkh_f16(s[m][nb][0], s[m][nb][1]);
                    pl[m][k2][2] = pkl_f16(s[m][nb][0], s[m][nb][1], ph[m][k2][2]);
                    ph[m][k2][3] = pkh_f16(s[m][nb][2], s[m][nb][3]);
                    pl[m][k2][3] = pkl_f16(s[m][nb][2], s[m][nb][3], ph[m][k2][3]);
                } else {
                    ph[m][k2][2] = ph[m][k2][3] = pl[m][k2][2] = pl[m][k2][3] = 0u;
                }
            }
        }

        // O = P @ V (fp16 2-pass)
        float o[2][4][4];
        #pragma unroll
        for (int m = 0; m < 2; ++m)
            #pragma unroll
            for (int nt = 0; nt < 4; ++nt)
                #pragma unroll
                for (int e = 0; e < 4; ++e) o[m][nt][e] = 0.f;
        #pragma unroll
        for (int k2 = 0; k2 < 4; ++k2) {
            u32 bvh[4][2];
            #pragma unroll
            for (int dp = 0; dp < 2; ++dp) {
                int vr = h * 32 + dp * 16 + ((lane >> 4) << 3) + (lane & 7);
                int ch = k2 * 2 + ((lane >> 3) & 1);
                u32 off = (u32)vr * 128 + (u32)(((ch ^ (vr & 7)) & 7) << 4);
                u32 r4[4];
                ldm4(r4, sb + OFF_VTHI + off);
                bvh[2*dp][0] = r4[0]; bvh[2*dp][1] = r4[1];
                bvh[2*dp+1][0] = r4[2]; bvh[2*dp+1][1] = r4[3];
            }
            #pragma unroll
            for (int nt = 0; nt < 4; ++nt)
                #pragma unroll
                for (int m = 0; m < 2; ++m) {
                    mma16816h(o[m][nt], ph[m][k2], bvh[nt][0], bvh[nt][1]);
                    mma16816h(o[m][nt], pl[m][k2], bvh[nt][0], bvh[nt][1]);
                }
        }

        // write O as SINGLE fp16 into proj-A layout
        #pragma unroll
        for (int m = 0; m < 2; ++m) {
            const int mt = mp * 2 + m;
            #pragma unroll
            for (int nt = 0; nt < 4; ++nt)
                #pragma unroll
                for (int rh = 0; rh < 2; ++rh) {
                    int r = mt * 16 + g + rh * 8;
                    int col = h * 32 + nt * 8 + 2 * t;
                    u32 byte = (u32)r * 256 + sw16(col >> 3, r) * 16 + (col & 7) * 2;
                    *(u32*)(sm + OFF_PHI + byte) = pkh_f16(o[m][nt][rh*2], o[m][nt][rh*2+1]);
                }
        }
    }
    __syncthreads();   // sync #4

    // ======== proj GEMM: fp16 single-pass ========
    float pacc[2][4][4];
    #pragma unroll
    for (int mt = 0; mt < 2; ++mt)
        #pragma unroll
        for (int nt = 0; nt < 4; ++nt)
            #pragma unroll
            for (int e = 0; e < 4; ++e) pacc[mt][nt][e] = 0.f;

    #pragma unroll 1
    for (int kh = 0; kh < 2; ++kh) {
        const unsigned char* base = g_wp + (size_t)kh * 16384;
        #pragma unroll
        for (int ks = 0; ks < 4; ++ks) {
            u32 b0[4], b1[4];
            ldgB(b0, b1, base, ng, ks, lane);
            int ch = kh * 8 + ks * 2 + achsel;
            u32 ah[2][4];
            ldm4(ah[0], sb + OFF_PHI + (u32)arow0 * 256 + sw16(ch, arow0) * 16);
            ldm4(ah[1], sb + OFF_PHI + (u32)arow1 * 256 + sw16(ch, arow1) * 16);
            #pragma unroll
            for (int mt = 0; mt < 2; ++mt)
                #pragma unroll
                for (int nt = 0; nt < 4; ++nt)
                    mma16816h(pacc[mt][nt], ah[mt], b0[nt], b1[nt]);
        }
    }

    // proj epilogue -> gmem (bias hoisted)
    {
        int rb = mg * 32 + (lane >> 2);
        float pb0[4], pb1[4];
        #pragma unroll
        for (int nt = 0; nt < 4; ++nt) {
            pb0[nt] = __ldg(proj_b + cb + nt * 8);
            pb1[nt] = __ldg(proj_b + cb + nt * 8 + 1);
        }
        #pragma unroll
        for (int mt = 0; mt < 2; ++mt)
            #pragma unroll
            for (int rh = 0; rh < 2; ++rh) {
                int r = rb + mt * 16 + rh * 8;
                if (r < 49) {
                    float* go = out + ((size_t)b * 49 + r) * 128;
                    #pragma unroll
                    for (int nt = 0; nt < 4; ++nt) {
                        int cc = cb + nt * 8;
                        float v0 = pacc[mt][nt][rh*2]   + pb0[nt];
                        float v1 = pacc[mt][nt][rh*2+1] + pb1[nt];
                        *(float2*)(go + cc) = make_float2(v0, v1);
                    }
                }
            }
    }
}

extern "C" void kernel_launch(void* const* d_in, const int* in_sizes, int n_in,
                              void* d_out, int out_size)
{
    const float* x      = (const float*)d_in[0];
    const float* mask   = (const float*)d_in[1];
    const float* qkv_w  = (const float*)d_in[2];
    const float* qkv_b  = (const float*)d_in[3];
    const float* proj_w = (const float*)d_in[4];
    const float* proj_b = (const float*)d_in[5];
    const float* table  = (const float*)d_in[6];
    const int*   relidx = (const int*)d_in[7];
    float*       out    = (float*)d_out;

    const int B  = in_sizes[0] / (49 * 128);
    const int nW = in_sizes[1] / (49 * 49);

    prep_all<<<2840, 256>>>(qkv_w, proj_w, mask, table, relidx, nW);

    cudaFuncSetAttribute(win_attn_fa11,
                         cudaFuncAttributeMaxDynamicSharedMemorySize, SMEM_BYTES);
    win_attn_fa11<<<B, 256, SMEM_BYTES>>>(x, qkv_b, proj_b, out, nW);
}